// round 10
// baseline (speedup 1.0000x reference)
#include <cuda_runtime.h>
#include <cuda_bf16.h>
#include <cstdint>
#include <cstddef>

// ---------------- problem constants ----------------
#define Bv   128
#define Nv   196
#define Lv   25
#define Tv   24
#define Vv   10000
#define Ev   300
#define Av   512
#define ENCv 512
#define Dv   512
#define G4D  2048   // 4*D
#define HW   2560   // cols of [W_dec | W_hh]
#define KE   320    // E padded
#define VP   10112  // V padded (multiple of 128)

// ---------------- device scratch (static, no allocation) ----------------
__device__ float g_featproj[(size_t)Bv * Nv * Av];
__device__ float g_embgates[(size_t)Tv * Bv * G4D];
__device__ float g_bh[HW];
__device__ float g_bias2[G4D];
__device__ float g_meanf[Bv * ENCv];
__device__ float g_h0[Bv * Dv];
__device__ float g_c[Bv * Dv];
__device__ float g_hproj[Bv * HW];

__device__ __nv_bfloat16 g_feat_hi[(size_t)Bv * Nv * ENCv];
__device__ __nv_bfloat16 g_feat_lo[(size_t)Bv * Nv * ENCv];
__device__ __nv_bfloat16 g_WencT_hi[Av * ENCv];
__device__ __nv_bfloat16 g_WencT_lo[Av * ENCv];
__device__ __nv_bfloat16 g_WihT_hi[G4D * KE];
__device__ __nv_bfloat16 g_WihT_lo[G4D * KE];
__device__ __nv_bfloat16 g_WihcT_hi[G4D * Dv];
__device__ __nv_bfloat16 g_WihcT_lo[G4D * Dv];
__device__ __nv_bfloat16 g_whcatT_hi[HW * Dv];
__device__ __nv_bfloat16 g_whcatT_lo[HW * Dv];
__device__ __nv_bfloat16 g_WoutT_hi[(size_t)VP * Dv];
__device__ __nv_bfloat16 g_WoutT_lo[(size_t)VP * Dv];
__device__ __nv_bfloat16 g_embA_hi[Tv * Bv * KE];
__device__ __nv_bfloat16 g_embA_lo[Tv * Bv * KE];
__device__ __nv_bfloat16 g_H_hi[(size_t)Tv * Bv * Dv];
__device__ __nv_bfloat16 g_H_lo[(size_t)Tv * Bv * Dv];
__device__ __nv_bfloat16 g_h0_hi[Bv * Dv];
__device__ __nv_bfloat16 g_h0_lo[Bv * Dv];
__device__ __nv_bfloat16 g_ctx_hi[Bv * Dv];
__device__ __nv_bfloat16 g_ctx_lo[Bv * Dv];

// ---------------- PTX helpers ----------------
__device__ __forceinline__ uint32_t smem_u32(const void* p) {
    uint32_t a;
    asm("{ .reg .u64 t; cvta.to.shared.u64 t, %1; cvt.u32.u64 %0, t; }" : "=r"(a) : "l"(p));
    return a;
}

#define LDSM4(r, addr) \
    asm volatile("ldmatrix.sync.aligned.m8n8.x4.shared.b16 {%0,%1,%2,%3}, [%4];" \
        : "=r"((r)[0]), "=r"((r)[1]), "=r"((r)[2]), "=r"((r)[3]) : "r"(addr))

#define MMA16816(d, a, b0, b1) \
    asm volatile("mma.sync.aligned.m16n8k16.row.col.f32.bf16.bf16.f32 " \
        "{%0,%1,%2,%3}, {%4,%5,%6,%7}, {%8,%9}, {%0,%1,%2,%3};" \
        : "+f"((d)[0]), "+f"((d)[1]), "+f"((d)[2]), "+f"((d)[3]) \
        : "r"((a)[0]), "r"((a)[1]), "r"((a)[2]), "r"((a)[3]), "r"(b0), "r"(b1))

// =================================================================
// BIG HMMA GEMM: CTA 128x128, 8 warps 2M x 4N (warp tile 64x32), BK=64.
// 12 LDSM per 48 MMA per warp-k16 (vs 10/24 in the 128x64 kernel).
// smem: 4 regions x 128 rows x 144B = 73728 B, 1 CTA/SM.
// C[M,N] = A[M,K] @ Bt[N,K]^T + bias ; remap for logits.
// =================================================================
#define BOFF_AHI 0
#define BOFF_ALO 18432
#define BOFF_BHI 36864
#define BOFF_BLO 55296
#define BIG_SMEM 73728

__global__ __launch_bounds__(256)
void hmma_big_kernel(int Nreal, int K,
                     const __nv_bfloat16* __restrict__ Ahi, const __nv_bfloat16* __restrict__ Alo,
                     const __nv_bfloat16* __restrict__ Bhi, const __nv_bfloat16* __restrict__ Blo,
                     float* __restrict__ C, int ldc,
                     const float* __restrict__ bias, int remap)
{
    extern __shared__ char sm[];
    const uint32_t sb = smem_u32(sm);
    const int tid = threadIdx.x;
    const int wid = tid >> 5, lane = tid & 31;
    const int warp_m = wid & 1;          // 2 x 64 rows
    const int warp_n = wid >> 1;         // 4 x 32 cols
    const int row0 = blockIdx.y * 128;
    const int col0 = blockIdx.x * 128;

    float acc[4][4][4];
#pragma unroll
    for (int mt = 0; mt < 4; mt++)
#pragma unroll
        for (int nt = 0; nt < 4; nt++)
#pragma unroll
            for (int r = 0; r < 4; r++) acc[mt][nt][r] = 0.f;

    const int a_lr = lane & 15, a_lk = (lane >> 4) * 8;
    const int b_grp = lane >> 3;
    const int b_lr = (lane & 7) + ((b_grp >> 1) * 8);
    const int b_lk = (b_grp & 1) * 8;

    const int nchunks = K >> 6;
    for (int kc = 0; kc < nchunks; kc++) {
        const size_t koff = (size_t)kc * 64;
        // A and B tiles are both 128 rows x 64 bf16 (x hi/lo)
#pragma unroll 2
        for (int i = tid; i < 1024; i += 256) {
            const int r = i >> 3, s = i & 7;
            const uint32_t d = (uint32_t)(r * 144 + s * 16);
            const size_t ga = (size_t)(row0 + r) * K + koff + s * 8;
            const size_t gb = (size_t)(col0 + r) * K + koff + s * 8;
            *(uint4*)(sm + BOFF_AHI + d) = *(const uint4*)(Ahi + ga);
            *(uint4*)(sm + BOFF_ALO + d) = *(const uint4*)(Alo + ga);
            *(uint4*)(sm + BOFF_BHI + d) = *(const uint4*)(Bhi + gb);
            *(uint4*)(sm + BOFF_BLO + d) = *(const uint4*)(Blo + gb);
        }
        __syncthreads();

#pragma unroll
        for (int k16 = 0; k16 < 64; k16 += 16) {
            uint32_t aHi[4][4], aLo[4][4], bH[8], bL[8];
#pragma unroll
            for (int mt = 0; mt < 4; mt++) {
                const uint32_t ab = (uint32_t)((warp_m * 64 + mt * 16 + a_lr) * 144
                                               + (k16 + a_lk) * 2);
                LDSM4(aHi[mt], sb + BOFF_AHI + ab);
                LDSM4(aLo[mt], sb + BOFF_ALO + ab);
            }
#pragma unroll
            for (int half = 0; half < 2; half++) {
                const uint32_t bb = (uint32_t)((warp_n * 32 + half * 16 + b_lr) * 144
                                               + (k16 + b_lk) * 2);
                LDSM4(bH + half * 4, sb + BOFF_BHI + bb);
                LDSM4(bL + half * 4, sb + BOFF_BLO + bb);
            }
#pragma unroll
            for (int mt = 0; mt < 4; mt++)
#pragma unroll
                for (int nt = 0; nt < 4; nt++) {
                    MMA16816(acc[mt][nt], aHi[mt], bH[nt * 2], bH[nt * 2 + 1]);
                    MMA16816(acc[mt][nt], aLo[mt], bH[nt * 2], bH[nt * 2 + 1]);
                    MMA16816(acc[mt][nt], aHi[mt], bL[nt * 2], bL[nt * 2 + 1]);
                }
        }
        __syncthreads();
    }

    const int quad = lane >> 2, tc = lane & 3;
#pragma unroll
    for (int mt = 0; mt < 4; mt++)
#pragma unroll
        for (int half = 0; half < 2; half++) {
            const int gm = row0 + warp_m * 64 + mt * 16 + quad + half * 8;
            const size_t rowC = remap ? ((size_t)(gm & (Bv - 1)) * Tv + (gm >> 7))
                                      : (size_t)gm;
#pragma unroll
            for (int nt = 0; nt < 4; nt++) {
                const int gn = col0 + warp_n * 32 + nt * 8 + tc * 2;
                if (gn >= Nreal) continue;
                const float2 bv = *(const float2*)&bias[gn];
                float2 o;
                o.x = acc[mt][nt][half * 2]     + bv.x;
                o.y = acc[mt][nt][half * 2 + 1] + bv.y;
                *(float2*)&C[rowC * (size_t)ldc + gn] = o;
            }
        }
}

// =================================================================
// Loop HMMA GEMM: CTA 128x64, 8 warps 4M x 2N (warp tile 32x32), BK=64.
// 8 LDSM per 24 MMA per warp-k16 (was 10/24). Cinit for in-place gates acc.
// =================================================================
#define OFF_AHI 0
#define OFF_ALO (128 * 144)
#define OFF_BHI (256 * 144)
#define OFF_BLO (320 * 144)
#define HM_SMEM (384 * 144)   // 55296

__global__ __launch_bounds__(256, 2)
void hmma_kernel(int M, int N, int Nreal, int K,
                 const __nv_bfloat16* __restrict__ Ahi, const __nv_bfloat16* __restrict__ Alo,
                 const __nv_bfloat16* __restrict__ Bhi, const __nv_bfloat16* __restrict__ Blo,
                 float* __restrict__ C, int ldc,
                 const float* __restrict__ bias,
                 const float* __restrict__ Cinit)
{
    extern __shared__ char sm[];
    const uint32_t sb = smem_u32(sm);
    const int tid = threadIdx.x;
    const int wid = tid >> 5, lane = tid & 31;
    const int warp_m = wid & 3;          // 4 x 32 rows
    const int warp_n = wid >> 2;         // 2 x 32 cols
    const int row0 = blockIdx.y * 128;
    const int col0 = blockIdx.x * 64;

    float acc[2][4][4];
#pragma unroll
    for (int mt = 0; mt < 2; mt++)
#pragma unroll
        for (int nt = 0; nt < 4; nt++)
#pragma unroll
            for (int r = 0; r < 4; r++) acc[mt][nt][r] = 0.f;

    const int a_lr = lane & 15, a_lk = (lane >> 4) * 8;
    const int b_grp = lane >> 3;
    const int b_lr = (lane & 7) + ((b_grp >> 1) * 8);
    const int b_lk = (b_grp & 1) * 8;

    const int nchunks = K >> 6;
    for (int kc = 0; kc < nchunks; kc++) {
        const size_t koff = (size_t)kc * 64;
#pragma unroll 2
        for (int i = tid; i < 1024; i += 256) {
            const int r = i >> 3, s = i & 7;
            const uint32_t d = (uint32_t)(r * 144 + s * 16);
            const size_t g = (size_t)(row0 + r) * K + koff + s * 8;
            *(uint4*)(sm + OFF_AHI + d) = *(const uint4*)(Ahi + g);
            *(uint4*)(sm + OFF_ALO + d) = *(const uint4*)(Alo + g);
        }
#pragma unroll 2
        for (int i = tid; i < 512; i += 256) {
            const int r = i >> 3, s = i & 7;
            const uint32_t d = (uint32_t)(r * 144 + s * 16);
            const size_t g = (size_t)(col0 + r) * K + koff + s * 8;
            *(uint4*)(sm + OFF_BHI + d) = *(const uint4*)(Bhi + g);
            *(uint4*)(sm + OFF_BLO + d) = *(const uint4*)(Blo + g);
        }
        __syncthreads();

#pragma unroll
        for (int k16 = 0; k16 < 64; k16 += 16) {
            uint32_t aHi[2][4], aLo[2][4], bH[8], bL[8];
#pragma unroll
            for (int mt = 0; mt < 2; mt++) {
                const uint32_t ab = (uint32_t)((warp_m * 32 + mt * 16 + a_lr) * 144
                                               + (k16 + a_lk) * 2);
                LDSM4(aHi[mt], sb + OFF_AHI + ab);
                LDSM4(aLo[mt], sb + OFF_ALO + ab);
            }
#pragma unroll
            for (int half = 0; half < 2; half++) {
                const uint32_t bb = (uint32_t)((warp_n * 32 + half * 16 + b_lr) * 144
                                               + (k16 + b_lk) * 2);
                LDSM4(bH + half * 4, sb + OFF_BHI + bb);
                LDSM4(bL + half * 4, sb + OFF_BLO + bb);
            }
#pragma unroll
            for (int mt = 0; mt < 2; mt++)
#pragma unroll
                for (int nt = 0; nt < 4; nt++) {
                    MMA16816(acc[mt][nt], aHi[mt], bH[nt * 2], bH[nt * 2 + 1]);
                    MMA16816(acc[mt][nt], aLo[mt], bH[nt * 2], bH[nt * 2 + 1]);
                    MMA16816(acc[mt][nt], aHi[mt], bL[nt * 2], bL[nt * 2 + 1]);
                }
        }
        __syncthreads();
    }

    const int quad = lane >> 2, tc = lane & 3;
#pragma unroll
    for (int mt = 0; mt < 2; mt++)
#pragma unroll
        for (int half = 0; half < 2; half++) {
            const int gm = row0 + warp_m * 32 + mt * 16 + quad + half * 8;
#pragma unroll
            for (int nt = 0; nt < 4; nt++) {
                const int gn = col0 + warp_n * 32 + nt * 8 + tc * 2;
                if (gn >= Nreal) continue;
                float v0 = acc[mt][nt][half * 2];
                float v1 = acc[mt][nt][half * 2 + 1];
                if (bias) {
                    const float2 bv = *(const float2*)&bias[gn];
                    v0 += bv.x; v1 += bv.y;
                }
                if (Cinit) {
                    const float2 cv = *(const float2*)&Cinit[(size_t)gm * ldc + gn];
                    v0 += cv.x; v1 += cv.y;
                }
                float2 o; o.x = v0; o.y = v1;
                *(float2*)&C[(size_t)gm * ldc + gn] = o;
            }
        }
}

// =================================================================
// Small fp32 SGEMM (one-time h0/c0 init only)
// =================================================================
template<int BM, int BN, int BK, int TM, int TN>
__global__ void sgemm_kernel(int M, int N, int K,
                             const float* __restrict__ A, int lda,
                             const float* __restrict__ B, int ldb,
                             float* __restrict__ C, int ldc,
                             const float* __restrict__ bias)
{
    constexpr int TX = BN / TN;
    constexpr int TY = BM / TM;
    constexpr int NT = TX * TY;
    __shared__ float As[BK][BM + 1];
    __shared__ float Bs[BK][BN];

    const int tid = threadIdx.x;
    const int tx = tid % TX, ty = tid / TX;
    const int row0 = blockIdx.y * BM;
    const int col0 = blockIdx.x * BN;

    float acc[TM][TN];
#pragma unroll
    for (int i = 0; i < TM; i++)
#pragma unroll
        for (int j = 0; j < TN; j++) acc[i][j] = 0.f;

    for (int k0 = 0; k0 < K; k0 += BK) {
#pragma unroll
        for (int i = tid; i < BM * BK; i += NT) {
            int m = i / BK, k = i % BK;
            As[k][m] = A[(size_t)(row0 + m) * lda + k0 + k];
        }
#pragma unroll
        for (int i = tid; i < BK * BN; i += NT) {
            int k = i / BN, n = i % BN;
            Bs[k][n] = B[(size_t)(k0 + k) * ldb + col0 + n];
        }
        __syncthreads();
#pragma unroll
        for (int kk = 0; kk < BK; kk++) {
            float ra[TM], rb[TN];
#pragma unroll
            for (int i = 0; i < TM; i++) ra[i] = As[kk][ty * TM + i];
#pragma unroll
            for (int j = 0; j < TN; j++) rb[j] = Bs[kk][tx * TN + j];
#pragma unroll
            for (int i = 0; i < TM; i++)
#pragma unroll
                for (int j = 0; j < TN; j++)
                    acc[i][j] = fmaf(ra[i], rb[j], acc[i][j]);
        }
        __syncthreads();
    }

#pragma unroll
    for (int i = 0; i < TM; i++)
#pragma unroll
        for (int j = 0; j < TN; j++) {
            int gm = row0 + ty * TM + i, gn = col0 + tx * TN + j;
            C[(size_t)gm * ldc + gn] = acc[i][j] + bias[gn];
        }
}

// ---------------- prep kernels ----------------
__device__ __forceinline__ void split_hilo(float v, __nv_bfloat16& h, __nv_bfloat16& l) {
    h = __float2bfloat16(v);
    l = __float2bfloat16(v - __bfloat162float(h));
}

__global__ void whcatT_hilo_kernel(const float* __restrict__ Wdec, const float* __restrict__ Whh,
                                   __nv_bfloat16* __restrict__ hi, __nv_bfloat16* __restrict__ lo)
{
    int idx = blockIdx.x * blockDim.x + threadIdx.x;
    if (idx >= HW * Dv) return;
    int k = idx & 511, n = idx >> 9;
    float v = (n < 512) ? Wdec[(size_t)k * Av + n]
                        : Whh[(size_t)k * G4D + (n - 512)];
    split_hilo(v, hi[idx], lo[idx]);
}

__global__ void biases_kernel(const float* __restrict__ bdec,
                              const float* __restrict__ bih, const float* __restrict__ bhh,
                              float* __restrict__ bh, float* __restrict__ b2)
{
    int j = blockIdx.x * blockDim.x + threadIdx.x;
    if (j < HW)  bh[j] = (j < 512) ? bdec[j] : 0.f;
    if (j < G4D) b2[j] = bih[j] + bhh[j];
}

__global__ void embgather_hilo_kernel(const float* __restrict__ emb, const int* __restrict__ cap,
                                      __nv_bfloat16* __restrict__ hi, __nv_bfloat16* __restrict__ lo)
{
    int idx = blockIdx.x * blockDim.x + threadIdx.x;
    if (idx >= Tv * Bv * KE) return;
    int k = idx % KE, r = idx / KE;
    int t = r / Bv, b = r % Bv;
    float v = 0.f;
    if (k < Ev) v = emb[(size_t)cap[b * Lv + t] * Ev + k];
    split_hilo(v, hi[idx], lo[idx]);
}

__global__ void conv_hilo_kernel(const float* __restrict__ in, size_t n,
                                 __nv_bfloat16* __restrict__ hi, __nv_bfloat16* __restrict__ lo)
{
    size_t idx = (size_t)blockIdx.x * blockDim.x + threadIdx.x;
    if (idx >= n) return;
    split_hilo(in[idx], hi[idx], lo[idx]);
}

__global__ void conv4_hilo_kernel(const float4* __restrict__ in, size_t n4,
                                  __nv_bfloat162* __restrict__ hi, __nv_bfloat162* __restrict__ lo)
{
    size_t idx = (size_t)blockIdx.x * blockDim.x + threadIdx.x;
    if (idx >= n4) return;
    float4 v = in[idx];
    __nv_bfloat16 h0, l0, h1, l1, h2, l2, h3, l3;
    split_hilo(v.x, h0, l0); split_hilo(v.y, h1, l1);
    split_hilo(v.z, h2, l2); split_hilo(v.w, h3, l3);
    hi[idx * 2]     = __nv_bfloat162(h0, h1);
    hi[idx * 2 + 1] = __nv_bfloat162(h2, h3);
    lo[idx * 2]     = __nv_bfloat162(l0, l1);
    lo[idx * 2 + 1] = __nv_bfloat162(l2, l3);
}

__global__ void trans_hilo_kernel(const float* __restrict__ in, int R, int C,
                                  __nv_bfloat16* __restrict__ hi, __nv_bfloat16* __restrict__ lo,
                                  int Kpad, int Npad)
{
    __shared__ float t[32][33];
    const int cb = blockIdx.x * 32;
    const int rb = blockIdx.y * 32;
    const int x = threadIdx.x, y = threadIdx.y;
#pragma unroll
    for (int i = y; i < 32; i += 8) {
        int r = rb + i, ccol = cb + x;
        t[i][x] = (r < R && ccol < C) ? in[(size_t)r * C + ccol] : 0.f;
    }
    __syncthreads();
#pragma unroll
    for (int i = y; i < 32; i += 8) {
        int n = cb + i, k = rb + x;
        if (n < Npad && k < Kpad) {
            size_t o = (size_t)n * Kpad + k;
            split_hilo(t[x][i], hi[o], lo[o]);
        }
    }
}

__global__ void meanf_kernel(const float* __restrict__ feat, float* __restrict__ mf)
{
    int b = blockIdx.x, tid = threadIdx.x;
    for (int d = tid; d < ENCv; d += 256) {
        float s = 0.f;
        const float* p = feat + (size_t)b * Nv * ENCv + d;
#pragma unroll 4
        for (int n = 0; n < Nv; n++) s += p[(size_t)n * ENCv];
        mf[b * ENCv + d] = s * (1.0f / (float)Nv);
    }
}

// ---------------- fused attention ----------------
__global__ void attention_kernel(const float* __restrict__ fp,
                                 const float* __restrict__ feat,
                                 const float* __restrict__ dec,   // hproj[:, :512], ld=HW
                                 const float* __restrict__ watt,
                                 __nv_bfloat16* __restrict__ ctxHi,
                                 __nv_bfloat16* __restrict__ ctxLo,
                                 float* __restrict__ alphaOut)
{
    __shared__ float s_dec[Av];
    __shared__ float s_watt[Av];
    __shared__ float s_sc[Nv];
    __shared__ float s_red[8];
    const int b = blockIdx.x, tid = threadIdx.x;

    for (int i = tid; i < Av; i += 256) { s_dec[i] = dec[(size_t)b * HW + i]; s_watt[i] = watt[i]; }
    __syncthreads();

    const int warp = tid >> 5, lane = tid & 31;
    const float* fpb = fp + (size_t)b * Nv * Av;
    for (int n = warp; n < Nv; n += 8) {
        const float* row = fpb + (size_t)n * Av;
        float s = 0.f;
#pragma unroll 4
        for (int k = lane; k < Av; k += 32) {
            float x = row[k] + s_dec[k];
            float th;
            asm("tanh.approx.f32 %0, %1;" : "=f"(th) : "f"(x));
            s = fmaf(th, s_watt[k], s);
        }
#pragma unroll
        for (int o = 16; o; o >>= 1) s += __shfl_xor_sync(0xffffffffu, s, o);
        if (lane == 0) s_sc[n] = s;
    }
    __syncthreads();

    float m = -1e30f;
    for (int n = tid; n < Nv; n += 256) m = fmaxf(m, s_sc[n]);
#pragma unroll
    for (int o = 16; o; o >>= 1) m = fmaxf(m, __shfl_xor_sync(0xffffffffu, m, o));
    if (lane == 0) s_red[warp] = m;
    __syncthreads();
    if (tid == 0) {
        float mm = s_red[0];
        for (int w = 1; w < 8; w++) mm = fmaxf(mm, s_red[w]);
        s_red[0] = mm;
    }
    __syncthreads();
    m = s_red[0];
    __syncthreads();

    float sum = 0.f;
    for (int n = tid; n < Nv; n += 256) {
        float e = __expf(s_sc[n] - m);
        s_sc[n] = e;
        sum += e;
    }
#pragma unroll
    for (int o = 16; o; o >>= 1) sum += __shfl_xor_sync(0xffffffffu, sum, o);
    if (lane == 0) s_red[warp] = sum;
    __syncthreads();
    if (tid == 0) {
        float ss = 0.f;
        for (int w = 0; w < 8; w++) ss += s_red[w];
        s_red[0] = 1.f / ss;
    }
    __syncthreads();
    const float inv = s_red[0];
    for (int n = tid; n < Nv; n += 256) {
        float a = s_sc[n] * inv;
        s_sc[n] = a;
        alphaOut[(size_t)b * Tv * Nv + n] = a;
    }
    __syncthreads();

    const float* fb = feat + (size_t)b * Nv * ENCv;
    for (int d = tid; d < ENCv; d += 256) {
        float acc = 0.f;
#pragma unroll 4
        for (int n = 0; n < Nv; n++) acc = fmaf(s_sc[n], fb[(size_t)n * ENCv + d], acc);
        split_hilo(acc, ctxHi[b * ENCv + d], ctxLo[b * ENCv + d]);
    }
}

// ---------------- LSTM pointwise ----------------
__global__ void lstm_kernel(const float* __restrict__ gpart,
                            const float* __restrict__ hproj,
                            float* __restrict__ c,
                            __nv_bfloat16* __restrict__ hHi,
                            __nv_bfloat16* __restrict__ hLo)
{
    int idx = blockIdx.x * blockDim.x + threadIdx.x;
    if (idx >= Bv * Dv) return;
    int b = idx >> 9, d = idx & 511;
    const float* gp = gpart + (size_t)b * G4D;
    const float* hp = hproj + (size_t)b * HW + 512;
    float gi = gp[d]          + hp[d];
    float gf = gp[Dv + d]     + hp[Dv + d];
    float gg = gp[2 * Dv + d] + hp[2 * Dv + d];
    float go = gp[3 * Dv + d] + hp[3 * Dv + d];
    float si = 1.f / (1.f + __expf(-gi));
    float sf = 1.f / (1.f + __expf(-gf));
    float so = 1.f / (1.f + __expf(-go));
    float tg = tanhf(gg);
    float cn = sf * c[idx] + si * tg;
    c[idx] = cn;
    float h = so * tanhf(cn);
    split_hilo(h, hHi[idx], hLo[idx]);
}

// ---------------- host helpers ----------------
static void launch_big(int M, int N, int Nreal, int K,
                       const __nv_bfloat16* Ahi, const __nv_bfloat16* Alo,
                       const __nv_bfloat16* Bhi, const __nv_bfloat16* Blo,
                       float* C, int ldc, const float* bias, int remap)
{
    dim3 grid(N / 128, M / 128);
    hmma_big_kernel<<<grid, 256, BIG_SMEM>>>(Nreal, K, Ahi, Alo, Bhi, Blo,
                                             C, ldc, bias, remap);
}

static void launch_loop(int M, int N, int Nreal, int K,
                        const __nv_bfloat16* Ahi, const __nv_bfloat16* Alo,
                        const __nv_bfloat16* Bhi, const __nv_bfloat16* Blo,
                        float* C, int ldc, const float* bias, const float* Cinit)
{
    dim3 grid(N / 64, M / 128);
    hmma_kernel<<<grid, 256, HM_SMEM>>>(M, N, Nreal, K, Ahi, Alo, Bhi, Blo,
                                        C, ldc, bias, Cinit);
}

extern "C" void kernel_launch(void* const* d_in, const int* in_sizes, int n_in,
                              void* d_out, int out_size)
{
    const float* features  = (const float*)d_in[0];
    const int*   captions  = (const int*)  d_in[1];
    const float* embedding = (const float*)d_in[2];
    const float* W_enc     = (const float*)d_in[3];
    const float* b_enc     = (const float*)d_in[4];
    const float* W_dec     = (const float*)d_in[5];
    const float* b_dec     = (const float*)d_in[6];
    const float* w_att     = (const float*)d_in[7];
    // d_in[8] = b_att : softmax-invariant, unused
    const float* Wi_h      = (const float*)d_in[9];
    const float* bi_h      = (const float*)d_in[10];
    const float* Wi_c      = (const float*)d_in[11];
    const float* bi_c      = (const float*)d_in[12];
    const float* W_ih      = (const float*)d_in[13];
    const float* b_ih      = (const float*)d_in[14];
    const float* W_hh      = (const float*)d_in[15];
    const float* b_hh      = (const float*)d_in[16];
    const float* W_out     = (const float*)d_in[17];
    const float* b_out     = (const float*)d_in[18];
    float* out = (float*)d_out;

    cudaFuncSetAttribute(hmma_kernel,     cudaFuncAttributeMaxDynamicSharedMemorySize, HM_SMEM);
    cudaFuncSetAttribute(hmma_big_kernel, cudaFuncAttributeMaxDynamicSharedMemorySize, BIG_SMEM);

    float *featproj, *embgates, *bh, *bias2, *meanf, *h0, *c, *hproj;
    __nv_bfloat16 *fhi, *flo, *wenchi, *wenclo, *wihhi, *wihlo, *wihchi, *wihclo,
                  *whcthi, *whctlo, *wouthi, *woutlo, *eahi, *ealo,
                  *Hhi, *Hlo, *h0hi, *h0lo, *ctxhi, *ctxlo;
    cudaGetSymbolAddress((void**)&featproj, g_featproj);
    cudaGetSymbolAddress((void**)&embgates, g_embgates);
    cudaGetSymbolAddress((void**)&bh,       g_bh);
    cudaGetSymbolAddress((void**)&bias2,    g_bias2);
    cudaGetSymbolAddress((void**)&meanf,    g_meanf);
    cudaGetSymbolAddress((void**)&h0,       g_h0);
    cudaGetSymbolAddress((void**)&c,        g_c);
    cudaGetSymbolAddress((void**)&hproj,    g_hproj);
    cudaGetSymbolAddress((void**)&fhi,      g_feat_hi);
    cudaGetSymbolAddress((void**)&flo,      g_feat_lo);
    cudaGetSymbolAddress((void**)&wenchi,   g_WencT_hi);
    cudaGetSymbolAddress((void**)&wenclo,   g_WencT_lo);
    cudaGetSymbolAddress((void**)&wihhi,    g_WihT_hi);
    cudaGetSymbolAddress((void**)&wihlo,    g_WihT_lo);
    cudaGetSymbolAddress((void**)&wihchi,   g_WihcT_hi);
    cudaGetSymbolAddress((void**)&wihclo,   g_WihcT_lo);
    cudaGetSymbolAddress((void**)&whcthi,   g_whcatT_hi);
    cudaGetSymbolAddress((void**)&whctlo,   g_whcatT_lo);
    cudaGetSymbolAddress((void**)&wouthi,   g_WoutT_hi);
    cudaGetSymbolAddress((void**)&woutlo,   g_WoutT_lo);
    cudaGetSymbolAddress((void**)&eahi,     g_embA_hi);
    cudaGetSymbolAddress((void**)&ealo,     g_embA_lo);
    cudaGetSymbolAddress((void**)&Hhi,      g_H_hi);
    cudaGetSymbolAddress((void**)&Hlo,      g_H_lo);
    cudaGetSymbolAddress((void**)&h0hi,     g_h0_hi);
    cudaGetSymbolAddress((void**)&h0lo,     g_h0_lo);
    cudaGetSymbolAddress((void**)&ctxhi,    g_ctx_hi);
    cudaGetSymbolAddress((void**)&ctxlo,    g_ctx_lo);

    dim3 tthr(32, 8);

    // ---- prep, ordered so the featproj big GEMM is launch #4 (ncu slot) ----
    {
        size_t n4 = (size_t)Bv * Nv * ENCv / 4;
        conv4_hilo_kernel<<<(unsigned)((n4 + 255) / 256), 256>>>(
            (const float4*)features, n4, (__nv_bfloat162*)fhi, (__nv_bfloat162*)flo);     // 1
    }
    trans_hilo_kernel<<<dim3(16, 16), tthr>>>(W_enc, ENCv, Av, wenchi, wenclo, ENCv, Av); // 2
    whcatT_hilo_kernel<<<(HW * Dv + 255) / 256, 256>>>(W_dec, W_hh, whcthi, whctlo);      // 3
    // featproj = features @ W_enc + b_enc     <- PROFILED LAUNCH (#4)
    launch_big(Bv * Nv, Av, Av, ENCv, fhi, flo, wenchi, wenclo,
               featproj, Av, b_enc, 0);                                                   // 4
    biases_kernel<<<(HW + 255) / 256, 256>>>(b_dec, b_ih, b_hh, bh, bias2);               // 5
    embgather_hilo_kernel<<<(Tv * Bv * KE + 255) / 256, 256>>>(embedding, captions,
                                                               eahi, ealo);               // 6
    trans_hilo_kernel<<<dim3((G4D + 31) / 32, (KE + 31) / 32), tthr>>>(
        W_ih, Ev, G4D, wihhi, wihlo, KE, G4D);                                            // 7
    launch_big(Tv * Bv, G4D, G4D, KE, eahi, ealo, wihhi, wihlo,
               embgates, G4D, bias2, 0);                                                  // 8
    trans_hilo_kernel<<<dim3((G4D + 31) / 32, (Dv + 31) / 32), tthr>>>(
        W_ih + (size_t)Ev * G4D, Dv, G4D, wihchi, wihclo, Dv, G4D);                       // 9
    trans_hilo_kernel<<<dim3((VP + 31) / 32, (Dv + 31) / 32), tthr>>>(
        W_out, Dv, Vv, wouthi, woutlo, Dv, VP);                                           // 10
    meanf_kernel<<<Bv, 256>>>(features, meanf);                                           // 11
    {
        dim3 g(Dv / 64, Bv / 32);
        sgemm_kernel<32, 64, 16, 2, 4><<<g, 256>>>(Bv, Dv, ENCv, meanf, ENCv,
                                                   Wi_h, Dv, h0, Dv, bi_h);               // 12
        sgemm_kernel<32, 64, 16, 2, 4><<<g, 256>>>(Bv, Dv, ENCv, meanf, ENCv,
                                                   Wi_c, Dv, c, Dv, bi_c);                // 13
    }
    conv_hilo_kernel<<<(Bv * Dv + 255) / 256, 256>>>(h0, (size_t)Bv * Dv, h0hi, h0lo);    // 14

    const size_t PRED = (size_t)Bv * Tv * Vv;

    for (int t = 0; t < Tv; t++) {
        const __nv_bfloat16* hpHi = (t == 0) ? h0hi : (Hhi + (size_t)(t - 1) * Bv * Dv);
        const __nv_bfloat16* hpLo = (t == 0) ? h0lo : (Hlo + (size_t)(t - 1) * Bv * Dv);
        // hproj = h @ [W_dec | W_hh] + [b_dec | 0]
        launch_loop(Bv, HW, HW, Dv, hpHi, hpLo, whcthi, whctlo,
                    hproj, HW, bh, nullptr);
        // attention -> ctx hi/lo, alphas[:, t, :]
        attention_kernel<<<Bv, 256>>>(featproj, features, hproj, w_att,
                                      ctxhi, ctxlo, out + PRED + (size_t)t * Nv);
        // gates partial: ctx @ W_ih[E:,:] + embgates[t]  (in-place accumulate)
        launch_loop(Bv, G4D, G4D, Dv, ctxhi, ctxlo, wihchi, wihclo,
                    embgates + (size_t)t * Bv * G4D, G4D, nullptr,
                    embgates + (size_t)t * Bv * G4D);
        // LSTM pointwise -> Hhi/Hlo[t], c
        lstm_kernel<<<(Bv * Dv + 255) / 256, 256>>>(
            embgates + (size_t)t * Bv * G4D, hproj, c,
            Hhi + (size_t)t * Bv * Dv, Hlo + (size_t)t * Bv * Dv);
    }

    // preds: [T*B, V] = H @ W_out^T + b_out, remapped to [B, T, V]
    launch_big(Tv * Bv, VP, Vv, Dv, Hhi, Hlo, wouthi, woutlo,
               out, Vv, b_out, 1);
}

// round 11
// speedup vs baseline: 1.0220x; 1.0220x over previous
#include <cuda_runtime.h>
#include <cuda_bf16.h>
#include <cstdint>
#include <cstddef>

// ---------------- problem constants ----------------
#define Bv   128
#define Nv   196
#define Lv   25
#define Tv   24
#define Vv   10000
#define Ev   300
#define Av   512
#define ENCv 512
#define Dv   512
#define G4D  2048   // 4*D
#define HW   2560   // cols of [W_dec | W_hh]
#define KE   320    // E padded (multiple of 32)
#define VP   10112  // V padded (multiple of 64)

// ---------------- device scratch (static, no allocation) ----------------
__device__ float g_featproj[(size_t)Bv * Nv * Av];
__device__ float g_embgates[(size_t)Tv * Bv * G4D];
__device__ float g_bh[HW];
__device__ float g_bias2[G4D];
__device__ float g_meanf[Bv * ENCv];
__device__ float g_h0[Bv * Dv];
__device__ float g_c[Bv * Dv];
__device__ float g_hproj[Bv * HW];

__device__ __nv_bfloat16 g_feat_hi[(size_t)Bv * Nv * ENCv];
__device__ __nv_bfloat16 g_feat_lo[(size_t)Bv * Nv * ENCv];
__device__ __nv_bfloat16 g_WencT_hi[Av * ENCv];
__device__ __nv_bfloat16 g_WencT_lo[Av * ENCv];
__device__ __nv_bfloat16 g_WihT_hi[G4D * KE];
__device__ __nv_bfloat16 g_WihT_lo[G4D * KE];
__device__ __nv_bfloat16 g_WihcT_hi[G4D * Dv];
__device__ __nv_bfloat16 g_WihcT_lo[G4D * Dv];
__device__ __nv_bfloat16 g_whcatT_hi[HW * Dv];
__device__ __nv_bfloat16 g_whcatT_lo[HW * Dv];
__device__ __nv_bfloat16 g_WoutT_hi[(size_t)VP * Dv];
__device__ __nv_bfloat16 g_WoutT_lo[(size_t)VP * Dv];
__device__ __nv_bfloat16 g_embA_hi[Tv * Bv * KE];
__device__ __nv_bfloat16 g_embA_lo[Tv * Bv * KE];
__device__ __nv_bfloat16 g_H_hi[(size_t)Tv * Bv * Dv];
__device__ __nv_bfloat16 g_H_lo[(size_t)Tv * Bv * Dv];
__device__ __nv_bfloat16 g_h0_hi[Bv * Dv];
__device__ __nv_bfloat16 g_h0_lo[Bv * Dv];
__device__ __nv_bfloat16 g_ctx_hi[Bv * Dv];
__device__ __nv_bfloat16 g_ctx_lo[Bv * Dv];

// ---------------- PTX helpers ----------------
__device__ __forceinline__ uint32_t smem_u32(const void* p) {
    uint32_t a;
    asm("{ .reg .u64 t; cvta.to.shared.u64 t, %1; cvt.u32.u64 %0, t; }" : "=r"(a) : "l"(p));
    return a;
}

#define LDSM4(r, addr) \
    asm volatile("ldmatrix.sync.aligned.m8n8.x4.shared.b16 {%0,%1,%2,%3}, [%4];" \
        : "=r"((r)[0]), "=r"((r)[1]), "=r"((r)[2]), "=r"((r)[3]) : "r"(addr))

#define MMA16816(d, a, b0, b1) \
    asm volatile("mma.sync.aligned.m16n8k16.row.col.f32.bf16.bf16.f32 " \
        "{%0,%1,%2,%3}, {%4,%5,%6,%7}, {%8,%9}, {%0,%1,%2,%3};" \
        : "+f"((d)[0]), "+f"((d)[1]), "+f"((d)[2]), "+f"((d)[3]) \
        : "r"((a)[0]), "r"((a)[1]), "r"((a)[2]), "r"((a)[3]), "r"(b0), "r"(b1))

#define CP16(dst, src) \
    asm volatile("cp.async.cg.shared.global [%0], [%1], 16;" :: "r"(dst), "l"(src) : "memory")
#define CP_COMMIT() asm volatile("cp.async.commit_group;" ::: "memory")
#define CP_WAIT1() asm volatile("cp.async.wait_group 1;" ::: "memory")
#define CP_WAIT0() asm volatile("cp.async.wait_group 0;" ::: "memory")

// =================================================================
// BIG HMMA GEMM: CTA 128x64, 8 warps 4M x 2N (warp tile 32x32),
// BK=32, 2-stage cp.async pipeline, 2 CTAs/SM.
// 8 LDSM / 24 MMA per warp-k16. smem 61440 B (2 stages x 30720).
// C[M,N] = A[M,K] @ Bt[N,K]^T + bias ; remap for logits.
// =================================================================
#define SS       30720
#define POFF_AHI 0
#define POFF_ALO 10240
#define POFF_BHI 20480
#define POFF_BLO 25600
#define BIG_SMEM (2 * SS)   // 61440

__device__ __forceinline__ void big_load_stage(
    uint32_t base,
    const __nv_bfloat16* __restrict__ Ahi, const __nv_bfloat16* __restrict__ Alo,
    const __nv_bfloat16* __restrict__ Bhi, const __nv_bfloat16* __restrict__ Blo,
    int lda, int row0, int col0, int koff, int tid)
{
#pragma unroll
    for (int i = 0; i < 2; i++) {
        const int idx = tid + i * 256;
        const int r = idx >> 2, seg = idx & 3;
        const uint32_t d = base + (uint32_t)(r * 80 + seg * 16);
        const size_t g = (size_t)(row0 + r) * lda + koff + seg * 8;
        CP16(d + POFF_AHI, Ahi + g);
        CP16(d + POFF_ALO, Alo + g);
    }
    {
        const int r = tid >> 2, seg = tid & 3;
        const uint32_t d = base + (uint32_t)(r * 80 + seg * 16);
        const size_t g = (size_t)(col0 + r) * lda + koff + seg * 8;
        CP16(d + POFF_BHI, Bhi + g);
        CP16(d + POFF_BLO, Blo + g);
    }
}

__global__ __launch_bounds__(256, 2)
void hmma_big_kernel(int Nreal, int K,
                     const __nv_bfloat16* __restrict__ Ahi, const __nv_bfloat16* __restrict__ Alo,
                     const __nv_bfloat16* __restrict__ Bhi, const __nv_bfloat16* __restrict__ Blo,
                     float* __restrict__ C, int ldc,
                     const float* __restrict__ bias, int remap)
{
    extern __shared__ char sm[];
    const uint32_t sb = smem_u32(sm);
    const int tid = threadIdx.x;
    const int wid = tid >> 5, lane = tid & 31;
    const int warp_m = wid & 3;          // 4 x 32 rows
    const int warp_n = wid >> 2;         // 2 x 32 cols
    const int row0 = blockIdx.y * 128;
    const int col0 = blockIdx.x * 64;

    float acc[2][4][4];
#pragma unroll
    for (int mt = 0; mt < 2; mt++)
#pragma unroll
        for (int nt = 0; nt < 4; nt++)
#pragma unroll
            for (int r = 0; r < 4; r++) acc[mt][nt][r] = 0.f;

    const int a_lr = lane & 15, a_lk = (lane >> 4) * 8;
    const int b_grp = lane >> 3;
    const int b_lr = (lane & 7) + ((b_grp >> 1) * 8);
    const int b_lk = (b_grp & 1) * 8;

    const int nch = K >> 5;
    big_load_stage(sb, Ahi, Alo, Bhi, Blo, K, row0, col0, 0, tid);
    CP_COMMIT();
    for (int kc = 0; kc < nch; kc++) {
        if (kc + 1 < nch) {
            big_load_stage(sb + (uint32_t)(((kc + 1) & 1) * SS),
                           Ahi, Alo, Bhi, Blo, K, row0, col0, (kc + 1) * 32, tid);
            CP_COMMIT();
            CP_WAIT1();
        } else {
            CP_WAIT0();
        }
        __syncthreads();
        const uint32_t st = sb + (uint32_t)((kc & 1) * SS);
#pragma unroll
        for (int k16 = 0; k16 < 32; k16 += 16) {
            uint32_t aHi[2][4], aLo[2][4], bH[8], bL[8];
#pragma unroll
            for (int mt = 0; mt < 2; mt++) {
                const uint32_t ab = st + (uint32_t)((warp_m * 32 + mt * 16 + a_lr) * 80
                                                    + (k16 + a_lk) * 2);
                LDSM4(aHi[mt], ab + POFF_AHI);
                LDSM4(aLo[mt], ab + POFF_ALO);
            }
#pragma unroll
            for (int half = 0; half < 2; half++) {
                const uint32_t bb = st + (uint32_t)((warp_n * 32 + half * 16 + b_lr) * 80
                                                    + (k16 + b_lk) * 2);
                LDSM4(bH + half * 4, bb + POFF_BHI);
                LDSM4(bL + half * 4, bb + POFF_BLO);
            }
#pragma unroll
            for (int mt = 0; mt < 2; mt++)
#pragma unroll
                for (int nt = 0; nt < 4; nt++) {
                    MMA16816(acc[mt][nt], aHi[mt], bH[nt * 2], bH[nt * 2 + 1]);
                    MMA16816(acc[mt][nt], aLo[mt], bH[nt * 2], bH[nt * 2 + 1]);
                    MMA16816(acc[mt][nt], aHi[mt], bL[nt * 2], bL[nt * 2 + 1]);
                }
        }
        __syncthreads();
    }

    const int quad = lane >> 2, tc = lane & 3;
#pragma unroll
    for (int mt = 0; mt < 2; mt++)
#pragma unroll
        for (int half = 0; half < 2; half++) {
            const int gm = row0 + warp_m * 32 + mt * 16 + quad + half * 8;
            const size_t rowC = remap ? ((size_t)(gm & (Bv - 1)) * Tv + (gm >> 7))
                                      : (size_t)gm;
#pragma unroll
            for (int nt = 0; nt < 4; nt++) {
                const int gn = col0 + warp_n * 32 + nt * 8 + tc * 2;
                if (gn >= Nreal) continue;
                const float2 bv = *(const float2*)&bias[gn];
                float2 o;
                o.x = acc[mt][nt][half * 2]     + bv.x;
                o.y = acc[mt][nt][half * 2 + 1] + bv.y;
                *(float2*)&C[rowC * (size_t)ldc + gn] = o;
            }
        }
}

// =================================================================
// Loop HMMA GEMM (unchanged from R10): CTA 128x64, 4M x 2N, BK=64
// single-buffered. Cinit for in-place gates accumulate.
// =================================================================
#define OFF_AHI 0
#define OFF_ALO (128 * 144)
#define OFF_BHI (256 * 144)
#define OFF_BLO (320 * 144)
#define HM_SMEM (384 * 144)   // 55296

__global__ __launch_bounds__(256, 2)
void hmma_kernel(int M, int N, int Nreal, int K,
                 const __nv_bfloat16* __restrict__ Ahi, const __nv_bfloat16* __restrict__ Alo,
                 const __nv_bfloat16* __restrict__ Bhi, const __nv_bfloat16* __restrict__ Blo,
                 float* __restrict__ C, int ldc,
                 const float* __restrict__ bias,
                 const float* __restrict__ Cinit)
{
    extern __shared__ char sm[];
    const uint32_t sb = smem_u32(sm);
    const int tid = threadIdx.x;
    const int wid = tid >> 5, lane = tid & 31;
    const int warp_m = wid & 3;
    const int warp_n = wid >> 2;
    const int row0 = blockIdx.y * 128;
    const int col0 = blockIdx.x * 64;

    float acc[2][4][4];
#pragma unroll
    for (int mt = 0; mt < 2; mt++)
#pragma unroll
        for (int nt = 0; nt < 4; nt++)
#pragma unroll
            for (int r = 0; r < 4; r++) acc[mt][nt][r] = 0.f;

    const int a_lr = lane & 15, a_lk = (lane >> 4) * 8;
    const int b_grp = lane >> 3;
    const int b_lr = (lane & 7) + ((b_grp >> 1) * 8);
    const int b_lk = (b_grp & 1) * 8;

    const int nchunks = K >> 6;
    for (int kc = 0; kc < nchunks; kc++) {
        const size_t koff = (size_t)kc * 64;
#pragma unroll 2
        for (int i = tid; i < 1024; i += 256) {
            const int r = i >> 3, s = i & 7;
            const uint32_t d = (uint32_t)(r * 144 + s * 16);
            const size_t g = (size_t)(row0 + r) * K + koff + s * 8;
            *(uint4*)(sm + OFF_AHI + d) = *(const uint4*)(Ahi + g);
            *(uint4*)(sm + OFF_ALO + d) = *(const uint4*)(Alo + g);
        }
#pragma unroll 2
        for (int i = tid; i < 512; i += 256) {
            const int r = i >> 3, s = i & 7;
            const uint32_t d = (uint32_t)(r * 144 + s * 16);
            const size_t g = (size_t)(col0 + r) * K + koff + s * 8;
            *(uint4*)(sm + OFF_BHI + d) = *(const uint4*)(Bhi + g);
            *(uint4*)(sm + OFF_BLO + d) = *(const uint4*)(Blo + g);
        }
        __syncthreads();

#pragma unroll
        for (int k16 = 0; k16 < 64; k16 += 16) {
            uint32_t aHi[2][4], aLo[2][4], bH[8], bL[8];
#pragma unroll
            for (int mt = 0; mt < 2; mt++) {
                const uint32_t ab = (uint32_t)((warp_m * 32 + mt * 16 + a_lr) * 144
                                               + (k16 + a_lk) * 2);
                LDSM4(aHi[mt], sb + OFF_AHI + ab);
                LDSM4(aLo[mt], sb + OFF_ALO + ab);
            }
#pragma unroll
            for (int half = 0; half < 2; half++) {
                const uint32_t bb = (uint32_t)((warp_n * 32 + half * 16 + b_lr) * 144
                                               + (k16 + b_lk) * 2);
                LDSM4(bH + half * 4, sb + OFF_BHI + bb);
                LDSM4(bL + half * 4, sb + OFF_BLO + bb);
            }
#pragma unroll
            for (int mt = 0; mt < 2; mt++)
#pragma unroll
                for (int nt = 0; nt < 4; nt++) {
                    MMA16816(acc[mt][nt], aHi[mt], bH[nt * 2], bH[nt * 2 + 1]);
                    MMA16816(acc[mt][nt], aLo[mt], bH[nt * 2], bH[nt * 2 + 1]);
                    MMA16816(acc[mt][nt], aHi[mt], bL[nt * 2], bL[nt * 2 + 1]);
                }
        }
        __syncthreads();
    }

    const int quad = lane >> 2, tc = lane & 3;
#pragma unroll
    for (int mt = 0; mt < 2; mt++)
#pragma unroll
        for (int half = 0; half < 2; half++) {
            const int gm = row0 + warp_m * 32 + mt * 16 + quad + half * 8;
#pragma unroll
            for (int nt = 0; nt < 4; nt++) {
                const int gn = col0 + warp_n * 32 + nt * 8 + tc * 2;
                if (gn >= Nreal) continue;
                float v0 = acc[mt][nt][half * 2];
                float v1 = acc[mt][nt][half * 2 + 1];
                if (bias) {
                    const float2 bv = *(const float2*)&bias[gn];
                    v0 += bv.x; v1 += bv.y;
                }
                if (Cinit) {
                    const float2 cv = *(const float2*)&Cinit[(size_t)gm * ldc + gn];
                    v0 += cv.x; v1 += cv.y;
                }
                float2 o; o.x = v0; o.y = v1;
                *(float2*)&C[(size_t)gm * ldc + gn] = o;
            }
        }
}

// =================================================================
// Small fp32 SGEMM (one-time h0/c0 init only)
// =================================================================
template<int BM, int BN, int BK, int TM, int TN>
__global__ void sgemm_kernel(int M, int N, int K,
                             const float* __restrict__ A, int lda,
                             const float* __restrict__ B, int ldb,
                             float* __restrict__ C, int ldc,
                             const float* __restrict__ bias)
{
    constexpr int TX = BN / TN;
    constexpr int TY = BM / TM;
    constexpr int NT = TX * TY;
    __shared__ float As[BK][BM + 1];
    __shared__ float Bs[BK][BN];

    const int tid = threadIdx.x;
    const int tx = tid % TX, ty = tid / TX;
    const int row0 = blockIdx.y * BM;
    const int col0 = blockIdx.x * BN;

    float acc[TM][TN];
#pragma unroll
    for (int i = 0; i < TM; i++)
#pragma unroll
        for (int j = 0; j < TN; j++) acc[i][j] = 0.f;

    for (int k0 = 0; k0 < K; k0 += BK) {
#pragma unroll
        for (int i = tid; i < BM * BK; i += NT) {
            int m = i / BK, k = i % BK;
            As[k][m] = A[(size_t)(row0 + m) * lda + k0 + k];
        }
#pragma unroll
        for (int i = tid; i < BK * BN; i += NT) {
            int k = i / BN, n = i % BN;
            Bs[k][n] = B[(size_t)(k0 + k) * ldb + col0 + n];
        }
        __syncthreads();
#pragma unroll
        for (int kk = 0; kk < BK; kk++) {
            float ra[TM], rb[TN];
#pragma unroll
            for (int i = 0; i < TM; i++) ra[i] = As[kk][ty * TM + i];
#pragma unroll
            for (int j = 0; j < TN; j++) rb[j] = Bs[kk][tx * TN + j];
#pragma unroll
            for (int i = 0; i < TM; i++)
#pragma unroll
                for (int j = 0; j < TN; j++)
                    acc[i][j] = fmaf(ra[i], rb[j], acc[i][j]);
        }
        __syncthreads();
    }

#pragma unroll
    for (int i = 0; i < TM; i++)
#pragma unroll
        for (int j = 0; j < TN; j++) {
            int gm = row0 + ty * TM + i, gn = col0 + tx * TN + j;
            C[(size_t)gm * ldc + gn] = acc[i][j] + bias[gn];
        }
}

// ---------------- prep kernels ----------------
__device__ __forceinline__ void split_hilo(float v, __nv_bfloat16& h, __nv_bfloat16& l) {
    h = __float2bfloat16(v);
    l = __float2bfloat16(v - __bfloat162float(h));
}

__global__ void whcatT_hilo_kernel(const float* __restrict__ Wdec, const float* __restrict__ Whh,
                                   __nv_bfloat16* __restrict__ hi, __nv_bfloat16* __restrict__ lo)
{
    int idx = blockIdx.x * blockDim.x + threadIdx.x;
    if (idx >= HW * Dv) return;
    int k = idx & 511, n = idx >> 9;
    float v = (n < 512) ? Wdec[(size_t)k * Av + n]
                        : Whh[(size_t)k * G4D + (n - 512)];
    split_hilo(v, hi[idx], lo[idx]);
}

__global__ void biases_kernel(const float* __restrict__ bdec,
                              const float* __restrict__ bih, const float* __restrict__ bhh,
                              float* __restrict__ bh, float* __restrict__ b2)
{
    int j = blockIdx.x * blockDim.x + threadIdx.x;
    if (j < HW)  bh[j] = (j < 512) ? bdec[j] : 0.f;
    if (j < G4D) b2[j] = bih[j] + bhh[j];
}

__global__ void embgather_hilo_kernel(const float* __restrict__ emb, const int* __restrict__ cap,
                                      __nv_bfloat16* __restrict__ hi, __nv_bfloat16* __restrict__ lo)
{
    int idx = blockIdx.x * blockDim.x + threadIdx.x;
    if (idx >= Tv * Bv * KE) return;
    int k = idx % KE, r = idx / KE;
    int t = r / Bv, b = r % Bv;
    float v = 0.f;
    if (k < Ev) v = emb[(size_t)cap[b * Lv + t] * Ev + k];
    split_hilo(v, hi[idx], lo[idx]);
}

__global__ void conv_hilo_kernel(const float* __restrict__ in, size_t n,
                                 __nv_bfloat16* __restrict__ hi, __nv_bfloat16* __restrict__ lo)
{
    size_t idx = (size_t)blockIdx.x * blockDim.x + threadIdx.x;
    if (idx >= n) return;
    split_hilo(in[idx], hi[idx], lo[idx]);
}

__global__ void conv4_hilo_kernel(const float4* __restrict__ in, size_t n4,
                                  __nv_bfloat162* __restrict__ hi, __nv_bfloat162* __restrict__ lo)
{
    size_t idx = (size_t)blockIdx.x * blockDim.x + threadIdx.x;
    if (idx >= n4) return;
    float4 v = in[idx];
    __nv_bfloat16 h0, l0, h1, l1, h2, l2, h3, l3;
    split_hilo(v.x, h0, l0); split_hilo(v.y, h1, l1);
    split_hilo(v.z, h2, l2); split_hilo(v.w, h3, l3);
    hi[idx * 2]     = __nv_bfloat162(h0, h1);
    hi[idx * 2 + 1] = __nv_bfloat162(h2, h3);
    lo[idx * 2]     = __nv_bfloat162(l0, l1);
    lo[idx * 2 + 1] = __nv_bfloat162(l2, l3);
}

__global__ void trans_hilo_kernel(const float* __restrict__ in, int R, int C,
                                  __nv_bfloat16* __restrict__ hi, __nv_bfloat16* __restrict__ lo,
                                  int Kpad, int Npad)
{
    __shared__ float t[32][33];
    const int cb = blockIdx.x * 32;
    const int rb = blockIdx.y * 32;
    const int x = threadIdx.x, y = threadIdx.y;
#pragma unroll
    for (int i = y; i < 32; i += 8) {
        int r = rb + i, ccol = cb + x;
        t[i][x] = (r < R && ccol < C) ? in[(size_t)r * C + ccol] : 0.f;
    }
    __syncthreads();
#pragma unroll
    for (int i = y; i < 32; i += 8) {
        int n = cb + i, k = rb + x;
        if (n < Npad && k < Kpad) {
            size_t o = (size_t)n * Kpad + k;
            split_hilo(t[x][i], hi[o], lo[o]);
        }
    }
}

__global__ void meanf_kernel(const float* __restrict__ feat, float* __restrict__ mf)
{
    int b = blockIdx.x, tid = threadIdx.x;
    for (int d = tid; d < ENCv; d += 256) {
        float s = 0.f;
        const float* p = feat + (size_t)b * Nv * ENCv + d;
#pragma unroll 4
        for (int n = 0; n < Nv; n++) s += p[(size_t)n * ENCv];
        mf[b * ENCv + d] = s * (1.0f / (float)Nv);
    }
}

// ---------------- fused attention ----------------
__global__ void attention_kernel(const float* __restrict__ fp,
                                 const float* __restrict__ feat,
                                 const float* __restrict__ dec,   // hproj[:, :512], ld=HW
                                 const float* __restrict__ watt,
                                 __nv_bfloat16* __restrict__ ctxHi,
                                 __nv_bfloat16* __restrict__ ctxLo,
                                 float* __restrict__ alphaOut)
{
    __shared__ float s_dec[Av];
    __shared__ float s_watt[Av];
    __shared__ float s_sc[Nv];
    __shared__ float s_red[8];
    const int b = blockIdx.x, tid = threadIdx.x;

    for (int i = tid; i < Av; i += 256) { s_dec[i] = dec[(size_t)b * HW + i]; s_watt[i] = watt[i]; }
    __syncthreads();

    const int warp = tid >> 5, lane = tid & 31;
    const float* fpb = fp + (size_t)b * Nv * Av;
    for (int n = warp; n < Nv; n += 8) {
        const float* row = fpb + (size_t)n * Av;
        float s = 0.f;
#pragma unroll 4
        for (int k = lane; k < Av; k += 32) {
            float x = row[k] + s_dec[k];
            float th;
            asm("tanh.approx.f32 %0, %1;" : "=f"(th) : "f"(x));
            s = fmaf(th, s_watt[k], s);
        }
#pragma unroll
        for (int o = 16; o; o >>= 1) s += __shfl_xor_sync(0xffffffffu, s, o);
        if (lane == 0) s_sc[n] = s;
    }
    __syncthreads();

    float m = -1e30f;
    for (int n = tid; n < Nv; n += 256) m = fmaxf(m, s_sc[n]);
#pragma unroll
    for (int o = 16; o; o >>= 1) m = fmaxf(m, __shfl_xor_sync(0xffffffffu, m, o));
    if (lane == 0) s_red[warp] = m;
    __syncthreads();
    if (tid == 0) {
        float mm = s_red[0];
        for (int w = 1; w < 8; w++) mm = fmaxf(mm, s_red[w]);
        s_red[0] = mm;
    }
    __syncthreads();
    m = s_red[0];
    __syncthreads();

    float sum = 0.f;
    for (int n = tid; n < Nv; n += 256) {
        float e = __expf(s_sc[n] - m);
        s_sc[n] = e;
        sum += e;
    }
#pragma unroll
    for (int o = 16; o; o >>= 1) sum += __shfl_xor_sync(0xffffffffu, sum, o);
    if (lane == 0) s_red[warp] = sum;
    __syncthreads();
    if (tid == 0) {
        float ss = 0.f;
        for (int w = 0; w < 8; w++) ss += s_red[w];
        s_red[0] = 1.f / ss;
    }
    __syncthreads();
    const float inv = s_red[0];
    for (int n = tid; n < Nv; n += 256) {
        float a = s_sc[n] * inv;
        s_sc[n] = a;
        alphaOut[(size_t)b * Tv * Nv + n] = a;
    }
    __syncthreads();

    const float* fb = feat + (size_t)b * Nv * ENCv;
    for (int d = tid; d < ENCv; d += 256) {
        float acc = 0.f;
#pragma unroll 4
        for (int n = 0; n < Nv; n++) acc = fmaf(s_sc[n], fb[(size_t)n * ENCv + d], acc);
        split_hilo(acc, ctxHi[b * ENCv + d], ctxLo[b * ENCv + d]);
    }
}

// ---------------- LSTM pointwise ----------------
__global__ void lstm_kernel(const float* __restrict__ gpart,
                            const float* __restrict__ hproj,
                            float* __restrict__ c,
                            __nv_bfloat16* __restrict__ hHi,
                            __nv_bfloat16* __restrict__ hLo)
{
    int idx = blockIdx.x * blockDim.x + threadIdx.x;
    if (idx >= Bv * Dv) return;
    int b = idx >> 9, d = idx & 511;
    const float* gp = gpart + (size_t)b * G4D;
    const float* hp = hproj + (size_t)b * HW + 512;
    float gi = gp[d]          + hp[d];
    float gf = gp[Dv + d]     + hp[Dv + d];
    float gg = gp[2 * Dv + d] + hp[2 * Dv + d];
    float go = gp[3 * Dv + d] + hp[3 * Dv + d];
    float si = 1.f / (1.f + __expf(-gi));
    float sf = 1.f / (1.f + __expf(-gf));
    float so = 1.f / (1.f + __expf(-go));
    float tg = tanhf(gg);
    float cn = sf * c[idx] + si * tg;
    c[idx] = cn;
    float h = so * tanhf(cn);
    split_hilo(h, hHi[idx], hLo[idx]);
}

// ---------------- host helpers ----------------
static void launch_big(int M, int N, int Nreal, int K,
                       const __nv_bfloat16* Ahi, const __nv_bfloat16* Alo,
                       const __nv_bfloat16* Bhi, const __nv_bfloat16* Blo,
                       float* C, int ldc, const float* bias, int remap)
{
    dim3 grid(N / 64, M / 128);
    hmma_big_kernel<<<grid, 256, BIG_SMEM>>>(Nreal, K, Ahi, Alo, Bhi, Blo,
                                             C, ldc, bias, remap);
}

static void launch_loop(int M, int N, int Nreal, int K,
                        const __nv_bfloat16* Ahi, const __nv_bfloat16* Alo,
                        const __nv_bfloat16* Bhi, const __nv_bfloat16* Blo,
                        float* C, int ldc, const float* bias, const float* Cinit)
{
    dim3 grid(N / 64, M / 128);
    hmma_kernel<<<grid, 256, HM_SMEM>>>(M, N, Nreal, K, Ahi, Alo, Bhi, Blo,
                                        C, ldc, bias, Cinit);
}

extern "C" void kernel_launch(void* const* d_in, const int* in_sizes, int n_in,
                              void* d_out, int out_size)
{
    const float* features  = (const float*)d_in[0];
    const int*   captions  = (const int*)  d_in[1];
    const float* embedding = (const float*)d_in[2];
    const float* W_enc     = (const float*)d_in[3];
    const float* b_enc     = (const float*)d_in[4];
    const float* W_dec     = (const float*)d_in[5];
    const float* b_dec     = (const float*)d_in[6];
    const float* w_att     = (const float*)d_in[7];
    // d_in[8] = b_att : softmax-invariant, unused
    const float* Wi_h      = (const float*)d_in[9];
    const float* bi_h      = (const float*)d_in[10];
    const float* Wi_c      = (const float*)d_in[11];
    const float* bi_c      = (const float*)d_in[12];
    const float* W_ih      = (const float*)d_in[13];
    const float* b_ih      = (const float*)d_in[14];
    const float* W_hh      = (const float*)d_in[15];
    const float* b_hh      = (const float*)d_in[16];
    const float* W_out     = (const float*)d_in[17];
    const float* b_out     = (const float*)d_in[18];
    float* out = (float*)d_out;

    cudaFuncSetAttribute(hmma_kernel,     cudaFuncAttributeMaxDynamicSharedMemorySize, HM_SMEM);
    cudaFuncSetAttribute(hmma_big_kernel, cudaFuncAttributeMaxDynamicSharedMemorySize, BIG_SMEM);

    float *featproj, *embgates, *bh, *bias2, *meanf, *h0, *c, *hproj;
    __nv_bfloat16 *fhi, *flo, *wenchi, *wenclo, *wihhi, *wihlo, *wihchi, *wihclo,
                  *whcthi, *whctlo, *wouthi, *woutlo, *eahi, *ealo,
                  *Hhi, *Hlo, *h0hi, *h0lo, *ctxhi, *ctxlo;
    cudaGetSymbolAddress((void**)&featproj, g_featproj);
    cudaGetSymbolAddress((void**)&embgates, g_embgates);
    cudaGetSymbolAddress((void**)&bh,       g_bh);
    cudaGetSymbolAddress((void**)&bias2,    g_bias2);
    cudaGetSymbolAddress((void**)&meanf,    g_meanf);
    cudaGetSymbolAddress((void**)&h0,       g_h0);
    cudaGetSymbolAddress((void**)&c,        g_c);
    cudaGetSymbolAddress((void**)&hproj,    g_hproj);
    cudaGetSymbolAddress((void**)&fhi,      g_feat_hi);
    cudaGetSymbolAddress((void**)&flo,      g_feat_lo);
    cudaGetSymbolAddress((void**)&wenchi,   g_WencT_hi);
    cudaGetSymbolAddress((void**)&wenclo,   g_WencT_lo);
    cudaGetSymbolAddress((void**)&wihhi,    g_WihT_hi);
    cudaGetSymbolAddress((void**)&wihlo,    g_WihT_lo);
    cudaGetSymbolAddress((void**)&wihchi,   g_WihcT_hi);
    cudaGetSymbolAddress((void**)&wihclo,   g_WihcT_lo);
    cudaGetSymbolAddress((void**)&whcthi,   g_whcatT_hi);
    cudaGetSymbolAddress((void**)&whctlo,   g_whcatT_lo);
    cudaGetSymbolAddress((void**)&wouthi,   g_WoutT_hi);
    cudaGetSymbolAddress((void**)&woutlo,   g_WoutT_lo);
    cudaGetSymbolAddress((void**)&eahi,     g_embA_hi);
    cudaGetSymbolAddress((void**)&ealo,     g_embA_lo);
    cudaGetSymbolAddress((void**)&Hhi,      g_H_hi);
    cudaGetSymbolAddress((void**)&Hlo,      g_H_lo);
    cudaGetSymbolAddress((void**)&h0hi,     g_h0_hi);
    cudaGetSymbolAddress((void**)&h0lo,     g_h0_lo);
    cudaGetSymbolAddress((void**)&ctxhi,    g_ctx_hi);
    cudaGetSymbolAddress((void**)&ctxlo,    g_ctx_lo);

    dim3 tthr(32, 8);

    // ---- prep, ordered so the featproj big GEMM is launch #4 (ncu slot) ----
    {
        size_t n4 = (size_t)Bv * Nv * ENCv / 4;
        conv4_hilo_kernel<<<(unsigned)((n4 + 255) / 256), 256>>>(
            (const float4*)features, n4, (__nv_bfloat162*)fhi, (__nv_bfloat162*)flo);     // 1
    }
    trans_hilo_kernel<<<dim3(16, 16), tthr>>>(W_enc, ENCv, Av, wenchi, wenclo, ENCv, Av); // 2
    whcatT_hilo_kernel<<<(HW * Dv + 255) / 256, 256>>>(W_dec, W_hh, whcthi, whctlo);      // 3
    // featproj = features @ W_enc + b_enc     <- PROFILED LAUNCH (#4)
    launch_big(Bv * Nv, Av, Av, ENCv, fhi, flo, wenchi, wenclo,
               featproj, Av, b_enc, 0);                                                   // 4
    biases_kernel<<<(HW + 255) / 256, 256>>>(b_dec, b_ih, b_hh, bh, bias2);               // 5
    embgather_hilo_kernel<<<(Tv * Bv * KE + 255) / 256, 256>>>(embedding, captions,
                                                               eahi, ealo);               // 6
    trans_hilo_kernel<<<dim3((G4D + 31) / 32, (KE + 31) / 32), tthr>>>(
        W_ih, Ev, G4D, wihhi, wihlo, KE, G4D);                                            // 7
    launch_big(Tv * Bv, G4D, G4D, KE, eahi, ealo, wihhi, wihlo,
               embgates, G4D, bias2, 0);                                                  // 8
    trans_hilo_kernel<<<dim3((G4D + 31) / 32, (Dv + 31) / 32), tthr>>>(
        W_ih + (size_t)Ev * G4D, Dv, G4D, wihchi, wihclo, Dv, G4D);                       // 9
    trans_hilo_kernel<<<dim3((VP + 31) / 32, (Dv + 31) / 32), tthr>>>(
        W_out, Dv, Vv, wouthi, woutlo, Dv, VP);                                           // 10
    meanf_kernel<<<Bv, 256>>>(features, meanf);                                           // 11
    {
        dim3 g(Dv / 64, Bv / 32);
        sgemm_kernel<32, 64, 16, 2, 4><<<g, 256>>>(Bv, Dv, ENCv, meanf, ENCv,
                                                   Wi_h, Dv, h0, Dv, bi_h);               // 12
        sgemm_kernel<32, 64, 16, 2, 4><<<g, 256>>>(Bv, Dv, ENCv, meanf, ENCv,
                                                   Wi_c, Dv, c, Dv, bi_c);                // 13
    }
    conv_hilo_kernel<<<(Bv * Dv + 255) / 256, 256>>>(h0, (size_t)Bv * Dv, h0hi, h0lo);    // 14

    const size_t PRED = (size_t)Bv * Tv * Vv;

    for (int t = 0; t < Tv; t++) {
        const __nv_bfloat16* hpHi = (t == 0) ? h0hi : (Hhi + (size_t)(t - 1) * Bv * Dv);
        const __nv_bfloat16* hpLo = (t == 0) ? h0lo : (Hlo + (size_t)(t - 1) * Bv * Dv);
        // hproj = h @ [W_dec | W_hh] + [b_dec | 0]
        launch_loop(Bv, HW, HW, Dv, hpHi, hpLo, whcthi, whctlo,
                    hproj, HW, bh, nullptr);
        // attention -> ctx hi/lo, alphas[:, t, :]
        attention_kernel<<<Bv, 256>>>(featproj, features, hproj, w_att,
                                      ctxhi, ctxlo, out + PRED + (size_t)t * Nv);
        // gates partial: ctx @ W_ih[E:,:] + embgates[t]  (in-place accumulate)
        launch_loop(Bv, G4D, G4D, Dv, ctxhi, ctxlo, wihchi, wihclo,
                    embgates + (size_t)t * Bv * G4D, G4D, nullptr,
                    embgates + (size_t)t * Bv * G4D);
        // LSTM pointwise -> Hhi/Hlo[t], c
        lstm_kernel<<<(Bv * Dv + 255) / 256, 256>>>(
            embgates + (size_t)t * Bv * G4D, hproj, c,
            Hhi + (size_t)t * Bv * Dv, Hlo + (size_t)t * Bv * Dv);
    }

    // preds: [T*B, V] = H @ W_out^T + b_out, remapped to [B, T, V]
    launch_big(Tv * Bv, VP, Vv, Dv, Hhi, Hlo, wouthi, woutlo,
               out, Vv, b_out, 1);
}

// round 12
// speedup vs baseline: 1.1391x; 1.1146x over previous
#include <cuda_runtime.h>
#include <cuda_bf16.h>
#include <cstdint>
#include <cstddef>

// ---------------- problem constants ----------------
#define Bv   128
#define Nv   196
#define Lv   25
#define Tv   24
#define Vv   10000
#define Ev   300
#define Av   512
#define ENCv 512
#define Dv   512
#define G4D  2048   // 4*D
#define HW   2560   // cols of [W_dec | W_hh]
#define KE   320    // E padded (multiple of 32)
#define VP   10112  // V padded (multiple of 64)

// ---------------- device scratch (static, no allocation) ----------------
__device__ float g_featproj[(size_t)Bv * Nv * Av];
__device__ float g_embgates[(size_t)Tv * Bv * G4D];
__device__ float g_bh[HW];
__device__ float g_bias2[G4D];
__device__ float g_meanf[Bv * ENCv];
__device__ float g_h0[Bv * Dv];
__device__ float g_c[Bv * Dv];
__device__ float g_hproj[Bv * HW];

__device__ __nv_bfloat16 g_feat_hi[(size_t)Bv * Nv * ENCv];
__device__ __nv_bfloat16 g_feat_lo[(size_t)Bv * Nv * ENCv];
__device__ __nv_bfloat16 g_WencT_hi[Av * ENCv];
__device__ __nv_bfloat16 g_WencT_lo[Av * ENCv];
__device__ __nv_bfloat16 g_WihT_hi[G4D * KE];
__device__ __nv_bfloat16 g_WihT_lo[G4D * KE];
__device__ __nv_bfloat16 g_WihcT_hi[G4D * Dv];
__device__ __nv_bfloat16 g_WihcT_lo[G4D * Dv];
__device__ __nv_bfloat16 g_whcatT_hi[HW * Dv];
__device__ __nv_bfloat16 g_whcatT_lo[HW * Dv];
__device__ __nv_bfloat16 g_WoutT_hi[(size_t)VP * Dv];
__device__ __nv_bfloat16 g_WoutT_lo[(size_t)VP * Dv];
__device__ __nv_bfloat16 g_embA_hi[Tv * Bv * KE];
__device__ __nv_bfloat16 g_embA_lo[Tv * Bv * KE];
__device__ __nv_bfloat16 g_H_hi[(size_t)Tv * Bv * Dv];
__device__ __nv_bfloat16 g_H_lo[(size_t)Tv * Bv * Dv];
__device__ __nv_bfloat16 g_h0_hi[Bv * Dv];
__device__ __nv_bfloat16 g_h0_lo[Bv * Dv];
__device__ __nv_bfloat16 g_ctx_hi[Bv * Dv];
__device__ __nv_bfloat16 g_ctx_lo[Bv * Dv];

// ---------------- PTX helpers ----------------
__device__ __forceinline__ uint32_t smem_u32(const void* p) {
    uint32_t a;
    asm("{ .reg .u64 t; cvta.to.shared.u64 t, %1; cvt.u32.u64 %0, t; }" : "=r"(a) : "l"(p));
    return a;
}

#define LDSM4(r, addr) \
    asm volatile("ldmatrix.sync.aligned.m8n8.x4.shared.b16 {%0,%1,%2,%3}, [%4];" \
        : "=r"((r)[0]), "=r"((r)[1]), "=r"((r)[2]), "=r"((r)[3]) : "r"(addr))

#define MMA16816(d, a, b0, b1) \
    asm volatile("mma.sync.aligned.m16n8k16.row.col.f32.bf16.bf16.f32 " \
        "{%0,%1,%2,%3}, {%4,%5,%6,%7}, {%8,%9}, {%0,%1,%2,%3};" \
        : "+f"((d)[0]), "+f"((d)[1]), "+f"((d)[2]), "+f"((d)[3]) \
        : "r"((a)[0]), "r"((a)[1]), "r"((a)[2]), "r"((a)[3]), "r"(b0), "r"(b1))

#define CP16(dst, src) \
    asm volatile("cp.async.cg.shared.global [%0], [%1], 16;" :: "r"(dst), "l"(src) : "memory")
#define CP_COMMIT() asm volatile("cp.async.commit_group;" ::: "memory")
#define CP_WAIT1() asm volatile("cp.async.wait_group 1;" ::: "memory")
#define CP_WAIT0() asm volatile("cp.async.wait_group 0;" ::: "memory")

// =================================================================
// BIG HMMA GEMM: CTA 128x64, 8 warps 4M x 2N, BK=32, 2-stage cp.async,
// 2 CTAs/SM. (unchanged from R11)
// =================================================================
#define SS       30720
#define POFF_AHI 0
#define POFF_ALO 10240
#define POFF_BHI 20480
#define POFF_BLO 25600
#define BIG_SMEM (2 * SS)   // 61440

__device__ __forceinline__ void big_load_stage(
    uint32_t base,
    const __nv_bfloat16* __restrict__ Ahi, const __nv_bfloat16* __restrict__ Alo,
    const __nv_bfloat16* __restrict__ Bhi, const __nv_bfloat16* __restrict__ Blo,
    int lda, int row0, int col0, int koff, int tid)
{
#pragma unroll
    for (int i = 0; i < 2; i++) {
        const int idx = tid + i * 256;
        const int r = idx >> 2, seg = idx & 3;
        const uint32_t d = base + (uint32_t)(r * 80 + seg * 16);
        const size_t g = (size_t)(row0 + r) * lda + koff + seg * 8;
        CP16(d + POFF_AHI, Ahi + g);
        CP16(d + POFF_ALO, Alo + g);
    }
    {
        const int r = tid >> 2, seg = tid & 3;
        const uint32_t d = base + (uint32_t)(r * 80 + seg * 16);
        const size_t g = (size_t)(col0 + r) * lda + koff + seg * 8;
        CP16(d + POFF_BHI, Bhi + g);
        CP16(d + POFF_BLO, Blo + g);
    }
}

__global__ __launch_bounds__(256, 2)
void hmma_big_kernel(int Nreal, int K,
                     const __nv_bfloat16* __restrict__ Ahi, const __nv_bfloat16* __restrict__ Alo,
                     const __nv_bfloat16* __restrict__ Bhi, const __nv_bfloat16* __restrict__ Blo,
                     float* __restrict__ C, int ldc,
                     const float* __restrict__ bias, int remap)
{
    extern __shared__ char sm[];
    const uint32_t sb = smem_u32(sm);
    const int tid = threadIdx.x;
    const int wid = tid >> 5, lane = tid & 31;
    const int warp_m = wid & 3;
    const int warp_n = wid >> 2;
    const int row0 = blockIdx.y * 128;
    const int col0 = blockIdx.x * 64;

    float acc[2][4][4];
#pragma unroll
    for (int mt = 0; mt < 2; mt++)
#pragma unroll
        for (int nt = 0; nt < 4; nt++)
#pragma unroll
            for (int r = 0; r < 4; r++) acc[mt][nt][r] = 0.f;

    const int a_lr = lane & 15, a_lk = (lane >> 4) * 8;
    const int b_grp = lane >> 3;
    const int b_lr = (lane & 7) + ((b_grp >> 1) * 8);
    const int b_lk = (b_grp & 1) * 8;

    const int nch = K >> 5;
    big_load_stage(sb, Ahi, Alo, Bhi, Blo, K, row0, col0, 0, tid);
    CP_COMMIT();
    for (int kc = 0; kc < nch; kc++) {
        if (kc + 1 < nch) {
            big_load_stage(sb + (uint32_t)(((kc + 1) & 1) * SS),
                           Ahi, Alo, Bhi, Blo, K, row0, col0, (kc + 1) * 32, tid);
            CP_COMMIT();
            CP_WAIT1();
        } else {
            CP_WAIT0();
        }
        __syncthreads();
        const uint32_t st = sb + (uint32_t)((kc & 1) * SS);
#pragma unroll
        for (int k16 = 0; k16 < 32; k16 += 16) {
            uint32_t aHi[2][4], aLo[2][4], bH[8], bL[8];
#pragma unroll
            for (int mt = 0; mt < 2; mt++) {
                const uint32_t ab = st + (uint32_t)((warp_m * 32 + mt * 16 + a_lr) * 80
                                                    + (k16 + a_lk) * 2);
                LDSM4(aHi[mt], ab + POFF_AHI);
                LDSM4(aLo[mt], ab + POFF_ALO);
            }
#pragma unroll
            for (int half = 0; half < 2; half++) {
                const uint32_t bb = st + (uint32_t)((warp_n * 32 + half * 16 + b_lr) * 80
                                                    + (k16 + b_lk) * 2);
                LDSM4(bH + half * 4, bb + POFF_BHI);
                LDSM4(bL + half * 4, bb + POFF_BLO);
            }
#pragma unroll
            for (int mt = 0; mt < 2; mt++)
#pragma unroll
                for (int nt = 0; nt < 4; nt++) {
                    MMA16816(acc[mt][nt], aHi[mt], bH[nt * 2], bH[nt * 2 + 1]);
                    MMA16816(acc[mt][nt], aLo[mt], bH[nt * 2], bH[nt * 2 + 1]);
                    MMA16816(acc[mt][nt], aHi[mt], bL[nt * 2], bL[nt * 2 + 1]);
                }
        }
        __syncthreads();
    }

    const int quad = lane >> 2, tc = lane & 3;
#pragma unroll
    for (int mt = 0; mt < 2; mt++)
#pragma unroll
        for (int half = 0; half < 2; half++) {
            const int gm = row0 + warp_m * 32 + mt * 16 + quad + half * 8;
            const size_t rowC = remap ? ((size_t)(gm & (Bv - 1)) * Tv + (gm >> 7))
                                      : (size_t)gm;
#pragma unroll
            for (int nt = 0; nt < 4; nt++) {
                const int gn = col0 + warp_n * 32 + nt * 8 + tc * 2;
                if (gn >= Nreal) continue;
                const float2 bv = *(const float2*)&bias[gn];
                float2 o;
                o.x = acc[mt][nt][half * 2]     + bv.x;
                o.y = acc[mt][nt][half * 2 + 1] + bv.y;
                *(float2*)&C[rowC * (size_t)ldc + gn] = o;
            }
        }
}

// =================================================================
// Loop HMMA GEMM (unchanged): CTA 128x64, 4M x 2N, BK=64 single-buffered.
// =================================================================
#define OFF_AHI 0
#define OFF_ALO (128 * 144)
#define OFF_BHI (256 * 144)
#define OFF_BLO (320 * 144)
#define HM_SMEM (384 * 144)   // 55296

__global__ __launch_bounds__(256, 2)
void hmma_kernel(int M, int N, int Nreal, int K,
                 const __nv_bfloat16* __restrict__ Ahi, const __nv_bfloat16* __restrict__ Alo,
                 const __nv_bfloat16* __restrict__ Bhi, const __nv_bfloat16* __restrict__ Blo,
                 float* __restrict__ C, int ldc,
                 const float* __restrict__ bias,
                 const float* __restrict__ Cinit)
{
    extern __shared__ char sm[];
    const uint32_t sb = smem_u32(sm);
    const int tid = threadIdx.x;
    const int wid = tid >> 5, lane = tid & 31;
    const int warp_m = wid & 3;
    const int warp_n = wid >> 2;
    const int row0 = blockIdx.y * 128;
    const int col0 = blockIdx.x * 64;

    float acc[2][4][4];
#pragma unroll
    for (int mt = 0; mt < 2; mt++)
#pragma unroll
        for (int nt = 0; nt < 4; nt++)
#pragma unroll
            for (int r = 0; r < 4; r++) acc[mt][nt][r] = 0.f;

    const int a_lr = lane & 15, a_lk = (lane >> 4) * 8;
    const int b_grp = lane >> 3;
    const int b_lr = (lane & 7) + ((b_grp >> 1) * 8);
    const int b_lk = (b_grp & 1) * 8;

    const int nchunks = K >> 6;
    for (int kc = 0; kc < nchunks; kc++) {
        const size_t koff = (size_t)kc * 64;
#pragma unroll 2
        for (int i = tid; i < 1024; i += 256) {
            const int r = i >> 3, s = i & 7;
            const uint32_t d = (uint32_t)(r * 144 + s * 16);
            const size_t g = (size_t)(row0 + r) * K + koff + s * 8;
            *(uint4*)(sm + OFF_AHI + d) = *(const uint4*)(Ahi + g);
            *(uint4*)(sm + OFF_ALO + d) = *(const uint4*)(Alo + g);
        }
#pragma unroll 2
        for (int i = tid; i < 512; i += 256) {
            const int r = i >> 3, s = i & 7;
            const uint32_t d = (uint32_t)(r * 144 + s * 16);
            const size_t g = (size_t)(col0 + r) * K + koff + s * 8;
            *(uint4*)(sm + OFF_BHI + d) = *(const uint4*)(Bhi + g);
            *(uint4*)(sm + OFF_BLO + d) = *(const uint4*)(Blo + g);
        }
        __syncthreads();

#pragma unroll
        for (int k16 = 0; k16 < 64; k16 += 16) {
            uint32_t aHi[2][4], aLo[2][4], bH[8], bL[8];
#pragma unroll
            for (int mt = 0; mt < 2; mt++) {
                const uint32_t ab = (uint32_t)((warp_m * 32 + mt * 16 + a_lr) * 144
                                               + (k16 + a_lk) * 2);
                LDSM4(aHi[mt], sb + OFF_AHI + ab);
                LDSM4(aLo[mt], sb + OFF_ALO + ab);
            }
#pragma unroll
            for (int half = 0; half < 2; half++) {
                const uint32_t bb = (uint32_t)((warp_n * 32 + half * 16 + b_lr) * 144
                                               + (k16 + b_lk) * 2);
                LDSM4(bH + half * 4, sb + OFF_BHI + bb);
                LDSM4(bL + half * 4, sb + OFF_BLO + bb);
            }
#pragma unroll
            for (int mt = 0; mt < 2; mt++)
#pragma unroll
                for (int nt = 0; nt < 4; nt++) {
                    MMA16816(acc[mt][nt], aHi[mt], bH[nt * 2], bH[nt * 2 + 1]);
                    MMA16816(acc[mt][nt], aLo[mt], bH[nt * 2], bH[nt * 2 + 1]);
                    MMA16816(acc[mt][nt], aHi[mt], bL[nt * 2], bL[nt * 2 + 1]);
                }
        }
        __syncthreads();
    }

    const int quad = lane >> 2, tc = lane & 3;
#pragma unroll
    for (int mt = 0; mt < 2; mt++)
#pragma unroll
        for (int half = 0; half < 2; half++) {
            const int gm = row0 + warp_m * 32 + mt * 16 + quad + half * 8;
#pragma unroll
            for (int nt = 0; nt < 4; nt++) {
                const int gn = col0 + warp_n * 32 + nt * 8 + tc * 2;
                if (gn >= Nreal) continue;
                float v0 = acc[mt][nt][half * 2];
                float v1 = acc[mt][nt][half * 2 + 1];
                if (bias) {
                    const float2 bv = *(const float2*)&bias[gn];
                    v0 += bv.x; v1 += bv.y;
                }
                if (Cinit) {
                    const float2 cv = *(const float2*)&Cinit[(size_t)gm * ldc + gn];
                    v0 += cv.x; v1 += cv.y;
                }
                float2 o; o.x = v0; o.y = v1;
                *(float2*)&C[(size_t)gm * ldc + gn] = o;
            }
        }
}

// =================================================================
// Small fp32 SGEMM (one-time h0/c0 init only)
// =================================================================
template<int BM, int BN, int BK, int TM, int TN>
__global__ void sgemm_kernel(int M, int N, int K,
                             const float* __restrict__ A, int lda,
                             const float* __restrict__ B, int ldb,
                             float* __restrict__ C, int ldc,
                             const float* __restrict__ bias)
{
    constexpr int TX = BN / TN;
    constexpr int TY = BM / TM;
    constexpr int NT = TX * TY;
    __shared__ float As[BK][BM + 1];
    __shared__ float Bs[BK][BN];

    const int tid = threadIdx.x;
    const int tx = tid % TX, ty = tid / TX;
    const int row0 = blockIdx.y * BM;
    const int col0 = blockIdx.x * BN;

    float acc[TM][TN];
#pragma unroll
    for (int i = 0; i < TM; i++)
#pragma unroll
        for (int j = 0; j < TN; j++) acc[i][j] = 0.f;

    for (int k0 = 0; k0 < K; k0 += BK) {
#pragma unroll
        for (int i = tid; i < BM * BK; i += NT) {
            int m = i / BK, k = i % BK;
            As[k][m] = A[(size_t)(row0 + m) * lda + k0 + k];
        }
#pragma unroll
        for (int i = tid; i < BK * BN; i += NT) {
            int k = i / BN, n = i % BN;
            Bs[k][n] = B[(size_t)(k0 + k) * ldb + col0 + n];
        }
        __syncthreads();
#pragma unroll
        for (int kk = 0; kk < BK; kk++) {
            float ra[TM], rb[TN];
#pragma unroll
            for (int i = 0; i < TM; i++) ra[i] = As[kk][ty * TM + i];
#pragma unroll
            for (int j = 0; j < TN; j++) rb[j] = Bs[kk][tx * TN + j];
#pragma unroll
            for (int i = 0; i < TM; i++)
#pragma unroll
                for (int j = 0; j < TN; j++)
                    acc[i][j] = fmaf(ra[i], rb[j], acc[i][j]);
        }
        __syncthreads();
    }

#pragma unroll
    for (int i = 0; i < TM; i++)
#pragma unroll
        for (int j = 0; j < TN; j++) {
            int gm = row0 + ty * TM + i, gn = col0 + tx * TN + j;
            C[(size_t)gm * ldc + gn] = acc[i][j] + bias[gn];
        }
}

// ---------------- prep kernels ----------------
__device__ __forceinline__ void split_hilo(float v, __nv_bfloat16& h, __nv_bfloat16& l) {
    h = __float2bfloat16(v);
    l = __float2bfloat16(v - __bfloat162float(h));
}

__global__ void whcatT_hilo_kernel(const float* __restrict__ Wdec, const float* __restrict__ Whh,
                                   __nv_bfloat16* __restrict__ hi, __nv_bfloat16* __restrict__ lo)
{
    int idx = blockIdx.x * blockDim.x + threadIdx.x;
    if (idx >= HW * Dv) return;
    int k = idx & 511, n = idx >> 9;
    float v = (n < 512) ? Wdec[(size_t)k * Av + n]
                        : Whh[(size_t)k * G4D + (n - 512)];
    split_hilo(v, hi[idx], lo[idx]);
}

__global__ void biases_kernel(const float* __restrict__ bdec,
                              const float* __restrict__ bih, const float* __restrict__ bhh,
                              float* __restrict__ bh, float* __restrict__ b2)
{
    int j = blockIdx.x * blockDim.x + threadIdx.x;
    if (j < HW)  bh[j] = (j < 512) ? bdec[j] : 0.f;
    if (j < G4D) b2[j] = bih[j] + bhh[j];
}

__global__ void embgather_hilo_kernel(const float* __restrict__ emb, const int* __restrict__ cap,
                                      __nv_bfloat16* __restrict__ hi, __nv_bfloat16* __restrict__ lo)
{
    int idx = blockIdx.x * blockDim.x + threadIdx.x;
    if (idx >= Tv * Bv * KE) return;
    int k = idx % KE, r = idx / KE;
    int t = r / Bv, b = r % Bv;
    float v = 0.f;
    if (k < Ev) v = emb[(size_t)cap[b * Lv + t] * Ev + k];
    split_hilo(v, hi[idx], lo[idx]);
}

__global__ void conv_hilo_kernel(const float* __restrict__ in, size_t n,
                                 __nv_bfloat16* __restrict__ hi, __nv_bfloat16* __restrict__ lo)
{
    size_t idx = (size_t)blockIdx.x * blockDim.x + threadIdx.x;
    if (idx >= n) return;
    split_hilo(in[idx], hi[idx], lo[idx]);
}

__global__ void conv4_hilo_kernel(const float4* __restrict__ in, size_t n4,
                                  __nv_bfloat162* __restrict__ hi, __nv_bfloat162* __restrict__ lo)
{
    size_t idx = (size_t)blockIdx.x * blockDim.x + threadIdx.x;
    if (idx >= n4) return;
    float4 v = in[idx];
    __nv_bfloat16 h0, l0, h1, l1, h2, l2, h3, l3;
    split_hilo(v.x, h0, l0); split_hilo(v.y, h1, l1);
    split_hilo(v.z, h2, l2); split_hilo(v.w, h3, l3);
    hi[idx * 2]     = __nv_bfloat162(h0, h1);
    hi[idx * 2 + 1] = __nv_bfloat162(h2, h3);
    lo[idx * 2]     = __nv_bfloat162(l0, l1);
    lo[idx * 2 + 1] = __nv_bfloat162(l2, l3);
}

__global__ void trans_hilo_kernel(const float* __restrict__ in, int R, int C,
                                  __nv_bfloat16* __restrict__ hi, __nv_bfloat16* __restrict__ lo,
                                  int Kpad, int Npad)
{
    __shared__ float t[32][33];
    const int cb = blockIdx.x * 32;
    const int rb = blockIdx.y * 32;
    const int x = threadIdx.x, y = threadIdx.y;
#pragma unroll
    for (int i = y; i < 32; i += 8) {
        int r = rb + i, ccol = cb + x;
        t[i][x] = (r < R && ccol < C) ? in[(size_t)r * C + ccol] : 0.f;
    }
    __syncthreads();
#pragma unroll
    for (int i = y; i < 32; i += 8) {
        int n = cb + i, k = rb + x;
        if (n < Npad && k < Kpad) {
            size_t o = (size_t)n * Kpad + k;
            split_hilo(t[x][i], hi[o], lo[o]);
        }
    }
}

__global__ void meanf_kernel(const float* __restrict__ feat, float* __restrict__ mf)
{
    int b = blockIdx.x, tid = threadIdx.x;
    for (int d = tid; d < ENCv; d += 256) {
        float s = 0.f;
        const float* p = feat + (size_t)b * Nv * ENCv + d;
#pragma unroll 4
        for (int n = 0; n < Nv; n++) s += p[(size_t)n * ENCv];
        mf[b * ENCv + d] = s * (1.0f / (float)Nv);
    }
}

// ---------------- fused attention (f16x2 dual-tanh scores) ----------------
__global__ void attention_kernel(const float* __restrict__ fp,
                                 const float* __restrict__ feat,
                                 const float* __restrict__ dec,   // hproj[:, :512], ld=HW
                                 const float* __restrict__ watt,
                                 __nv_bfloat16* __restrict__ ctxHi,
                                 __nv_bfloat16* __restrict__ ctxLo,
                                 float* __restrict__ alphaOut)
{
    __shared__ float s_dec[Av];
    __shared__ float s_watt[Av];
    __shared__ float s_sc[Nv];
    __shared__ float s_red[8];
    const int b = blockIdx.x, tid = threadIdx.x;

    for (int i = tid; i < Av; i += 256) { s_dec[i] = dec[(size_t)b * HW + i]; s_watt[i] = watt[i]; }
    __syncthreads();

    const int warp = tid >> 5, lane = tid & 31;
    const float* fpb = fp + (size_t)b * Nv * Av;
    for (int n = warp; n < Nv; n += 8) {
        const float2* row2 = (const float2*)(fpb + (size_t)n * Av);
        float s = 0.f;
#pragma unroll 4
        for (int k2 = lane; k2 < 256; k2 += 32) {
            const float2 f = row2[k2];
            const float2 d2 = ((const float2*)s_dec)[k2];
            const float x0 = f.x + d2.x;
            const float x1 = f.y + d2.y;
            uint32_t xh, th;
            asm("cvt.rn.f16x2.f32 %0, %1, %2;" : "=r"(xh) : "f"(x1), "f"(x0));
            asm("tanh.approx.f16x2 %0, %1;" : "=r"(th) : "r"(xh));
            float t0, t1;
            asm("{\n\t.reg .f16 a, b;\n\tmov.b32 {a, b}, %2;\n\t"
                "cvt.f32.f16 %0, a;\n\tcvt.f32.f16 %1, b;\n\t}"
                : "=f"(t0), "=f"(t1) : "r"(th));
            const float2 w = ((const float2*)s_watt)[k2];
            s = fmaf(t0, w.x, s);
            s = fmaf(t1, w.y, s);
        }
#pragma unroll
        for (int o = 16; o; o >>= 1) s += __shfl_xor_sync(0xffffffffu, s, o);
        if (lane == 0) s_sc[n] = s;
    }
    __syncthreads();

    float m = -1e30f;
    for (int n = tid; n < Nv; n += 256) m = fmaxf(m, s_sc[n]);
#pragma unroll
    for (int o = 16; o; o >>= 1) m = fmaxf(m, __shfl_xor_sync(0xffffffffu, m, o));
    if (lane == 0) s_red[warp] = m;
    __syncthreads();
    if (tid == 0) {
        float mm = s_red[0];
        for (int w = 1; w < 8; w++) mm = fmaxf(mm, s_red[w]);
        s_red[0] = mm;
    }
    __syncthreads();
    m = s_red[0];
    __syncthreads();

    float sum = 0.f;
    for (int n = tid; n < Nv; n += 256) {
        float e = __expf(s_sc[n] - m);
        s_sc[n] = e;
        sum += e;
    }
#pragma unroll
    for (int o = 16; o; o >>= 1) sum += __shfl_xor_sync(0xffffffffu, sum, o);
    if (lane == 0) s_red[warp] = sum;
    __syncthreads();
    if (tid == 0) {
        float ss = 0.f;
        for (int w = 0; w < 8; w++) ss += s_red[w];
        s_red[0] = 1.f / ss;
    }
    __syncthreads();
    const float inv = s_red[0];
    for (int n = tid; n < Nv; n += 256) {
        float a = s_sc[n] * inv;
        s_sc[n] = a;
        alphaOut[(size_t)b * Tv * Nv + n] = a;
    }
    __syncthreads();

    const float* fb = feat + (size_t)b * Nv * ENCv;
    for (int d = tid; d < ENCv; d += 256) {
        float acc = 0.f;
#pragma unroll 4
        for (int n = 0; n < Nv; n++) acc = fmaf(s_sc[n], fb[(size_t)n * ENCv + d], acc);
        split_hilo(acc, ctxHi[b * ENCv + d], ctxLo[b * ENCv + d]);
    }
}

// ---------------- LSTM pointwise ----------------
__global__ void lstm_kernel(const float* __restrict__ gpart,
                            const float* __restrict__ hproj,
                            float* __restrict__ c,
                            __nv_bfloat16* __restrict__ hHi,
                            __nv_bfloat16* __restrict__ hLo)
{
    int idx = blockIdx.x * blockDim.x + threadIdx.x;
    if (idx >= Bv * Dv) return;
    int b = idx >> 9, d = idx & 511;
    const float* gp = gpart + (size_t)b * G4D;
    const float* hp = hproj + (size_t)b * HW + 512;
    float gi = gp[d]          + hp[d];
    float gf = gp[Dv + d]     + hp[Dv + d];
    float gg = gp[2 * Dv + d] + hp[2 * Dv + d];
    float go = gp[3 * Dv + d] + hp[3 * Dv + d];
    float si = 1.f / (1.f + __expf(-gi));
    float sf = 1.f / (1.f + __expf(-gf));
    float so = 1.f / (1.f + __expf(-go));
    float tg = tanhf(gg);
    float cn = sf * c[idx] + si * tg;
    c[idx] = cn;
    float h = so * tanhf(cn);
    split_hilo(h, hHi[idx], hLo[idx]);
}

// ---------------- host helpers ----------------
static void launch_big(int M, int N, int Nreal, int K,
                       const __nv_bfloat16* Ahi, const __nv_bfloat16* Alo,
                       const __nv_bfloat16* Bhi, const __nv_bfloat16* Blo,
                       float* C, int ldc, const float* bias, int remap)
{
    dim3 grid(N / 64, M / 128);
    hmma_big_kernel<<<grid, 256, BIG_SMEM>>>(Nreal, K, Ahi, Alo, Bhi, Blo,
                                             C, ldc, bias, remap);
}

static void launch_loop(int M, int N, int Nreal, int K,
                        const __nv_bfloat16* Ahi, const __nv_bfloat16* Alo,
                        const __nv_bfloat16* Bhi, const __nv_bfloat16* Blo,
                        float* C, int ldc, const float* bias, const float* Cinit)
{
    dim3 grid(N / 64, M / 128);
    hmma_kernel<<<grid, 256, HM_SMEM>>>(M, N, Nreal, K, Ahi, Alo, Bhi, Blo,
                                        C, ldc, bias, Cinit);
}

extern "C" void kernel_launch(void* const* d_in, const int* in_sizes, int n_in,
                              void* d_out, int out_size)
{
    const float* features  = (const float*)d_in[0];
    const int*   captions  = (const int*)  d_in[1];
    const float* embedding = (const float*)d_in[2];
    const float* W_enc     = (const float*)d_in[3];
    const float* b_enc     = (const float*)d_in[4];
    const float* W_dec     = (const float*)d_in[5];
    const float* b_dec     = (const float*)d_in[6];
    const float* w_att     = (const float*)d_in[7];
    // d_in[8] = b_att : softmax-invariant, unused
    const float* Wi_h      = (const float*)d_in[9];
    const float* bi_h      = (const float*)d_in[10];
    const float* Wi_c      = (const float*)d_in[11];
    const float* bi_c      = (const float*)d_in[12];
    const float* W_ih      = (const float*)d_in[13];
    const float* b_ih      = (const float*)d_in[14];
    const float* W_hh      = (const float*)d_in[15];
    const float* b_hh      = (const float*)d_in[16];
    const float* W_out     = (const float*)d_in[17];
    const float* b_out     = (const float*)d_in[18];
    float* out = (float*)d_out;

    cudaFuncSetAttribute(hmma_kernel,     cudaFuncAttributeMaxDynamicSharedMemorySize, HM_SMEM);
    cudaFuncSetAttribute(hmma_big_kernel, cudaFuncAttributeMaxDynamicSharedMemorySize, BIG_SMEM);

    float *featproj, *embgates, *bh, *bias2, *meanf, *h0, *c, *hproj;
    __nv_bfloat16 *fhi, *flo, *wenchi, *wenclo, *wihhi, *wihlo, *wihchi, *wihclo,
                  *whcthi, *whctlo, *wouthi, *woutlo, *eahi, *ealo,
                  *Hhi, *Hlo, *h0hi, *h0lo, *ctxhi, *ctxlo;
    cudaGetSymbolAddress((void**)&featproj, g_featproj);
    cudaGetSymbolAddress((void**)&embgates, g_embgates);
    cudaGetSymbolAddress((void**)&bh,       g_bh);
    cudaGetSymbolAddress((void**)&bias2,    g_bias2);
    cudaGetSymbolAddress((void**)&meanf,    g_meanf);
    cudaGetSymbolAddress((void**)&h0,       g_h0);
    cudaGetSymbolAddress((void**)&c,        g_c);
    cudaGetSymbolAddress((void**)&hproj,    g_hproj);
    cudaGetSymbolAddress((void**)&fhi,      g_feat_hi);
    cudaGetSymbolAddress((void**)&flo,      g_feat_lo);
    cudaGetSymbolAddress((void**)&wenchi,   g_WencT_hi);
    cudaGetSymbolAddress((void**)&wenclo,   g_WencT_lo);
    cudaGetSymbolAddress((void**)&wihhi,    g_WihT_hi);
    cudaGetSymbolAddress((void**)&wihlo,    g_WihT_lo);
    cudaGetSymbolAddress((void**)&wihchi,   g_WihcT_hi);
    cudaGetSymbolAddress((void**)&wihclo,   g_WihcT_lo);
    cudaGetSymbolAddress((void**)&whcthi,   g_whcatT_hi);
    cudaGetSymbolAddress((void**)&whctlo,   g_whcatT_lo);
    cudaGetSymbolAddress((void**)&wouthi,   g_WoutT_hi);
    cudaGetSymbolAddress((void**)&woutlo,   g_WoutT_lo);
    cudaGetSymbolAddress((void**)&eahi,     g_embA_hi);
    cudaGetSymbolAddress((void**)&ealo,     g_embA_lo);
    cudaGetSymbolAddress((void**)&Hhi,      g_H_hi);
    cudaGetSymbolAddress((void**)&Hlo,      g_H_lo);
    cudaGetSymbolAddress((void**)&h0hi,     g_h0_hi);
    cudaGetSymbolAddress((void**)&h0lo,     g_h0_lo);
    cudaGetSymbolAddress((void**)&ctxhi,    g_ctx_hi);
    cudaGetSymbolAddress((void**)&ctxlo,    g_ctx_lo);

    dim3 tthr(32, 8);

    // ---- prep, featproj big GEMM stays at launch #4 (ncu slot) ----
    {
        size_t n4 = (size_t)Bv * Nv * ENCv / 4;
        conv4_hilo_kernel<<<(unsigned)((n4 + 255) / 256), 256>>>(
            (const float4*)features, n4, (__nv_bfloat162*)fhi, (__nv_bfloat162*)flo);     // 1
    }
    trans_hilo_kernel<<<dim3(16, 16), tthr>>>(W_enc, ENCv, Av, wenchi, wenclo, ENCv, Av); // 2
    whcatT_hilo_kernel<<<(HW * Dv + 255) / 256, 256>>>(W_dec, W_hh, whcthi, whctlo);      // 3
    launch_big(Bv * Nv, Av, Av, ENCv, fhi, flo, wenchi, wenclo,
               featproj, Av, b_enc, 0);                                                   // 4
    biases_kernel<<<(HW + 255) / 256, 256>>>(b_dec, b_ih, b_hh, bh, bias2);               // 5
    embgather_hilo_kernel<<<(Tv * Bv * KE + 255) / 256, 256>>>(embedding, captions,
                                                               eahi, ealo);               // 6
    trans_hilo_kernel<<<dim3((G4D + 31) / 32, (KE + 31) / 32), tthr>>>(
        W_ih, Ev, G4D, wihhi, wihlo, KE, G4D);                                            // 7
    launch_big(Tv * Bv, G4D, G4D, KE, eahi, ealo, wihhi, wihlo,
               embgates, G4D, bias2, 0);                                                  // 8
    trans_hilo_kernel<<<dim3((G4D + 31) / 32, (Dv + 31) / 32), tthr>>>(
        W_ih + (size_t)Ev * G4D, Dv, G4D, wihchi, wihclo, Dv, G4D);                       // 9
    trans_hilo_kernel<<<dim3((VP + 31) / 32, (Dv + 31) / 32), tthr>>>(
        W_out, Dv, Vv, wouthi, woutlo, Dv, VP);                                           // 10
    meanf_kernel<<<Bv, 256>>>(features, meanf);                                           // 11
    {
        dim3 g(Dv / 64, Bv / 32);
        sgemm_kernel<32, 64, 16, 2, 4><<<g, 256>>>(Bv, Dv, ENCv, meanf, ENCv,
                                                   Wi_h, Dv, h0, Dv, bi_h);               // 12
        sgemm_kernel<32, 64, 16, 2, 4><<<g, 256>>>(Bv, Dv, ENCv, meanf, ENCv,
                                                   Wi_c, Dv, c, Dv, bi_c);                // 13
    }
    conv_hilo_kernel<<<(Bv * Dv + 255) / 256, 256>>>(h0, (size_t)Bv * Dv, h0hi, h0lo);    // 14

    const size_t PRED = (size_t)Bv * Tv * Vv;

    for (int t = 0; t < Tv; t++) {
        const __nv_bfloat16* hpHi = (t == 0) ? h0hi : (Hhi + (size_t)(t - 1) * Bv * Dv);
        const __nv_bfloat16* hpLo = (t == 0) ? h0lo : (Hlo + (size_t)(t - 1) * Bv * Dv);
        // hproj = h @ [W_dec | W_hh] + [b_dec | 0]
        launch_loop(Bv, HW, HW, Dv, hpHi, hpLo, whcthi, whctlo,
                    hproj, HW, bh, nullptr);
        // attention -> ctx hi/lo, alphas[:, t, :]
        attention_kernel<<<Bv, 256>>>(featproj, features, hproj, w_att,
                                      ctxhi, ctxlo, out + PRED + (size_t)t * Nv);
        // gates partial: ctx @ W_ih[E:,:] + embgates[t]  (in-place accumulate)
        launch_loop(Bv, G4D, G4D, Dv, ctxhi, ctxlo, wihchi, wihclo,
                    embgates + (size_t)t * Bv * G4D, G4D, nullptr,
                    embgates + (size_t)t * Bv * G4D);
        // LSTM pointwise -> Hhi/Hlo[t], c
        lstm_kernel<<<(Bv * Dv + 255) / 256, 256>>>(
            embgates + (size_t)t * Bv * G4D, hproj, c,
            Hhi + (size_t)t * Bv * Dv, Hlo + (size_t)t * Bv * Dv);
    }

    // preds: [T*B, V] = H @ W_out^T + b_out, remapped to [B, T, V]
    launch_big(Tv * Bv, VP, Vv, Dv, Hhi, Hlo, wouthi, woutlo,
               out, Vv, b_out, 1);
}

// round 13
// speedup vs baseline: 1.1972x; 1.0510x over previous
#include <cuda_runtime.h>
#include <cuda_bf16.h>
#include <cstdint>
#include <cstddef>

// ---------------- problem constants ----------------
#define Bv   128
#define Nv   196
#define Lv   25
#define Tv   24
#define Vv   10000
#define Ev   300
#define Av   512
#define ENCv 512
#define Dv   512
#define G4D  2048   // 4*D
#define HW   2560   // cols of [W_dec | W_hh_interleaved]
#define KE   320    // E padded (multiple of 32)
#define VP   10112  // V padded (multiple of 64)

// ---------------- device scratch (static, no allocation) ----------------
__device__ float g_featproj[(size_t)Bv * Nv * Av];
__device__ float g_embgates[(size_t)Tv * Bv * G4D];     // interleaved-gate layout
__device__ float g_bh[HW];
__device__ float g_bias2i[G4D];                         // interleaved
__device__ float g_meanf[Bv * ENCv];
__device__ float g_h0[Bv * Dv];
__device__ float g_c[Bv * Dv];
__device__ float g_hproj[Bv * HW];

__device__ __nv_bfloat16 g_feat_hi[(size_t)Bv * Nv * ENCv];
__device__ __nv_bfloat16 g_feat_lo[(size_t)Bv * Nv * ENCv];
__device__ __nv_bfloat16 g_WencT_hi[Av * ENCv];
__device__ __nv_bfloat16 g_WencT_lo[Av * ENCv];
__device__ __nv_bfloat16 g_WihTi_hi[G4D * KE];           // interleaved rows
__device__ __nv_bfloat16 g_WihTi_lo[G4D * KE];
__device__ __nv_bfloat16 g_WihcTi_hi[G4D * Dv];          // ctx rows of W_ih, interleaved
__device__ __nv_bfloat16 g_WihcTi_lo[G4D * Dv];
__device__ __nv_bfloat16 g_whcatT_hi[HW * Dv];           // [W_dec | W_hh interleaved]^T
__device__ __nv_bfloat16 g_whcatT_lo[HW * Dv];
__device__ __nv_bfloat16 g_WoutT_hi[(size_t)VP * Dv];
__device__ __nv_bfloat16 g_WoutT_lo[(size_t)VP * Dv];
__device__ __nv_bfloat16 g_embA_hi[Tv * Bv * KE];
__device__ __nv_bfloat16 g_embA_lo[Tv * Bv * KE];
__device__ __nv_bfloat16 g_H_hi[(size_t)Tv * Bv * Dv];
__device__ __nv_bfloat16 g_H_lo[(size_t)Tv * Bv * Dv];
__device__ __nv_bfloat16 g_h0_hi[Bv * Dv];
__device__ __nv_bfloat16 g_h0_lo[Bv * Dv];
__device__ __nv_bfloat16 g_ctx_hi[Bv * Dv];
__device__ __nv_bfloat16 g_ctx_lo[Bv * Dv];

// ---------------- PTX helpers ----------------
__device__ __forceinline__ uint32_t smem_u32(const void* p) {
    uint32_t a;
    asm("{ .reg .u64 t; cvta.to.shared.u64 t, %1; cvt.u32.u64 %0, t; }" : "=r"(a) : "l"(p));
    return a;
}

#define LDSM4(r, addr) \
    asm volatile("ldmatrix.sync.aligned.m8n8.x4.shared.b16 {%0,%1,%2,%3}, [%4];" \
        : "=r"((r)[0]), "=r"((r)[1]), "=r"((r)[2]), "=r"((r)[3]) : "r"(addr))

#define MMA16816(d, a, b0, b1) \
    asm volatile("mma.sync.aligned.m16n8k16.row.col.f32.bf16.bf16.f32 " \
        "{%0,%1,%2,%3}, {%4,%5,%6,%7}, {%8,%9}, {%0,%1,%2,%3};" \
        : "+f"((d)[0]), "+f"((d)[1]), "+f"((d)[2]), "+f"((d)[3]) \
        : "r"((a)[0]), "r"((a)[1]), "r"((a)[2]), "r"((a)[3]), "r"(b0), "r"(b1))

#define CP16(dst, src) \
    asm volatile("cp.async.cg.shared.global [%0], [%1], 16;" :: "r"(dst), "l"(src) : "memory")
#define CP_COMMIT() asm volatile("cp.async.commit_group;" ::: "memory")
#define CP_WAIT1() asm volatile("cp.async.wait_group 1;" ::: "memory")
#define CP_WAIT0() asm volatile("cp.async.wait_group 0;" ::: "memory")

// =================================================================
// Shared pipelined HMMA mainloop: CTA 128x64, 4M x 2N warps, BK=32,
// 2-stage cp.async, smem row stride 80 B. lda == ldb == K assumed.
// =================================================================
#define SS       30720
#define POFF_AHI 0
#define POFF_ALO 10240
#define POFF_BHI 20480
#define POFF_BLO 25600
#define BIG_SMEM (2 * SS)   // 61440

__device__ __forceinline__ void big_load_stage(
    uint32_t base,
    const __nv_bfloat16* __restrict__ Ahi, const __nv_bfloat16* __restrict__ Alo,
    const __nv_bfloat16* __restrict__ Bhi, const __nv_bfloat16* __restrict__ Blo,
    int lda, int row0, int col0, int koff, int tid)
{
#pragma unroll
    for (int i = 0; i < 2; i++) {
        const int idx = tid + i * 256;
        const int r = idx >> 2, seg = idx & 3;
        const uint32_t d = base + (uint32_t)(r * 80 + seg * 16);
        const size_t g = (size_t)(row0 + r) * lda + koff + seg * 8;
        CP16(d + POFF_AHI, Ahi + g);
        CP16(d + POFF_ALO, Alo + g);
    }
    {
        const int r = tid >> 2, seg = tid & 3;
        const uint32_t d = base + (uint32_t)(r * 80 + seg * 16);
        const size_t g = (size_t)(col0 + r) * lda + koff + seg * 8;
        CP16(d + POFF_BHI, Bhi + g);
        CP16(d + POFF_BLO, Blo + g);
    }
}

__device__ __forceinline__ void pipe_mainloop(
    uint32_t sb,
    const __nv_bfloat16* __restrict__ Ahi, const __nv_bfloat16* __restrict__ Alo,
    const __nv_bfloat16* __restrict__ Bhi, const __nv_bfloat16* __restrict__ Blo,
    int K, int row0, int col0, int tid, int warp_m, int warp_n, int lane,
    float acc[2][4][4])
{
    const int a_lr = lane & 15, a_lk = (lane >> 4) * 8;
    const int b_grp = lane >> 3;
    const int b_lr = (lane & 7) + ((b_grp >> 1) * 8);
    const int b_lk = (b_grp & 1) * 8;

    const int nch = K >> 5;
    big_load_stage(sb, Ahi, Alo, Bhi, Blo, K, row0, col0, 0, tid);
    CP_COMMIT();
    for (int kc = 0; kc < nch; kc++) {
        if (kc + 1 < nch) {
            big_load_stage(sb + (uint32_t)(((kc + 1) & 1) * SS),
                           Ahi, Alo, Bhi, Blo, K, row0, col0, (kc + 1) * 32, tid);
            CP_COMMIT();
            CP_WAIT1();
        } else {
            CP_WAIT0();
        }
        __syncthreads();
        const uint32_t st = sb + (uint32_t)((kc & 1) * SS);
#pragma unroll
        for (int k16 = 0; k16 < 32; k16 += 16) {
            uint32_t aHi[2][4], aLo[2][4], bH[8], bL[8];
#pragma unroll
            for (int mt = 0; mt < 2; mt++) {
                const uint32_t ab = st + (uint32_t)((warp_m * 32 + mt * 16 + a_lr) * 80
                                                    + (k16 + a_lk) * 2);
                LDSM4(aHi[mt], ab + POFF_AHI);
                LDSM4(aLo[mt], ab + POFF_ALO);
            }
#pragma unroll
            for (int half = 0; half < 2; half++) {
                const uint32_t bb = st + (uint32_t)((warp_n * 32 + half * 16 + b_lr) * 80
                                                    + (k16 + b_lk) * 2);
                LDSM4(bH + half * 4, bb + POFF_BHI);
                LDSM4(bL + half * 4, bb + POFF_BLO);
            }
#pragma unroll
            for (int mt = 0; mt < 2; mt++)
#pragma unroll
                for (int nt = 0; nt < 4; nt++) {
                    MMA16816(acc[mt][nt], aHi[mt], bH[nt * 2], bH[nt * 2 + 1]);
                    MMA16816(acc[mt][nt], aLo[mt], bH[nt * 2], bH[nt * 2 + 1]);
                    MMA16816(acc[mt][nt], aHi[mt], bL[nt * 2], bL[nt * 2 + 1]);
                }
        }
        __syncthreads();
    }
}

// =================================================================
// BIG HMMA GEMM (featproj / embgates / logits)
// =================================================================
__global__ __launch_bounds__(256, 2)
void hmma_big_kernel(int Nreal, int K,
                     const __nv_bfloat16* __restrict__ Ahi, const __nv_bfloat16* __restrict__ Alo,
                     const __nv_bfloat16* __restrict__ Bhi, const __nv_bfloat16* __restrict__ Blo,
                     float* __restrict__ C, int ldc,
                     const float* __restrict__ bias, int remap)
{
    extern __shared__ char sm[];
    const uint32_t sb = smem_u32(sm);
    const int tid = threadIdx.x;
    const int wid = tid >> 5, lane = tid & 31;
    const int warp_m = wid & 3;
    const int warp_n = wid >> 2;
    const int row0 = blockIdx.y * 128;
    const int col0 = blockIdx.x * 64;

    float acc[2][4][4];
#pragma unroll
    for (int mt = 0; mt < 2; mt++)
#pragma unroll
        for (int nt = 0; nt < 4; nt++)
#pragma unroll
            for (int r = 0; r < 4; r++) acc[mt][nt][r] = 0.f;

    pipe_mainloop(sb, Ahi, Alo, Bhi, Blo, K, row0, col0, tid, warp_m, warp_n, lane, acc);

    const int quad = lane >> 2, tc = lane & 3;
#pragma unroll
    for (int mt = 0; mt < 2; mt++)
#pragma unroll
        for (int half = 0; half < 2; half++) {
            const int gm = row0 + warp_m * 32 + mt * 16 + quad + half * 8;
            const size_t rowC = remap ? ((size_t)(gm & (Bv - 1)) * Tv + (gm >> 7))
                                      : (size_t)gm;
#pragma unroll
            for (int nt = 0; nt < 4; nt++) {
                const int gn = col0 + warp_n * 32 + nt * 8 + tc * 2;
                if (gn >= Nreal) continue;
                const float2 bv = *(const float2*)&bias[gn];
                float2 o;
                o.x = acc[mt][nt][half * 2]     + bv.x;
                o.y = acc[mt][nt][half * 2 + 1] + bv.y;
                *(float2*)&C[rowC * (size_t)ldc + gn] = o;
            }
        }
}

// =================================================================
// hproj GEMM (pipelined): hproj = h @ [W_dec | W_hh_int] + bh. M=128.
// =================================================================
__global__ __launch_bounds__(256, 2)
void hproj_kernel(const __nv_bfloat16* __restrict__ Ahi, const __nv_bfloat16* __restrict__ Alo,
                  const __nv_bfloat16* __restrict__ Bhi, const __nv_bfloat16* __restrict__ Blo,
                  float* __restrict__ C, const float* __restrict__ bias)
{
    extern __shared__ char sm[];
    const uint32_t sb = smem_u32(sm);
    const int tid = threadIdx.x;
    const int wid = tid >> 5, lane = tid & 31;
    const int warp_m = wid & 3;
    const int warp_n = wid >> 2;
    const int col0 = blockIdx.x * 64;

    float acc[2][4][4];
#pragma unroll
    for (int mt = 0; mt < 2; mt++)
#pragma unroll
        for (int nt = 0; nt < 4; nt++)
#pragma unroll
            for (int r = 0; r < 4; r++) acc[mt][nt][r] = 0.f;

    pipe_mainloop(sb, Ahi, Alo, Bhi, Blo, Dv, 0, col0, tid, warp_m, warp_n, lane, acc);

    const int quad = lane >> 2, tc = lane & 3;
#pragma unroll
    for (int mt = 0; mt < 2; mt++)
#pragma unroll
        for (int half = 0; half < 2; half++) {
            const int gm = warp_m * 32 + mt * 16 + quad + half * 8;
#pragma unroll
            for (int nt = 0; nt < 4; nt++) {
                const int gn = col0 + warp_n * 32 + nt * 8 + tc * 2;
                const float2 bv = *(const float2*)&bias[gn];
                float2 o;
                o.x = acc[mt][nt][half * 2]     + bv.x;
                o.y = acc[mt][nt][half * 2 + 1] + bv.y;
                *(float2*)&C[(size_t)gm * HW + gn] = o;
            }
        }
}

// =================================================================
// Gates GEMM + fused LSTM epilogue (pipelined mainloop).
// gates_int = ctx @ WihcTi^T + embgates_int[t] + hproj[:, 512:].
// Interleaved: col 4d+g = gate g of unit d. grid = 32 CTAs.
// =================================================================
__global__ __launch_bounds__(256, 2)
void gates_lstm_kernel(const __nv_bfloat16* __restrict__ ctxHi, const __nv_bfloat16* __restrict__ ctxLo,
                       const __nv_bfloat16* __restrict__ wHi, const __nv_bfloat16* __restrict__ wLo,
                       const float* __restrict__ egt,      // embgates + t*Bv*G4D
                       const float* __restrict__ hproj,    // [B, HW]
                       float* __restrict__ c,
                       __nv_bfloat16* __restrict__ HtHi, __nv_bfloat16* __restrict__ HtLo)
{
    extern __shared__ char sm[];
    const uint32_t sb = smem_u32(sm);
    const int tid = threadIdx.x;
    const int wid = tid >> 5, lane = tid & 31;
    const int warp_m = wid & 3;
    const int warp_n = wid >> 2;
    const int col0 = blockIdx.x * 64;

    float acc[2][4][4];
#pragma unroll
    for (int mt = 0; mt < 2; mt++)
#pragma unroll
        for (int nt = 0; nt < 4; nt++)
#pragma unroll
            for (int r = 0; r < 4; r++) acc[mt][nt][r] = 0.f;

    pipe_mainloop(sb, ctxHi, ctxLo, wHi, wLo, Dv, 0, col0, tid, warp_m, warp_n, lane, acc);

    // stage gates into smem f32 [128][68]
    float* gs = (float*)sm;
    const int quad = lane >> 2, tc = lane & 3;
#pragma unroll
    for (int mt = 0; mt < 2; mt++)
#pragma unroll
        for (int half = 0; half < 2; half++) {
            const int gm = warp_m * 32 + mt * 16 + quad + half * 8;
#pragma unroll
            for (int nt = 0; nt < 4; nt++) {
                const int gn = warp_n * 32 + nt * 8 + tc * 2;
                const float2 e = *(const float2*)&egt[(size_t)gm * G4D + col0 + gn];
                const float2 hp = *(const float2*)&hproj[(size_t)gm * HW + 512 + col0 + gn];
                gs[gm * 68 + gn]     = acc[mt][nt][half * 2]     + e.x + hp.x;
                gs[gm * 68 + gn + 1] = acc[mt][nt][half * 2 + 1] + e.y + hp.y;
            }
        }
    __syncthreads();

    const int d0 = col0 >> 2;
#pragma unroll
    for (int i = tid; i < 2048; i += 256) {
        const int b = i >> 4, u = i & 15;
        const float* gr = gs + b * 68 + u * 4;
        const float gi = gr[0], gf = gr[1], gg = gr[2], go = gr[3];
        const int d = d0 + u;
        const float si = 1.f / (1.f + __expf(-gi));
        const float sf = 1.f / (1.f + __expf(-gf));
        const float so = 1.f / (1.f + __expf(-go));
        const float tg = tanhf(gg);
        const float cn = sf * c[b * Dv + d] + si * tg;
        c[b * Dv + d] = cn;
        const float h = so * tanhf(cn);
        const __nv_bfloat16 hh = __float2bfloat16(h);
        HtHi[b * Dv + d] = hh;
        HtLo[b * Dv + d] = __float2bfloat16(h - __bfloat162float(hh));
    }
}

// =================================================================
// Small fp32 SGEMM (one-time h0/c0 init only)
// =================================================================
template<int BM, int BN, int BK, int TM, int TN>
__global__ void sgemm_kernel(int M, int N, int K,
                             const float* __restrict__ A, int lda,
                             const float* __restrict__ B, int ldb,
                             float* __restrict__ C, int ldc,
                             const float* __restrict__ bias)
{
    constexpr int TX = BN / TN;
    constexpr int TY = BM / TM;
    constexpr int NT = TX * TY;
    __shared__ float As[BK][BM + 1];
    __shared__ float Bs[BK][BN];

    const int tid = threadIdx.x;
    const int tx = tid % TX, ty = tid / TX;
    const int row0 = blockIdx.y * BM;
    const int col0 = blockIdx.x * BN;

    float acc[TM][TN];
#pragma unroll
    for (int i = 0; i < TM; i++)
#pragma unroll
        for (int j = 0; j < TN; j++) acc[i][j] = 0.f;

    for (int k0 = 0; k0 < K; k0 += BK) {
#pragma unroll
        for (int i = tid; i < BM * BK; i += NT) {
            int m = i / BK, k = i % BK;
            As[k][m] = A[(size_t)(row0 + m) * lda + k0 + k];
        }
#pragma unroll
        for (int i = tid; i < BK * BN; i += NT) {
            int k = i / BN, n = i % BN;
            Bs[k][n] = B[(size_t)(k0 + k) * ldb + col0 + n];
        }
        __syncthreads();
#pragma unroll
        for (int kk = 0; kk < BK; kk++) {
            float ra[TM], rb[TN];
#pragma unroll
            for (int i = 0; i < TM; i++) ra[i] = As[kk][ty * TM + i];
#pragma unroll
            for (int j = 0; j < TN; j++) rb[j] = Bs[kk][tx * TN + j];
#pragma unroll
            for (int i = 0; i < TM; i++)
#pragma unroll
                for (int j = 0; j < TN; j++)
                    acc[i][j] = fmaf(ra[i], rb[j], acc[i][j]);
        }
        __syncthreads();
    }

#pragma unroll
    for (int i = 0; i < TM; i++)
#pragma unroll
        for (int j = 0; j < TN; j++) {
            int gm = row0 + ty * TM + i, gn = col0 + tx * TN + j;
            C[(size_t)gm * ldc + gn] = acc[i][j] + bias[gn];
        }
}

// ---------------- prep kernels ----------------
__device__ __forceinline__ void split_hilo(float v, __nv_bfloat16& h, __nv_bfloat16& l) {
    h = __float2bfloat16(v);
    l = __float2bfloat16(v - __bfloat162float(h));
}

// [W_dec | W_hh interleaved]^T: n<512 -> Wdec[k][n]; n>=512: m=n-512,
// col_old=(m&3)*512+(m>>2) -> Whh[k][col_old]
__global__ void whcatT_hilo_kernel(const float* __restrict__ Wdec, const float* __restrict__ Whh,
                                   __nv_bfloat16* __restrict__ hi, __nv_bfloat16* __restrict__ lo)
{
    int idx = blockIdx.x * blockDim.x + threadIdx.x;
    if (idx >= HW * Dv) return;
    int k = idx & 511, n = idx >> 9;
    float v;
    if (n < 512) {
        v = Wdec[(size_t)k * Av + n];
    } else {
        int m = n - 512;
        int col_old = (m & 3) * 512 + (m >> 2);
        v = Whh[(size_t)k * G4D + col_old];
    }
    split_hilo(v, hi[idx], lo[idx]);
}

// W_ih ctx-part transposed, interleaved rows: n in [0,2048), k in [0,512)
__global__ void wihcTi_kernel(const float* __restrict__ Wih,
                              __nv_bfloat16* __restrict__ hi, __nv_bfloat16* __restrict__ lo)
{
    int idx = blockIdx.x * blockDim.x + threadIdx.x;
    if (idx >= G4D * Dv) return;
    int k = idx & 511, n = idx >> 9;
    int col_old = (n & 3) * 512 + (n >> 2);
    float v = Wih[(size_t)(Ev + k) * G4D + col_old];
    split_hilo(v, hi[idx], lo[idx]);
}

// W_ih emb-part transposed, interleaved rows, K padded to KE
__global__ void wihTi_kernel(const float* __restrict__ Wih,
                             __nv_bfloat16* __restrict__ hi, __nv_bfloat16* __restrict__ lo)
{
    int idx = blockIdx.x * blockDim.x + threadIdx.x;
    if (idx >= G4D * KE) return;
    int k = idx % KE, n = idx / KE;
    int col_old = (n & 3) * 512 + (n >> 2);
    float v = (k < Ev) ? Wih[(size_t)k * G4D + col_old] : 0.f;
    split_hilo(v, hi[idx], lo[idx]);
}

__global__ void biases_kernel(const float* __restrict__ bdec,
                              const float* __restrict__ bih, const float* __restrict__ bhh,
                              float* __restrict__ bh, float* __restrict__ b2i)
{
    int j = blockIdx.x * blockDim.x + threadIdx.x;
    if (j < HW) bh[j] = (j < 512) ? bdec[j] : 0.f;
    if (j < G4D) {
        int col_old = (j & 3) * 512 + (j >> 2);
        b2i[j] = bih[col_old] + bhh[col_old];
    }
}

__global__ void embgather_hilo_kernel(const float* __restrict__ emb, const int* __restrict__ cap,
                                      __nv_bfloat16* __restrict__ hi, __nv_bfloat16* __restrict__ lo)
{
    int idx = blockIdx.x * blockDim.x + threadIdx.x;
    if (idx >= Tv * Bv * KE) return;
    int k = idx % KE, r = idx / KE;
    int t = r / Bv, b = r % Bv;
    float v = 0.f;
    if (k < Ev) v = emb[(size_t)cap[b * Lv + t] * Ev + k];
    split_hilo(v, hi[idx], lo[idx]);
}

__global__ void conv_hilo_kernel(const float* __restrict__ in, size_t n,
                                 __nv_bfloat16* __restrict__ hi, __nv_bfloat16* __restrict__ lo)
{
    size_t idx = (size_t)blockIdx.x * blockDim.x + threadIdx.x;
    if (idx >= n) return;
    split_hilo(in[idx], hi[idx], lo[idx]);
}

__global__ void conv4_hilo_kernel(const float4* __restrict__ in, size_t n4,
                                  __nv_bfloat162* __restrict__ hi, __nv_bfloat162* __restrict__ lo)
{
    size_t idx = (size_t)blockIdx.x * blockDim.x + threadIdx.x;
    if (idx >= n4) return;
    float4 v = in[idx];
    __nv_bfloat16 h0, l0, h1, l1, h2, l2, h3, l3;
    split_hilo(v.x, h0, l0); split_hilo(v.y, h1, l1);
    split_hilo(v.z, h2, l2); split_hilo(v.w, h3, l3);
    hi[idx * 2]     = __nv_bfloat162(h0, h1);
    hi[idx * 2 + 1] = __nv_bfloat162(h2, h3);
    lo[idx * 2]     = __nv_bfloat162(l0, l1);
    lo[idx * 2 + 1] = __nv_bfloat162(l2, l3);
}

__global__ void trans_hilo_kernel(const float* __restrict__ in, int R, int C,
                                  __nv_bfloat16* __restrict__ hi, __nv_bfloat16* __restrict__ lo,
                                  int Kpad, int Npad)
{
    __shared__ float t[32][33];
    const int cb = blockIdx.x * 32;
    const int rb = blockIdx.y * 32;
    const int x = threadIdx.x, y = threadIdx.y;
#pragma unroll
    for (int i = y; i < 32; i += 8) {
        int r = rb + i, ccol = cb + x;
        t[i][x] = (r < R && ccol < C) ? in[(size_t)r * C + ccol] : 0.f;
    }
    __syncthreads();
#pragma unroll
    for (int i = y; i < 32; i += 8) {
        int n = cb + i, k = rb + x;
        if (n < Npad && k < Kpad) {
            size_t o = (size_t)n * Kpad + k;
            split_hilo(t[x][i], hi[o], lo[o]);
        }
    }
}

__global__ void meanf_kernel(const float* __restrict__ feat, float* __restrict__ mf)
{
    int b = blockIdx.x, tid = threadIdx.x;
    for (int d = tid; d < ENCv; d += 256) {
        float s = 0.f;
        const float* p = feat + (size_t)b * Nv * ENCv + d;
#pragma unroll 4
        for (int n = 0; n < Nv; n++) s += p[(size_t)n * ENCv];
        mf[b * ENCv + d] = s * (1.0f / (float)Nv);
    }
}

// ---------------- fused attention (f16x2 dual-tanh scores) ----------------
__global__ void attention_kernel(const float* __restrict__ fp,
                                 const float* __restrict__ feat,
                                 const float* __restrict__ dec,   // hproj[:, :512], ld=HW
                                 const float* __restrict__ watt,
                                 __nv_bfloat16* __restrict__ ctxHi,
                                 __nv_bfloat16* __restrict__ ctxLo,
                                 float* __restrict__ alphaOut)
{
    __shared__ float s_dec[Av];
    __shared__ float s_watt[Av];
    __shared__ float s_sc[Nv];
    __shared__ float s_red[8];
    const int b = blockIdx.x, tid = threadIdx.x;

    for (int i = tid; i < Av; i += 256) { s_dec[i] = dec[(size_t)b * HW + i]; s_watt[i] = watt[i]; }
    __syncthreads();

    const int warp = tid >> 5, lane = tid & 31;
    const float* fpb = fp + (size_t)b * Nv * Av;
    for (int n = warp; n < Nv; n += 8) {
        const float2* row2 = (const float2*)(fpb + (size_t)n * Av);
        float s = 0.f;
#pragma unroll 4
        for (int k2 = lane; k2 < 256; k2 += 32) {
            const float2 f = row2[k2];
            const float2 d2 = ((const float2*)s_dec)[k2];
            const float x0 = f.x + d2.x;
            const float x1 = f.y + d2.y;
            uint32_t xh, th;
            asm("cvt.rn.f16x2.f32 %0, %1, %2;" : "=r"(xh) : "f"(x1), "f"(x0));
            asm("tanh.approx.f16x2 %0, %1;" : "=r"(th) : "r"(xh));
            float t0, t1;
            asm("{\n\t.reg .f16 a, b;\n\tmov.b32 {a, b}, %2;\n\t"
                "cvt.f32.f16 %0, a;\n\tcvt.f32.f16 %1, b;\n\t}"
                : "=f"(t0), "=f"(t1) : "r"(th));
            const float2 w = ((const float2*)s_watt)[k2];
            s = fmaf(t0, w.x, s);
            s = fmaf(t1, w.y, s);
        }
#pragma unroll
        for (int o = 16; o; o >>= 1) s += __shfl_xor_sync(0xffffffffu, s, o);
        if (lane == 0) s_sc[n] = s;
    }
    __syncthreads();

    float m = -1e30f;
    for (int n = tid; n < Nv; n += 256) m = fmaxf(m, s_sc[n]);
#pragma unroll
    for (int o = 16; o; o >>= 1) m = fmaxf(m, __shfl_xor_sync(0xffffffffu, m, o));
    if (lane == 0) s_red[warp] = m;
    __syncthreads();
    if (tid == 0) {
        float mm = s_red[0];
        for (int w = 1; w < 8; w++) mm = fmaxf(mm, s_red[w]);
        s_red[0] = mm;
    }
    __syncthreads();
    m = s_red[0];
    __syncthreads();

    float sum = 0.f;
    for (int n = tid; n < Nv; n += 256) {
        float e = __expf(s_sc[n] - m);
        s_sc[n] = e;
        sum += e;
    }
#pragma unroll
    for (int o = 16; o; o >>= 1) sum += __shfl_xor_sync(0xffffffffu, sum, o);
    if (lane == 0) s_red[warp] = sum;
    __syncthreads();
    if (tid == 0) {
        float ss = 0.f;
        for (int w = 0; w < 8; w++) ss += s_red[w];
        s_red[0] = 1.f / ss;
    }
    __syncthreads();
    const float inv = s_red[0];
    for (int n = tid; n < Nv; n += 256) {
        float a = s_sc[n] * inv;
        s_sc[n] = a;
        alphaOut[(size_t)b * Tv * Nv + n] = a;
    }
    __syncthreads();

    const float* fb = feat + (size_t)b * Nv * ENCv;
    for (int d = tid; d < ENCv; d += 256) {
        float acc = 0.f;
#pragma unroll 4
        for (int n = 0; n < Nv; n++) acc = fmaf(s_sc[n], fb[(size_t)n * ENCv + d], acc);
        split_hilo(acc, ctxHi[b * ENCv + d], ctxLo[b * ENCv + d]);
    }
}

// ---------------- host helpers ----------------
static void launch_big(int M, int N, int Nreal, int K,
                       const __nv_bfloat16* Ahi, const __nv_bfloat16* Alo,
                       const __nv_bfloat16* Bhi, const __nv_bfloat16* Blo,
                       float* C, int ldc, const float* bias, int remap)
{
    dim3 grid(N / 64, M / 128);
    hmma_big_kernel<<<grid, 256, BIG_SMEM>>>(Nreal, K, Ahi, Alo, Bhi, Blo,
                                             C, ldc, bias, remap);
}

extern "C" void kernel_launch(void* const* d_in, const int* in_sizes, int n_in,
                              void* d_out, int out_size)
{
    const float* features  = (const float*)d_in[0];
    const int*   captions  = (const int*)  d_in[1];
    const float* embedding = (const float*)d_in[2];
    const float* W_enc     = (const float*)d_in[3];
    const float* b_enc     = (const float*)d_in[4];
    const float* W_dec     = (const float*)d_in[5];
    const float* b_dec     = (const float*)d_in[6];
    const float* w_att     = (const float*)d_in[7];
    // d_in[8] = b_att : softmax-invariant, unused
    const float* Wi_h      = (const float*)d_in[9];
    const float* bi_h      = (const float*)d_in[10];
    const float* Wi_c      = (const float*)d_in[11];
    const float* bi_c      = (const float*)d_in[12];
    const float* W_ih      = (const float*)d_in[13];
    const float* b_ih      = (const float*)d_in[14];
    const float* W_hh      = (const float*)d_in[15];
    const float* b_hh      = (const float*)d_in[16];
    const float* W_out     = (const float*)d_in[17];
    const float* b_out     = (const float*)d_in[18];
    float* out = (float*)d_out;

    cudaFuncSetAttribute(hmma_big_kernel, cudaFuncAttributeMaxDynamicSharedMemorySize, BIG_SMEM);
    cudaFuncSetAttribute(hproj_kernel,    cudaFuncAttributeMaxDynamicSharedMemorySize, BIG_SMEM);
    cudaFuncSetAttribute(gates_lstm_kernel, cudaFuncAttributeMaxDynamicSharedMemorySize, BIG_SMEM);

    float *featproj, *embgates, *bh, *bias2i, *meanf, *h0, *c, *hproj;
    __nv_bfloat16 *fhi, *flo, *wenchi, *wenclo, *wihhi, *wihlo, *wihchi, *wihclo,
                  *whcthi, *whctlo, *wouthi, *woutlo, *eahi, *ealo,
                  *Hhi, *Hlo, *h0hi, *h0lo, *ctxhi, *ctxlo;
    cudaGetSymbolAddress((void**)&featproj, g_featproj);
    cudaGetSymbolAddress((void**)&embgates, g_embgates);
    cudaGetSymbolAddress((void**)&bh,       g_bh);
    cudaGetSymbolAddress((void**)&bias2i,   g_bias2i);
    cudaGetSymbolAddress((void**)&meanf,    g_meanf);
    cudaGetSymbolAddress((void**)&h0,       g_h0);
    cudaGetSymbolAddress((void**)&c,        g_c);
    cudaGetSymbolAddress((void**)&hproj,    g_hproj);
    cudaGetSymbolAddress((void**)&fhi,      g_feat_hi);
    cudaGetSymbolAddress((void**)&flo,      g_feat_lo);
    cudaGetSymbolAddress((void**)&wenchi,   g_WencT_hi);
    cudaGetSymbolAddress((void**)&wenclo,   g_WencT_lo);
    cudaGetSymbolAddress((void**)&wihhi,    g_WihTi_hi);
    cudaGetSymbolAddress((void**)&wihlo,    g_WihTi_lo);
    cudaGetSymbolAddress((void**)&wihchi,   g_WihcTi_hi);
    cudaGetSymbolAddress((void**)&wihclo,   g_WihcTi_lo);
    cudaGetSymbolAddress((void**)&whcthi,   g_whcatT_hi);
    cudaGetSymbolAddress((void**)&whctlo,   g_whcatT_lo);
    cudaGetSymbolAddress((void**)&wouthi,   g_WoutT_hi);
    cudaGetSymbolAddress((void**)&woutlo,   g_WoutT_lo);
    cudaGetSymbolAddress((void**)&eahi,     g_embA_hi);
    cudaGetSymbolAddress((void**)&ealo,     g_embA_lo);
    cudaGetSymbolAddress((void**)&Hhi,      g_H_hi);
    cudaGetSymbolAddress((void**)&Hlo,      g_H_lo);
    cudaGetSymbolAddress((void**)&h0hi,     g_h0_hi);
    cudaGetSymbolAddress((void**)&h0lo,     g_h0_lo);
    cudaGetSymbolAddress((void**)&ctxhi,    g_ctx_hi);
    cudaGetSymbolAddress((void**)&ctxlo,    g_ctx_lo);

    dim3 tthr(32, 8);

    // ---- prep, featproj big GEMM stays at launch #4 (ncu slot) ----
    {
        size_t n4 = (size_t)Bv * Nv * ENCv / 4;
        conv4_hilo_kernel<<<(unsigned)((n4 + 255) / 256), 256>>>(
            (const float4*)features, n4, (__nv_bfloat162*)fhi, (__nv_bfloat162*)flo);     // 1
    }
    trans_hilo_kernel<<<dim3(16, 16), tthr>>>(W_enc, ENCv, Av, wenchi, wenclo, ENCv, Av); // 2
    whcatT_hilo_kernel<<<(HW * Dv + 255) / 256, 256>>>(W_dec, W_hh, whcthi, whctlo);      // 3
    launch_big(Bv * Nv, Av, Av, ENCv, fhi, flo, wenchi, wenclo,
               featproj, Av, b_enc, 0);                                                   // 4
    biases_kernel<<<(HW + 255) / 256, 256>>>(b_dec, b_ih, b_hh, bh, bias2i);              // 5
    embgather_hilo_kernel<<<(Tv * Bv * KE + 255) / 256, 256>>>(embedding, captions,
                                                               eahi, ealo);               // 6
    wihTi_kernel<<<(G4D * KE + 255) / 256, 256>>>(W_ih, wihhi, wihlo);                    // 7
    launch_big(Tv * Bv, G4D, G4D, KE, eahi, ealo, wihhi, wihlo,
               embgates, G4D, bias2i, 0);                                                 // 8
    wihcTi_kernel<<<(G4D * Dv + 255) / 256, 256>>>(W_ih, wihchi, wihclo);                 // 9
    trans_hilo_kernel<<<dim3((VP + 31) / 32, (Dv + 31) / 32), tthr>>>(
        W_out, Dv, Vv, wouthi, woutlo, Dv, VP);                                           // 10
    meanf_kernel<<<Bv, 256>>>(features, meanf);                                           // 11
    {
        dim3 g(Dv / 64, Bv / 32);
        sgemm_kernel<32, 64, 16, 2, 4><<<g, 256>>>(Bv, Dv, ENCv, meanf, ENCv,
                                                   Wi_h, Dv, h0, Dv, bi_h);               // 12
        sgemm_kernel<32, 64, 16, 2, 4><<<g, 256>>>(Bv, Dv, ENCv, meanf, ENCv,
                                                   Wi_c, Dv, c, Dv, bi_c);                // 13
    }
    conv_hilo_kernel<<<(Bv * Dv + 255) / 256, 256>>>(h0, (size_t)Bv * Dv, h0hi, h0lo);    // 14

    const size_t PRED = (size_t)Bv * Tv * Vv;

    for (int t = 0; t < Tv; t++) {
        const __nv_bfloat16* hpHi = (t == 0) ? h0hi : (Hhi + (size_t)(t - 1) * Bv * Dv);
        const __nv_bfloat16* hpLo = (t == 0) ? h0lo : (Hlo + (size_t)(t - 1) * Bv * Dv);
        // hproj = h @ [W_dec | W_hh_int] + [b_dec | 0]
        hproj_kernel<<<HW / 64, 256, BIG_SMEM>>>(hpHi, hpLo, whcthi, whctlo, hproj, bh);
        // attention -> ctx hi/lo, alphas[:, t, :]
        attention_kernel<<<Bv, 256>>>(featproj, features, hproj, w_att,
                                      ctxhi, ctxlo, out + PRED + (size_t)t * Nv);
        // gates + fused LSTM -> c, Hhi/Hlo[t]
        gates_lstm_kernel<<<G4D / 64, 256, BIG_SMEM>>>(
            ctxhi, ctxlo, wihchi, wihclo,
            embgates + (size_t)t * Bv * G4D, hproj, c,
            Hhi + (size_t)t * Bv * Dv, Hlo + (size_t)t * Bv * Dv);
    }

    // preds: [T*B, V] = H @ W_out^T + b_out, remapped to [B, T, V]
    launch_big(Tv * Bv, VP, Vv, Dv, Hhi, Hlo, wouthi, woutlo,
               out, Vv, b_out, 1);
}

// round 14
// speedup vs baseline: 1.3460x; 1.1243x over previous
#include <cuda_runtime.h>
#include <cuda_bf16.h>
#include <cuda_fp16.h>
#include <cstdint>
#include <cstddef>

// ---------------- problem constants ----------------
#define Bv   128
#define Nv   196
#define Lv   25
#define Tv   24
#define Vv   10000
#define Ev   300
#define Av   512
#define ENCv 512
#define Dv   512
#define G4D  2048   // 4*D
#define HW   2560   // cols of [W_dec | W_hh_interleaved]
#define KE   320    // E padded (multiple of 32)
#define VP   10112  // V padded (multiple of 64)

// ---------------- device scratch (static, no allocation) ----------------
__device__ __half g_featproj_h[(size_t)Bv * Nv * Av];   // f16 featproj (score-only consumer)
__device__ float g_embgates[(size_t)Tv * Bv * G4D];     // interleaved-gate layout
__device__ float g_bh[HW];
__device__ float g_bias2i[G4D];                         // interleaved
__device__ float g_meanf[Bv * ENCv];
__device__ float g_h0[Bv * Dv];
__device__ float g_c[Bv * Dv];
__device__ float g_hproj[Bv * HW];

__device__ __nv_bfloat16 g_feat_hi[(size_t)Bv * Nv * ENCv];
__device__ __nv_bfloat16 g_feat_lo[(size_t)Bv * Nv * ENCv];
__device__ __nv_bfloat16 g_WencT_hi[Av * ENCv];
__device__ __nv_bfloat16 g_WencT_lo[Av * ENCv];
__device__ __nv_bfloat16 g_WihTi_hi[G4D * KE];           // interleaved rows
__device__ __nv_bfloat16 g_WihTi_lo[G4D * KE];
__device__ __nv_bfloat16 g_WihcTi_hi[G4D * Dv];          // ctx rows of W_ih, interleaved
__device__ __nv_bfloat16 g_WihcTi_lo[G4D * Dv];
__device__ __nv_bfloat16 g_whcatT_hi[HW * Dv];           // [W_dec | W_hh interleaved]^T
__device__ __nv_bfloat16 g_whcatT_lo[HW * Dv];
__device__ __nv_bfloat16 g_WoutT_hi[(size_t)VP * Dv];
__device__ __nv_bfloat16 g_WoutT_lo[(size_t)VP * Dv];
__device__ __nv_bfloat16 g_embA_hi[Tv * Bv * KE];
__device__ __nv_bfloat16 g_embA_lo[Tv * Bv * KE];
__device__ __nv_bfloat16 g_H_hi[(size_t)Tv * Bv * Dv];
__device__ __nv_bfloat16 g_H_lo[(size_t)Tv * Bv * Dv];
__device__ __nv_bfloat16 g_h0_hi[Bv * Dv];
__device__ __nv_bfloat16 g_h0_lo[Bv * Dv];
__device__ __nv_bfloat16 g_ctx_hi[Bv * Dv];
__device__ __nv_bfloat16 g_ctx_lo[Bv * Dv];

// ---------------- PTX helpers ----------------
__device__ __forceinline__ uint32_t smem_u32(const void* p) {
    uint32_t a;
    asm("{ .reg .u64 t; cvta.to.shared.u64 t, %1; cvt.u32.u64 %0, t; }" : "=r"(a) : "l"(p));
    return a;
}

#define LDSM4(r, addr) \
    asm volatile("ldmatrix.sync.aligned.m8n8.x4.shared.b16 {%0,%1,%2,%3}, [%4];" \
        : "=r"((r)[0]), "=r"((r)[1]), "=r"((r)[2]), "=r"((r)[3]) : "r"(addr))

#define MMA16816(d, a, b0, b1) \
    asm volatile("mma.sync.aligned.m16n8k16.row.col.f32.bf16.bf16.f32 " \
        "{%0,%1,%2,%3}, {%4,%5,%6,%7}, {%8,%9}, {%0,%1,%2,%3};" \
        : "+f"((d)[0]), "+f"((d)[1]), "+f"((d)[2]), "+f"((d)[3]) \
        : "r"((a)[0]), "r"((a)[1]), "r"((a)[2]), "r"((a)[3]), "r"(b0), "r"(b1))

#define CP16(dst, src) \
    asm volatile("cp.async.cg.shared.global [%0], [%1], 16;" :: "r"(dst), "l"(src) : "memory")
#define CP_COMMIT() asm volatile("cp.async.commit_group;" ::: "memory")
#define CP_WAIT1() asm volatile("cp.async.wait_group 1;" ::: "memory")
#define CP_WAIT0() asm volatile("cp.async.wait_group 0;" ::: "memory")

// =================================================================
// Shared pipelined HMMA mainloop: CTA 128x64, 4M x 2N warps, BK=32,
// 2-stage cp.async, smem row stride 80 B. lda == ldb == K assumed.
// =================================================================
#define SS       30720
#define POFF_AHI 0
#define POFF_ALO 10240
#define POFF_BHI 20480
#define POFF_BLO 25600
#define BIG_SMEM (2 * SS)   // 61440

__device__ __forceinline__ void big_load_stage(
    uint32_t base,
    const __nv_bfloat16* __restrict__ Ahi, const __nv_bfloat16* __restrict__ Alo,
    const __nv_bfloat16* __restrict__ Bhi, const __nv_bfloat16* __restrict__ Blo,
    int lda, int row0, int col0, int koff, int tid)
{
#pragma unroll
    for (int i = 0; i < 2; i++) {
        const int idx = tid + i * 256;
        const int r = idx >> 2, seg = idx & 3;
        const uint32_t d = base + (uint32_t)(r * 80 + seg * 16);
        const size_t g = (size_t)(row0 + r) * lda + koff + seg * 8;
        CP16(d + POFF_AHI, Ahi + g);
        CP16(d + POFF_ALO, Alo + g);
    }
    {
        const int r = tid >> 2, seg = tid & 3;
        const uint32_t d = base + (uint32_t)(r * 80 + seg * 16);
        const size_t g = (size_t)(col0 + r) * lda + koff + seg * 8;
        CP16(d + POFF_BHI, Bhi + g);
        CP16(d + POFF_BLO, Blo + g);
    }
}

__device__ __forceinline__ void pipe_mainloop(
    uint32_t sb,
    const __nv_bfloat16* __restrict__ Ahi, const __nv_bfloat16* __restrict__ Alo,
    const __nv_bfloat16* __restrict__ Bhi, const __nv_bfloat16* __restrict__ Blo,
    int K, int row0, int col0, int tid, int warp_m, int warp_n, int lane,
    float acc[2][4][4])
{
    const int a_lr = lane & 15, a_lk = (lane >> 4) * 8;
    const int b_grp = lane >> 3;
    const int b_lr = (lane & 7) + ((b_grp >> 1) * 8);
    const int b_lk = (b_grp & 1) * 8;

    const int nch = K >> 5;
    big_load_stage(sb, Ahi, Alo, Bhi, Blo, K, row0, col0, 0, tid);
    CP_COMMIT();
    for (int kc = 0; kc < nch; kc++) {
        if (kc + 1 < nch) {
            big_load_stage(sb + (uint32_t)(((kc + 1) & 1) * SS),
                           Ahi, Alo, Bhi, Blo, K, row0, col0, (kc + 1) * 32, tid);
            CP_COMMIT();
            CP_WAIT1();
        } else {
            CP_WAIT0();
        }
        __syncthreads();
        const uint32_t st = sb + (uint32_t)((kc & 1) * SS);
#pragma unroll
        for (int k16 = 0; k16 < 32; k16 += 16) {
            uint32_t aHi[2][4], aLo[2][4], bH[8], bL[8];
#pragma unroll
            for (int mt = 0; mt < 2; mt++) {
                const uint32_t ab = st + (uint32_t)((warp_m * 32 + mt * 16 + a_lr) * 80
                                                    + (k16 + a_lk) * 2);
                LDSM4(aHi[mt], ab + POFF_AHI);
                LDSM4(aLo[mt], ab + POFF_ALO);
            }
#pragma unroll
            for (int half = 0; half < 2; half++) {
                const uint32_t bb = st + (uint32_t)((warp_n * 32 + half * 16 + b_lr) * 80
                                                    + (k16 + b_lk) * 2);
                LDSM4(bH + half * 4, bb + POFF_BHI);
                LDSM4(bL + half * 4, bb + POFF_BLO);
            }
#pragma unroll
            for (int mt = 0; mt < 2; mt++)
#pragma unroll
                for (int nt = 0; nt < 4; nt++) {
                    MMA16816(acc[mt][nt], aHi[mt], bH[nt * 2], bH[nt * 2 + 1]);
                    MMA16816(acc[mt][nt], aLo[mt], bH[nt * 2], bH[nt * 2 + 1]);
                    MMA16816(acc[mt][nt], aHi[mt], bL[nt * 2], bL[nt * 2 + 1]);
                }
        }
        __syncthreads();
    }
}

// =================================================================
// BIG HMMA GEMM (featproj / embgates / logits)
// Ch != null -> write f16 output (featproj); else fp32 C.
// =================================================================
__global__ __launch_bounds__(256, 2)
void hmma_big_kernel(int Nreal, int K,
                     const __nv_bfloat16* __restrict__ Ahi, const __nv_bfloat16* __restrict__ Alo,
                     const __nv_bfloat16* __restrict__ Bhi, const __nv_bfloat16* __restrict__ Blo,
                     float* __restrict__ C, __half* __restrict__ Ch, int ldc,
                     const float* __restrict__ bias, int remap)
{
    extern __shared__ char sm[];
    const uint32_t sb = smem_u32(sm);
    const int tid = threadIdx.x;
    const int wid = tid >> 5, lane = tid & 31;
    const int warp_m = wid & 3;
    const int warp_n = wid >> 2;
    const int row0 = blockIdx.y * 128;
    const int col0 = blockIdx.x * 64;

    float acc[2][4][4];
#pragma unroll
    for (int mt = 0; mt < 2; mt++)
#pragma unroll
        for (int nt = 0; nt < 4; nt++)
#pragma unroll
            for (int r = 0; r < 4; r++) acc[mt][nt][r] = 0.f;

    pipe_mainloop(sb, Ahi, Alo, Bhi, Blo, K, row0, col0, tid, warp_m, warp_n, lane, acc);

    const int quad = lane >> 2, tc = lane & 3;
#pragma unroll
    for (int mt = 0; mt < 2; mt++)
#pragma unroll
        for (int half = 0; half < 2; half++) {
            const int gm = row0 + warp_m * 32 + mt * 16 + quad + half * 8;
            const size_t rowC = remap ? ((size_t)(gm & (Bv - 1)) * Tv + (gm >> 7))
                                      : (size_t)gm;
#pragma unroll
            for (int nt = 0; nt < 4; nt++) {
                const int gn = col0 + warp_n * 32 + nt * 8 + tc * 2;
                if (gn >= Nreal) continue;
                const float2 bv = *(const float2*)&bias[gn];
                const float v0 = acc[mt][nt][half * 2]     + bv.x;
                const float v1 = acc[mt][nt][half * 2 + 1] + bv.y;
                if (Ch) {
                    *(__half2*)&Ch[rowC * (size_t)ldc + gn] = __floats2half2_rn(v0, v1);
                } else {
                    float2 o; o.x = v0; o.y = v1;
                    *(float2*)&C[rowC * (size_t)ldc + gn] = o;
                }
            }
        }
}

// =================================================================
// hproj GEMM (pipelined): hproj = h @ [W_dec | W_hh_int] + bh. M=128.
// =================================================================
__global__ __launch_bounds__(256, 2)
void hproj_kernel(const __nv_bfloat16* __restrict__ Ahi, const __nv_bfloat16* __restrict__ Alo,
                  const __nv_bfloat16* __restrict__ Bhi, const __nv_bfloat16* __restrict__ Blo,
                  float* __restrict__ C, const float* __restrict__ bias)
{
    extern __shared__ char sm[];
    const uint32_t sb = smem_u32(sm);
    const int tid = threadIdx.x;
    const int wid = tid >> 5, lane = tid & 31;
    const int warp_m = wid & 3;
    const int warp_n = wid >> 2;
    const int col0 = blockIdx.x * 64;

    float acc[2][4][4];
#pragma unroll
    for (int mt = 0; mt < 2; mt++)
#pragma unroll
        for (int nt = 0; nt < 4; nt++)
#pragma unroll
            for (int r = 0; r < 4; r++) acc[mt][nt][r] = 0.f;

    pipe_mainloop(sb, Ahi, Alo, Bhi, Blo, Dv, 0, col0, tid, warp_m, warp_n, lane, acc);

    const int quad = lane >> 2, tc = lane & 3;
#pragma unroll
    for (int mt = 0; mt < 2; mt++)
#pragma unroll
        for (int half = 0; half < 2; half++) {
            const int gm = warp_m * 32 + mt * 16 + quad + half * 8;
#pragma unroll
            for (int nt = 0; nt < 4; nt++) {
                const int gn = col0 + warp_n * 32 + nt * 8 + tc * 2;
                const float2 bv = *(const float2*)&bias[gn];
                float2 o;
                o.x = acc[mt][nt][half * 2]     + bv.x;
                o.y = acc[mt][nt][half * 2 + 1] + bv.y;
                *(float2*)&C[(size_t)gm * HW + gn] = o;
            }
        }
}

// =================================================================
// Gates GEMM + fused LSTM epilogue (pipelined mainloop).
// gates_int = ctx @ WihcTi^T + embgates_int[t] + hproj[:, 512:].
// =================================================================
__global__ __launch_bounds__(256, 2)
void gates_lstm_kernel(const __nv_bfloat16* __restrict__ ctxHi, const __nv_bfloat16* __restrict__ ctxLo,
                       const __nv_bfloat16* __restrict__ wHi, const __nv_bfloat16* __restrict__ wLo,
                       const float* __restrict__ egt,
                       const float* __restrict__ hproj,
                       float* __restrict__ c,
                       __nv_bfloat16* __restrict__ HtHi, __nv_bfloat16* __restrict__ HtLo)
{
    extern __shared__ char sm[];
    const uint32_t sb = smem_u32(sm);
    const int tid = threadIdx.x;
    const int wid = tid >> 5, lane = tid & 31;
    const int warp_m = wid & 3;
    const int warp_n = wid >> 2;
    const int col0 = blockIdx.x * 64;

    float acc[2][4][4];
#pragma unroll
    for (int mt = 0; mt < 2; mt++)
#pragma unroll
        for (int nt = 0; nt < 4; nt++)
#pragma unroll
            for (int r = 0; r < 4; r++) acc[mt][nt][r] = 0.f;

    pipe_mainloop(sb, ctxHi, ctxLo, wHi, wLo, Dv, 0, col0, tid, warp_m, warp_n, lane, acc);

    float* gs = (float*)sm;
    const int quad = lane >> 2, tc = lane & 3;
#pragma unroll
    for (int mt = 0; mt < 2; mt++)
#pragma unroll
        for (int half = 0; half < 2; half++) {
            const int gm = warp_m * 32 + mt * 16 + quad + half * 8;
#pragma unroll
            for (int nt = 0; nt < 4; nt++) {
                const int gn = warp_n * 32 + nt * 8 + tc * 2;
                const float2 e = *(const float2*)&egt[(size_t)gm * G4D + col0 + gn];
                const float2 hp = *(const float2*)&hproj[(size_t)gm * HW + 512 + col0 + gn];
                gs[gm * 68 + gn]     = acc[mt][nt][half * 2]     + e.x + hp.x;
                gs[gm * 68 + gn + 1] = acc[mt][nt][half * 2 + 1] + e.y + hp.y;
            }
        }
    __syncthreads();

    const int d0 = col0 >> 2;
#pragma unroll
    for (int i = tid; i < 2048; i += 256) {
        const int b = i >> 4, u = i & 15;
        const float* gr = gs + b * 68 + u * 4;
        const float gi = gr[0], gf = gr[1], gg = gr[2], go = gr[3];
        const int d = d0 + u;
        const float si = 1.f / (1.f + __expf(-gi));
        const float sf = 1.f / (1.f + __expf(-gf));
        const float so = 1.f / (1.f + __expf(-go));
        const float tg = tanhf(gg);
        const float cn = sf * c[b * Dv + d] + si * tg;
        c[b * Dv + d] = cn;
        const float h = so * tanhf(cn);
        const __nv_bfloat16 hh = __float2bfloat16(h);
        HtHi[b * Dv + d] = hh;
        HtLo[b * Dv + d] = __float2bfloat16(h - __bfloat162float(hh));
    }
}

// =================================================================
// Small fp32 SGEMM (one-time h0/c0 init only)
// =================================================================
template<int BM, int BN, int BK, int TM, int TN>
__global__ void sgemm_kernel(int M, int N, int K,
                             const float* __restrict__ A, int lda,
                             const float* __restrict__ B, int ldb,
                             float* __restrict__ C, int ldc,
                             const float* __restrict__ bias)
{
    constexpr int TX = BN / TN;
    constexpr int TY = BM / TM;
    constexpr int NT = TX * TY;
    __shared__ float As[BK][BM + 1];
    __shared__ float Bs[BK][BN];

    const int tid = threadIdx.x;
    const int tx = tid % TX, ty = tid / TX;
    const int row0 = blockIdx.y * BM;
    const int col0 = blockIdx.x * BN;

    float acc[TM][TN];
#pragma unroll
    for (int i = 0; i < TM; i++)
#pragma unroll
        for (int j = 0; j < TN; j++) acc[i][j] = 0.f;

    for (int k0 = 0; k0 < K; k0 += BK) {
#pragma unroll
        for (int i = tid; i < BM * BK; i += NT) {
            int m = i / BK, k = i % BK;
            As[k][m] = A[(size_t)(row0 + m) * lda + k0 + k];
        }
#pragma unroll
        for (int i = tid; i < BK * BN; i += NT) {
            int k = i / BN, n = i % BN;
            Bs[k][n] = B[(size_t)(k0 + k) * ldb + col0 + n];
        }
        __syncthreads();
#pragma unroll
        for (int kk = 0; kk < BK; kk++) {
            float ra[TM], rb[TN];
#pragma unroll
            for (int i = 0; i < TM; i++) ra[i] = As[kk][ty * TM + i];
#pragma unroll
            for (int j = 0; j < TN; j++) rb[j] = Bs[kk][tx * TN + j];
#pragma unroll
            for (int i = 0; i < TM; i++)
#pragma unroll
                for (int j = 0; j < TN; j++)
                    acc[i][j] = fmaf(ra[i], rb[j], acc[i][j]);
        }
        __syncthreads();
    }

#pragma unroll
    for (int i = 0; i < TM; i++)
#pragma unroll
        for (int j = 0; j < TN; j++) {
            int gm = row0 + ty * TM + i, gn = col0 + tx * TN + j;
            C[(size_t)gm * ldc + gn] = acc[i][j] + bias[gn];
        }
}

// ---------------- prep kernels ----------------
__device__ __forceinline__ void split_hilo(float v, __nv_bfloat16& h, __nv_bfloat16& l) {
    h = __float2bfloat16(v);
    l = __float2bfloat16(v - __bfloat162float(h));
}

__global__ void whcatT_hilo_kernel(const float* __restrict__ Wdec, const float* __restrict__ Whh,
                                   __nv_bfloat16* __restrict__ hi, __nv_bfloat16* __restrict__ lo)
{
    int idx = blockIdx.x * blockDim.x + threadIdx.x;
    if (idx >= HW * Dv) return;
    int k = idx & 511, n = idx >> 9;
    float v;
    if (n < 512) {
        v = Wdec[(size_t)k * Av + n];
    } else {
        int m = n - 512;
        int col_old = (m & 3) * 512 + (m >> 2);
        v = Whh[(size_t)k * G4D + col_old];
    }
    split_hilo(v, hi[idx], lo[idx]);
}

__global__ void wihcTi_kernel(const float* __restrict__ Wih,
                              __nv_bfloat16* __restrict__ hi, __nv_bfloat16* __restrict__ lo)
{
    int idx = blockIdx.x * blockDim.x + threadIdx.x;
    if (idx >= G4D * Dv) return;
    int k = idx & 511, n = idx >> 9;
    int col_old = (n & 3) * 512 + (n >> 2);
    float v = Wih[(size_t)(Ev + k) * G4D + col_old];
    split_hilo(v, hi[idx], lo[idx]);
}

__global__ void wihTi_kernel(const float* __restrict__ Wih,
                             __nv_bfloat16* __restrict__ hi, __nv_bfloat16* __restrict__ lo)
{
    int idx = blockIdx.x * blockDim.x + threadIdx.x;
    if (idx >= G4D * KE) return;
    int k = idx % KE, n = idx / KE;
    int col_old = (n & 3) * 512 + (n >> 2);
    float v = (k < Ev) ? Wih[(size_t)k * G4D + col_old] : 0.f;
    split_hilo(v, hi[idx], lo[idx]);
}

__global__ void biases_kernel(const float* __restrict__ bdec,
                              const float* __restrict__ bih, const float* __restrict__ bhh,
                              float* __restrict__ bh, float* __restrict__ b2i)
{
    int j = blockIdx.x * blockDim.x + threadIdx.x;
    if (j < HW) bh[j] = (j < 512) ? bdec[j] : 0.f;
    if (j < G4D) {
        int col_old = (j & 3) * 512 + (j >> 2);
        b2i[j] = bih[col_old] + bhh[col_old];
    }
}

__global__ void embgather_hilo_kernel(const float* __restrict__ emb, const int* __restrict__ cap,
                                      __nv_bfloat16* __restrict__ hi, __nv_bfloat16* __restrict__ lo)
{
    int idx = blockIdx.x * blockDim.x + threadIdx.x;
    if (idx >= Tv * Bv * KE) return;
    int k = idx % KE, r = idx / KE;
    int t = r / Bv, b = r % Bv;
    float v = 0.f;
    if (k < Ev) v = emb[(size_t)cap[b * Lv + t] * Ev + k];
    split_hilo(v, hi[idx], lo[idx]);
}

__global__ void conv_hilo_kernel(const float* __restrict__ in, size_t n,
                                 __nv_bfloat16* __restrict__ hi, __nv_bfloat16* __restrict__ lo)
{
    size_t idx = (size_t)blockIdx.x * blockDim.x + threadIdx.x;
    if (idx >= n) return;
    split_hilo(in[idx], hi[idx], lo[idx]);
}

__global__ void conv4_hilo_kernel(const float4* __restrict__ in, size_t n4,
                                  __nv_bfloat162* __restrict__ hi, __nv_bfloat162* __restrict__ lo)
{
    size_t idx = (size_t)blockIdx.x * blockDim.x + threadIdx.x;
    if (idx >= n4) return;
    float4 v = in[idx];
    __nv_bfloat16 h0, l0, h1, l1, h2, l2, h3, l3;
    split_hilo(v.x, h0, l0); split_hilo(v.y, h1, l1);
    split_hilo(v.z, h2, l2); split_hilo(v.w, h3, l3);
    hi[idx * 2]     = __nv_bfloat162(h0, h1);
    hi[idx * 2 + 1] = __nv_bfloat162(h2, h3);
    lo[idx * 2]     = __nv_bfloat162(l0, l1);
    lo[idx * 2 + 1] = __nv_bfloat162(l2, l3);
}

__global__ void trans_hilo_kernel(const float* __restrict__ in, int R, int C,
                                  __nv_bfloat16* __restrict__ hi, __nv_bfloat16* __restrict__ lo,
                                  int Kpad, int Npad)
{
    __shared__ float t[32][33];
    const int cb = blockIdx.x * 32;
    const int rb = blockIdx.y * 32;
    const int x = threadIdx.x, y = threadIdx.y;
#pragma unroll
    for (int i = y; i < 32; i += 8) {
        int r = rb + i, ccol = cb + x;
        t[i][x] = (r < R && ccol < C) ? in[(size_t)r * C + ccol] : 0.f;
    }
    __syncthreads();
#pragma unroll
    for (int i = y; i < 32; i += 8) {
        int n = cb + i, k = rb + x;
        if (n < Npad && k < Kpad) {
            size_t o = (size_t)n * Kpad + k;
            split_hilo(t[x][i], hi[o], lo[o]);
        }
    }
}

__global__ void meanf_kernel(const float* __restrict__ feat, float* __restrict__ mf)
{
    int b = blockIdx.x, tid = threadIdx.x;
    for (int d = tid; d < ENCv; d += 256) {
        float s = 0.f;
        const float* p = feat + (size_t)b * Nv * ENCv + d;
#pragma unroll 4
        for (int n = 0; n < Nv; n++) s += p[(size_t)n * ENCv];
        mf[b * ENCv + d] = s * (1.0f / (float)Nv);
    }
}

// ---------------- fused attention: f16 score loop (4 instrs / 2 elems) ----------------
__global__ void attention_kernel(const __half2* __restrict__ fp_h,  // [B*N, 256] half2
                                 const float* __restrict__ feat,
                                 const float* __restrict__ dec,     // hproj[:, :512], ld=HW
                                 const float* __restrict__ watt,
                                 __nv_bfloat16* __restrict__ ctxHi,
                                 __nv_bfloat16* __restrict__ ctxLo,
                                 float* __restrict__ alphaOut)
{
    __shared__ __half2 s_dech[256];
    __shared__ __half2 s_wh[256];
    __shared__ float s_sc[Nv];
    __shared__ float s_red[8];
    const int b = blockIdx.x, tid = threadIdx.x;

    {
        const float2 dv = ((const float2*)(dec + (size_t)b * HW))[tid];
        s_dech[tid] = __floats2half2_rn(dv.x, dv.y);
        const float2 wv = ((const float2*)watt)[tid];
        s_wh[tid] = __floats2half2_rn(wv.x, wv.y);
    }
    __syncthreads();

    const int warp = tid >> 5, lane = tid & 31;
    // preload dec and w into registers (fixed lane positions)
    __half2 rd[8], rw[8];
#pragma unroll
    for (int i = 0; i < 8; i++) {
        rd[i] = s_dech[lane + 32 * i];
        rw[i] = s_wh[lane + 32 * i];
    }

    for (int n = warp; n < Nv; n += 8) {
        const __half2* row = fp_h + (size_t)(b * Nv + n) * 256;
        __half2 acc2 = __floats2half2_rn(0.f, 0.f);
#pragma unroll
        for (int i = 0; i < 8; i++) {
            __half2 x = __hadd2(row[lane + 32 * i], rd[i]);
            uint32_t th;
            asm("tanh.approx.f16x2 %0, %1;" : "=r"(th) : "r"(*(uint32_t*)&x));
            acc2 = __hfma2(*(__half2*)&th, rw[i], acc2);
        }
        float s = __low2float(acc2) + __high2float(acc2);
#pragma unroll
        for (int o = 16; o; o >>= 1) s += __shfl_xor_sync(0xffffffffu, s, o);
        if (lane == 0) s_sc[n] = s;
    }
    __syncthreads();

    float m = -1e30f;
    for (int n = tid; n < Nv; n += 256) m = fmaxf(m, s_sc[n]);
#pragma unroll
    for (int o = 16; o; o >>= 1) m = fmaxf(m, __shfl_xor_sync(0xffffffffu, m, o));
    if (lane == 0) s_red[warp] = m;
    __syncthreads();
    if (tid == 0) {
        float mm = s_red[0];
        for (int w = 1; w < 8; w++) mm = fmaxf(mm, s_red[w]);
        s_red[0] = mm;
    }
    __syncthreads();
    m = s_red[0];
    __syncthreads();

    float sum = 0.f;
    for (int n = tid; n < Nv; n += 256) {
        float e = __expf(s_sc[n] - m);
        s_sc[n] = e;
        sum += e;
    }
#pragma unroll
    for (int o = 16; o; o >>= 1) sum += __shfl_xor_sync(0xffffffffu, sum, o);
    if (lane == 0) s_red[warp] = sum;
    __syncthreads();
    if (tid == 0) {
        float ss = 0.f;
        for (int w = 0; w < 8; w++) ss += s_red[w];
        s_red[0] = 1.f / ss;
    }
    __syncthreads();
    const float inv = s_red[0];
    for (int n = tid; n < Nv; n += 256) {
        float a = s_sc[n] * inv;
        s_sc[n] = a;
        alphaOut[(size_t)b * Tv * Nv + n] = a;
    }
    __syncthreads();

    const float* fb = feat + (size_t)b * Nv * ENCv;
    for (int d = tid; d < ENCv; d += 256) {
        float acc = 0.f;
#pragma unroll 4
        for (int n = 0; n < Nv; n++) acc = fmaf(s_sc[n], fb[(size_t)n * ENCv + d], acc);
        split_hilo(acc, ctxHi[b * ENCv + d], ctxLo[b * ENCv + d]);
    }
}

// ---------------- host helpers ----------------
static void launch_big(int M, int N, int Nreal, int K,
                       const __nv_bfloat16* Ahi, const __nv_bfloat16* Alo,
                       const __nv_bfloat16* Bhi, const __nv_bfloat16* Blo,
                       float* C, __half* Ch, int ldc, const float* bias, int remap)
{
    dim3 grid(N / 64, M / 128);
    hmma_big_kernel<<<grid, 256, BIG_SMEM>>>(Nreal, K, Ahi, Alo, Bhi, Blo,
                                             C, Ch, ldc, bias, remap);
}

extern "C" void kernel_launch(void* const* d_in, const int* in_sizes, int n_in,
                              void* d_out, int out_size)
{
    const float* features  = (const float*)d_in[0];
    const int*   captions  = (const int*)  d_in[1];
    const float* embedding = (const float*)d_in[2];
    const float* W_enc     = (const float*)d_in[3];
    const float* b_enc     = (const float*)d_in[4];
    const float* W_dec     = (const float*)d_in[5];
    const float* b_dec     = (const float*)d_in[6];
    const float* w_att     = (const float*)d_in[7];
    // d_in[8] = b_att : softmax-invariant, unused
    const float* Wi_h      = (const float*)d_in[9];
    const float* bi_h      = (const float*)d_in[10];
    const float* Wi_c      = (const float*)d_in[11];
    const float* bi_c      = (const float*)d_in[12];
    const float* W_ih      = (const float*)d_in[13];
    const float* b_ih      = (const float*)d_in[14];
    const float* W_hh      = (const float*)d_in[15];
    const float* b_hh      = (const float*)d_in[16];
    const float* W_out     = (const float*)d_in[17];
    const float* b_out     = (const float*)d_in[18];
    float* out = (float*)d_out;

    cudaFuncSetAttribute(hmma_big_kernel, cudaFuncAttributeMaxDynamicSharedMemorySize, BIG_SMEM);
    cudaFuncSetAttribute(hproj_kernel,    cudaFuncAttributeMaxDynamicSharedMemorySize, BIG_SMEM);
    cudaFuncSetAttribute(gates_lstm_kernel, cudaFuncAttributeMaxDynamicSharedMemorySize, BIG_SMEM);

    float *embgates, *bh, *bias2i, *meanf, *h0, *c, *hproj;
    __half* featprojh;
    __nv_bfloat16 *fhi, *flo, *wenchi, *wenclo, *wihhi, *wihlo, *wihchi, *wihclo,
                  *whcthi, *whctlo, *wouthi, *woutlo, *eahi, *ealo,
                  *Hhi, *Hlo, *h0hi, *h0lo, *ctxhi, *ctxlo;
    cudaGetSymbolAddress((void**)&featprojh, g_featproj_h);
    cudaGetSymbolAddress((void**)&embgates, g_embgates);
    cudaGetSymbolAddress((void**)&bh,       g_bh);
    cudaGetSymbolAddress((void**)&bias2i,   g_bias2i);
    cudaGetSymbolAddress((void**)&meanf,    g_meanf);
    cudaGetSymbolAddress((void**)&h0,       g_h0);
    cudaGetSymbolAddress((void**)&c,        g_c);
    cudaGetSymbolAddress((void**)&hproj,    g_hproj);
    cudaGetSymbolAddress((void**)&fhi,      g_feat_hi);
    cudaGetSymbolAddress((void**)&flo,      g_feat_lo);
    cudaGetSymbolAddress((void**)&wenchi,   g_WencT_hi);
    cudaGetSymbolAddress((void**)&wenclo,   g_WencT_lo);
    cudaGetSymbolAddress((void**)&wihhi,    g_WihTi_hi);
    cudaGetSymbolAddress((void**)&wihlo,    g_WihTi_lo);
    cudaGetSymbolAddress((void**)&wihchi,   g_WihcTi_hi);
    cudaGetSymbolAddress((void**)&wihclo,   g_WihcTi_lo);
    cudaGetSymbolAddress((void**)&whcthi,   g_whcatT_hi);
    cudaGetSymbolAddress((void**)&whctlo,   g_whcatT_lo);
    cudaGetSymbolAddress((void**)&wouthi,   g_WoutT_hi);
    cudaGetSymbolAddress((void**)&woutlo,   g_WoutT_lo);
    cudaGetSymbolAddress((void**)&eahi,     g_embA_hi);
    cudaGetSymbolAddress((void**)&ealo,     g_embA_lo);
    cudaGetSymbolAddress((void**)&Hhi,      g_H_hi);
    cudaGetSymbolAddress((void**)&Hlo,      g_H_lo);
    cudaGetSymbolAddress((void**)&h0hi,     g_h0_hi);
    cudaGetSymbolAddress((void**)&h0lo,     g_h0_lo);
    cudaGetSymbolAddress((void**)&ctxhi,    g_ctx_hi);
    cudaGetSymbolAddress((void**)&ctxlo,    g_ctx_lo);

    dim3 tthr(32, 8);

    // ---- prep, featproj big GEMM stays at launch #4 (ncu slot) ----
    {
        size_t n4 = (size_t)Bv * Nv * ENCv / 4;
        conv4_hilo_kernel<<<(unsigned)((n4 + 255) / 256), 256>>>(
            (const float4*)features, n4, (__nv_bfloat162*)fhi, (__nv_bfloat162*)flo);     // 1
    }
    trans_hilo_kernel<<<dim3(16, 16), tthr>>>(W_enc, ENCv, Av, wenchi, wenclo, ENCv, Av); // 2
    whcatT_hilo_kernel<<<(HW * Dv + 255) / 256, 256>>>(W_dec, W_hh, whcthi, whctlo);      // 3
    // featproj (f16 output) = features @ W_enc + b_enc
    launch_big(Bv * Nv, Av, Av, ENCv, fhi, flo, wenchi, wenclo,
               nullptr, featprojh, Av, b_enc, 0);                                         // 4
    biases_kernel<<<(HW + 255) / 256, 256>>>(b_dec, b_ih, b_hh, bh, bias2i);              // 5
    embgather_hilo_kernel<<<(Tv * Bv * KE + 255) / 256, 256>>>(embedding, captions,
                                                               eahi, ealo);               // 6
    wihTi_kernel<<<(G4D * KE + 255) / 256, 256>>>(W_ih, wihhi, wihlo);                    // 7
    launch_big(Tv * Bv, G4D, G4D, KE, eahi, ealo, wihhi, wihlo,
               embgates, nullptr, G4D, bias2i, 0);                                        // 8
    wihcTi_kernel<<<(G4D * Dv + 255) / 256, 256>>>(W_ih, wihchi, wihclo);                 // 9
    trans_hilo_kernel<<<dim3((VP + 31) / 32, (Dv + 31) / 32), tthr>>>(
        W_out, Dv, Vv, wouthi, woutlo, Dv, VP);                                           // 10
    meanf_kernel<<<Bv, 256>>>(features, meanf);                                           // 11
    {
        dim3 g(Dv / 64, Bv / 32);
        sgemm_kernel<32, 64, 16, 2, 4><<<g, 256>>>(Bv, Dv, ENCv, meanf, ENCv,
                                                   Wi_h, Dv, h0, Dv, bi_h);               // 12
        sgemm_kernel<32, 64, 16, 2, 4><<<g, 256>>>(Bv, Dv, ENCv, meanf, ENCv,
                                                   Wi_c, Dv, c, Dv, bi_c);                // 13
    }
    conv_hilo_kernel<<<(Bv * Dv + 255) / 256, 256>>>(h0, (size_t)Bv * Dv, h0hi, h0lo);    // 14

    const size_t PRED = (size_t)Bv * Tv * Vv;

    for (int t = 0; t < Tv; t++) {
        const __nv_bfloat16* hpHi = (t == 0) ? h0hi : (Hhi + (size_t)(t - 1) * Bv * Dv);
        const __nv_bfloat16* hpLo = (t == 0) ? h0lo : (Hlo + (size_t)(t - 1) * Bv * Dv);
        // hproj = h @ [W_dec | W_hh_int] + [b_dec | 0]
        hproj_kernel<<<HW / 64, 256, BIG_SMEM>>>(hpHi, hpLo, whcthi, whctlo, hproj, bh);
        // attention -> ctx hi/lo, alphas[:, t, :]
        attention_kernel<<<Bv, 256>>>((const __half2*)featprojh, features, hproj, w_att,
                                      ctxhi, ctxlo, out + PRED + (size_t)t * Nv);
        // gates + fused LSTM -> c, Hhi/Hlo[t]
        gates_lstm_kernel<<<G4D / 64, 256, BIG_SMEM>>>(
            ctxhi, ctxlo, wihchi, wihclo,
            embgates + (size_t)t * Bv * G4D, hproj, c,
            Hhi + (size_t)t * Bv * Dv, Hlo + (size_t)t * Bv * Dv);
    }

    // preds: [T*B, V] = H @ W_out^T + b_out, remapped to [B, T, V]
    launch_big(Tv * Bv, VP, Vv, Dv, Hhi, Hlo, wouthi, woutlo,
               out, nullptr, Vv, b_out, 1);
}

// round 15
// speedup vs baseline: 1.3886x; 1.0316x over previous
#include <cuda_runtime.h>
#include <cuda_bf16.h>
#include <cuda_fp16.h>
#include <cstdint>
#include <cstddef>

// ---------------- problem constants ----------------
#define Bv   128
#define Nv   196
#define Lv   25
#define Tv   24
#define Vv   10000
#define Ev   300
#define Av   512
#define ENCv 512
#define Dv   512
#define G4D  2048   // 4*D
#define HW   2560   // cols of [W_dec | W_hh_interleaved]
#define KE   320    // E padded (multiple of 32)
#define VP   10112  // V padded (multiple of 64)

// ---------------- device scratch (static, no allocation) ----------------
__device__ __half g_featproj_h[(size_t)Bv * Nv * Av];   // f16 featproj
__device__ float g_embgates[(size_t)Tv * Bv * G4D];     // interleaved-gate layout
__device__ float g_bh[HW];
__device__ float g_bias2i[G4D];
__device__ float g_meanf[Bv * ENCv];
__device__ float g_h0[Bv * Dv];
__device__ float g_c[Bv * Dv];
__device__ float g_hproj[Bv * HW];

__device__ __nv_bfloat16 g_feat_hi[(size_t)Bv * Nv * ENCv];
__device__ __nv_bfloat16 g_feat_lo[(size_t)Bv * Nv * ENCv];
__device__ __nv_bfloat16 g_WencT_hi[Av * ENCv];
__device__ __nv_bfloat16 g_WencT_lo[Av * ENCv];
__device__ __nv_bfloat16 g_WihTi_hi[G4D * KE];
__device__ __nv_bfloat16 g_WihTi_lo[G4D * KE];
__device__ __nv_bfloat16 g_WihcTi_hi[G4D * Dv];
__device__ __nv_bfloat16 g_WihcTi_lo[G4D * Dv];
__device__ __nv_bfloat16 g_whcatT_hi[HW * Dv];
__device__ __nv_bfloat16 g_whcatT_lo[HW * Dv];
__device__ __nv_bfloat16 g_WoutT_hi[(size_t)VP * Dv];
__device__ __nv_bfloat16 g_WoutT_lo[(size_t)VP * Dv];
__device__ __nv_bfloat16 g_embA_hi[Tv * Bv * KE];
__device__ __nv_bfloat16 g_embA_lo[Tv * Bv * KE];
__device__ __nv_bfloat16 g_H_hi[(size_t)Tv * Bv * Dv];
__device__ __nv_bfloat16 g_H_lo[(size_t)Tv * Bv * Dv];
__device__ __nv_bfloat16 g_h0_hi[Bv * Dv];
__device__ __nv_bfloat16 g_h0_lo[Bv * Dv];
__device__ __nv_bfloat16 g_ctx_hi[Bv * Dv];
__device__ __nv_bfloat16 g_ctx_lo[Bv * Dv];

// ---------------- PTX helpers ----------------
__device__ __forceinline__ uint32_t smem_u32(const void* p) {
    uint32_t a;
    asm("{ .reg .u64 t; cvta.to.shared.u64 t, %1; cvt.u32.u64 %0, t; }" : "=r"(a) : "l"(p));
    return a;
}

#define LDSM4(r, addr) \
    asm volatile("ldmatrix.sync.aligned.m8n8.x4.shared.b16 {%0,%1,%2,%3}, [%4];" \
        : "=r"((r)[0]), "=r"((r)[1]), "=r"((r)[2]), "=r"((r)[3]) : "r"(addr))

#define MMA16816(d, a, b0, b1) \
    asm volatile("mma.sync.aligned.m16n8k16.row.col.f32.bf16.bf16.f32 " \
        "{%0,%1,%2,%3}, {%4,%5,%6,%7}, {%8,%9}, {%0,%1,%2,%3};" \
        : "+f"((d)[0]), "+f"((d)[1]), "+f"((d)[2]), "+f"((d)[3]) \
        : "r"((a)[0]), "r"((a)[1]), "r"((a)[2]), "r"((a)[3]), "r"(b0), "r"(b1))

#define CP16(dst, src) \
    asm volatile("cp.async.cg.shared.global [%0], [%1], 16;" :: "r"(dst), "l"(src) : "memory")
#define CP_COMMIT() asm volatile("cp.async.commit_group;" ::: "memory")
#define CP_WAIT1() asm volatile("cp.async.wait_group 1;" ::: "memory")
#define CP_WAIT0() asm volatile("cp.async.wait_group 0;" ::: "memory")

// =================================================================
// Shared pipelined HMMA mainloop: CTA 128x64, 4M x 2N warps, BK=32,
// 2-stage cp.async, smem row stride 80 B. lda == ldb == K assumed.
// =================================================================
#define SS       30720
#define POFF_AHI 0
#define POFF_ALO 10240
#define POFF_BHI 20480
#define POFF_BLO 25600
#define BIG_SMEM (2 * SS)   // 61440

__device__ __forceinline__ void big_load_stage(
    uint32_t base,
    const __nv_bfloat16* __restrict__ Ahi, const __nv_bfloat16* __restrict__ Alo,
    const __nv_bfloat16* __restrict__ Bhi, const __nv_bfloat16* __restrict__ Blo,
    int lda, int row0, int col0, int koff, int tid)
{
#pragma unroll
    for (int i = 0; i < 2; i++) {
        const int idx = tid + i * 256;
        const int r = idx >> 2, seg = idx & 3;
        const uint32_t d = base + (uint32_t)(r * 80 + seg * 16);
        const size_t g = (size_t)(row0 + r) * lda + koff + seg * 8;
        CP16(d + POFF_AHI, Ahi + g);
        CP16(d + POFF_ALO, Alo + g);
    }
    {
        const int r = tid >> 2, seg = tid & 3;
        const uint32_t d = base + (uint32_t)(r * 80 + seg * 16);
        const size_t g = (size_t)(col0 + r) * lda + koff + seg * 8;
        CP16(d + POFF_BHI, Bhi + g);
        CP16(d + POFF_BLO, Blo + g);
    }
}

__device__ __forceinline__ void pipe_mainloop(
    uint32_t sb,
    const __nv_bfloat16* __restrict__ Ahi, const __nv_bfloat16* __restrict__ Alo,
    const __nv_bfloat16* __restrict__ Bhi, const __nv_bfloat16* __restrict__ Blo,
    int K, int row0, int col0, int tid, int warp_m, int warp_n, int lane,
    float acc[2][4][4])
{
    const int a_lr = lane & 15, a_lk = (lane >> 4) * 8;
    const int b_grp = lane >> 3;
    const int b_lr = (lane & 7) + ((b_grp >> 1) * 8);
    const int b_lk = (b_grp & 1) * 8;

    const int nch = K >> 5;
    big_load_stage(sb, Ahi, Alo, Bhi, Blo, K, row0, col0, 0, tid);
    CP_COMMIT();
    for (int kc = 0; kc < nch; kc++) {
        if (kc + 1 < nch) {
            big_load_stage(sb + (uint32_t)(((kc + 1) & 1) * SS),
                           Ahi, Alo, Bhi, Blo, K, row0, col0, (kc + 1) * 32, tid);
            CP_COMMIT();
            CP_WAIT1();
        } else {
            CP_WAIT0();
        }
        __syncthreads();
        const uint32_t st = sb + (uint32_t)((kc & 1) * SS);
#pragma unroll
        for (int k16 = 0; k16 < 32; k16 += 16) {
            uint32_t aHi[2][4], aLo[2][4], bH[8], bL[8];
#pragma unroll
            for (int mt = 0; mt < 2; mt++) {
                const uint32_t ab = st + (uint32_t)((warp_m * 32 + mt * 16 + a_lr) * 80
                                                    + (k16 + a_lk) * 2);
                LDSM4(aHi[mt], ab + POFF_AHI);
                LDSM4(aLo[mt], ab + POFF_ALO);
            }
#pragma unroll
            for (int half = 0; half < 2; half++) {
                const uint32_t bb = st + (uint32_t)((warp_n * 32 + half * 16 + b_lr) * 80
                                                    + (k16 + b_lk) * 2);
                LDSM4(bH + half * 4, bb + POFF_BHI);
                LDSM4(bL + half * 4, bb + POFF_BLO);
            }
#pragma unroll
            for (int mt = 0; mt < 2; mt++)
#pragma unroll
                for (int nt = 0; nt < 4; nt++) {
                    MMA16816(acc[mt][nt], aHi[mt], bH[nt * 2], bH[nt * 2 + 1]);
                    MMA16816(acc[mt][nt], aLo[mt], bH[nt * 2], bH[nt * 2 + 1]);
                    MMA16816(acc[mt][nt], aHi[mt], bL[nt * 2], bL[nt * 2 + 1]);
                }
        }
        __syncthreads();
    }
}

// =================================================================
// BIG HMMA GEMM (featproj / embgates / logits)
// =================================================================
__global__ __launch_bounds__(256, 2)
void hmma_big_kernel(int Nreal, int K,
                     const __nv_bfloat16* __restrict__ Ahi, const __nv_bfloat16* __restrict__ Alo,
                     const __nv_bfloat16* __restrict__ Bhi, const __nv_bfloat16* __restrict__ Blo,
                     float* __restrict__ C, __half* __restrict__ Ch, int ldc,
                     const float* __restrict__ bias, int remap)
{
    extern __shared__ char sm[];
    const uint32_t sb = smem_u32(sm);
    const int tid = threadIdx.x;
    const int wid = tid >> 5, lane = tid & 31;
    const int warp_m = wid & 3;
    const int warp_n = wid >> 2;
    const int row0 = blockIdx.y * 128;
    const int col0 = blockIdx.x * 64;

    float acc[2][4][4];
#pragma unroll
    for (int mt = 0; mt < 2; mt++)
#pragma unroll
        for (int nt = 0; nt < 4; nt++)
#pragma unroll
            for (int r = 0; r < 4; r++) acc[mt][nt][r] = 0.f;

    pipe_mainloop(sb, Ahi, Alo, Bhi, Blo, K, row0, col0, tid, warp_m, warp_n, lane, acc);

    const int quad = lane >> 2, tc = lane & 3;
#pragma unroll
    for (int mt = 0; mt < 2; mt++)
#pragma unroll
        for (int half = 0; half < 2; half++) {
            const int gm = row0 + warp_m * 32 + mt * 16 + quad + half * 8;
            const size_t rowC = remap ? ((size_t)(gm & (Bv - 1)) * Tv + (gm >> 7))
                                      : (size_t)gm;
#pragma unroll
            for (int nt = 0; nt < 4; nt++) {
                const int gn = col0 + warp_n * 32 + nt * 8 + tc * 2;
                if (gn >= Nreal) continue;
                const float2 bv = *(const float2*)&bias[gn];
                const float v0 = acc[mt][nt][half * 2]     + bv.x;
                const float v1 = acc[mt][nt][half * 2 + 1] + bv.y;
                if (Ch) {
                    *(__half2*)&Ch[rowC * (size_t)ldc + gn] = __floats2half2_rn(v0, v1);
                } else {
                    float2 o; o.x = v0; o.y = v1;
                    *(float2*)&C[rowC * (size_t)ldc + gn] = o;
                }
            }
        }
}

// =================================================================
// hproj partial GEMM: cols [0, grid*64) of hproj = h @ whcat + bh.
// Launched with grid=8 -> dec part only.
// =================================================================
__global__ __launch_bounds__(256, 2)
void hproj_kernel(const __nv_bfloat16* __restrict__ Ahi, const __nv_bfloat16* __restrict__ Alo,
                  const __nv_bfloat16* __restrict__ Bhi, const __nv_bfloat16* __restrict__ Blo,
                  float* __restrict__ C, const float* __restrict__ bias)
{
    extern __shared__ char sm[];
    const uint32_t sb = smem_u32(sm);
    const int tid = threadIdx.x;
    const int wid = tid >> 5, lane = tid & 31;
    const int warp_m = wid & 3;
    const int warp_n = wid >> 2;
    const int col0 = blockIdx.x * 64;

    float acc[2][4][4];
#pragma unroll
    for (int mt = 0; mt < 2; mt++)
#pragma unroll
        for (int nt = 0; nt < 4; nt++)
#pragma unroll
            for (int r = 0; r < 4; r++) acc[mt][nt][r] = 0.f;

    pipe_mainloop(sb, Ahi, Alo, Bhi, Blo, Dv, 0, col0, tid, warp_m, warp_n, lane, acc);

    const int quad = lane >> 2, tc = lane & 3;
#pragma unroll
    for (int mt = 0; mt < 2; mt++)
#pragma unroll
        for (int half = 0; half < 2; half++) {
            const int gm = warp_m * 32 + mt * 16 + quad + half * 8;
#pragma unroll
            for (int nt = 0; nt < 4; nt++) {
                const int gn = col0 + warp_n * 32 + nt * 8 + tc * 2;
                const float2 bv = *(const float2*)&bias[gn];
                float2 o;
                o.x = acc[mt][nt][half * 2]     + bv.x;
                o.y = acc[mt][nt][half * 2 + 1] + bv.y;
                *(float2*)&C[(size_t)gm * HW + gn] = o;
            }
        }
}

// =================================================================
// Fused stage 2: CTAs 0..127 attention (f16 score loop, ld128);
// CTAs 128..159 hproj W_hh-part GEMM (cols 512..2559).
// =================================================================
__global__ __launch_bounds__(256, 2)
void att_hh_kernel(const __half2* __restrict__ fp_h,
                   const float* __restrict__ feat,
                   float* hproj,                       // read [:, :512], write [:, 512:]
                   const float* __restrict__ watt,
                   const __nv_bfloat16* __restrict__ hpHi, const __nv_bfloat16* __restrict__ hpLo,
                   const __nv_bfloat16* __restrict__ wHi, const __nv_bfloat16* __restrict__ wLo,
                   const float* __restrict__ bh,
                   __nv_bfloat16* __restrict__ ctxHi, __nv_bfloat16* __restrict__ ctxLo,
                   float* __restrict__ alphaOut)
{
    extern __shared__ char sm[];
    const int tid = threadIdx.x;

    if (blockIdx.x >= 128) {
        // ---- hproj W_hh part: cols 512 + (bid-128)*64 ----
        const uint32_t sb = smem_u32(sm);
        const int wid = tid >> 5, lane = tid & 31;
        const int warp_m = wid & 3;
        const int warp_n = wid >> 2;
        const int col0 = 512 + (blockIdx.x - 128) * 64;

        float acc[2][4][4];
#pragma unroll
        for (int mt = 0; mt < 2; mt++)
#pragma unroll
            for (int nt = 0; nt < 4; nt++)
#pragma unroll
                for (int r = 0; r < 4; r++) acc[mt][nt][r] = 0.f;

        pipe_mainloop(sb, hpHi, hpLo, wHi, wLo, Dv, 0, col0, tid, warp_m, warp_n, lane, acc);

        const int quad = lane >> 2, tc = lane & 3;
#pragma unroll
        for (int mt = 0; mt < 2; mt++)
#pragma unroll
            for (int half = 0; half < 2; half++) {
                const int gm = warp_m * 32 + mt * 16 + quad + half * 8;
#pragma unroll
                for (int nt = 0; nt < 4; nt++) {
                    const int gn = col0 + warp_n * 32 + nt * 8 + tc * 2;
                    float2 o;
                    o.x = acc[mt][nt][half * 2];
                    o.y = acc[mt][nt][half * 2 + 1];
                    *(float2*)&hproj[(size_t)gm * HW + gn] = o;
                }
            }
        return;
    }

    // ---- attention for batch row b ----
    __shared__ __half2 s_dech[256];
    __shared__ __half2 s_wh[256];
    __shared__ float s_sc[Nv];
    __shared__ float s_red[8];
    const int b = blockIdx.x;

    {
        const float2 dv = ((const float2*)(hproj + (size_t)b * HW))[tid];
        s_dech[tid] = __floats2half2_rn(dv.x, dv.y);
        const float2 wv = ((const float2*)watt)[tid];
        s_wh[tid] = __floats2half2_rn(wv.x, wv.y);
    }
    __syncthreads();

    const int warp = tid >> 5, lane = tid & 31;
    // lane covers contiguous half2 block [lane*8, lane*8+8)
    __half2 rd[8], rw[8];
#pragma unroll
    for (int j = 0; j < 8; j++) {
        rd[j] = s_dech[lane * 8 + j];
        rw[j] = s_wh[lane * 8 + j];
    }

    for (int n = warp; n < Nv; n += 8) {
        const uint4* r4 = reinterpret_cast<const uint4*>(fp_h + (size_t)(b * Nv + n) * 256)
                          + lane * 2;
        const uint4 q0 = r4[0];
        const uint4 q1 = r4[1];
        uint32_t qa[8];
        qa[0] = q0.x; qa[1] = q0.y; qa[2] = q0.z; qa[3] = q0.w;
        qa[4] = q1.x; qa[5] = q1.y; qa[6] = q1.z; qa[7] = q1.w;
        __half2 acc2 = __floats2half2_rn(0.f, 0.f);
#pragma unroll
        for (int j = 0; j < 8; j++) {
            __half2 x = __hadd2(*(__half2*)&qa[j], rd[j]);
            uint32_t th;
            asm("tanh.approx.f16x2 %0, %1;" : "=r"(th) : "r"(*(uint32_t*)&x));
            acc2 = __hfma2(*(__half2*)&th, rw[j], acc2);
        }
        float s = __low2float(acc2) + __high2float(acc2);
#pragma unroll
        for (int o = 16; o; o >>= 1) s += __shfl_xor_sync(0xffffffffu, s, o);
        if (lane == 0) s_sc[n] = s;
    }
    __syncthreads();

    float m = -1e30f;
    for (int n = tid; n < Nv; n += 256) m = fmaxf(m, s_sc[n]);
#pragma unroll
    for (int o = 16; o; o >>= 1) m = fmaxf(m, __shfl_xor_sync(0xffffffffu, m, o));
    if (lane == 0) s_red[warp] = m;
    __syncthreads();
    if (tid == 0) {
        float mm = s_red[0];
        for (int w = 1; w < 8; w++) mm = fmaxf(mm, s_red[w]);
        s_red[0] = mm;
    }
    __syncthreads();
    m = s_red[0];
    __syncthreads();

    float sum = 0.f;
    for (int n = tid; n < Nv; n += 256) {
        float e = __expf(s_sc[n] - m);
        s_sc[n] = e;
        sum += e;
    }
#pragma unroll
    for (int o = 16; o; o >>= 1) sum += __shfl_xor_sync(0xffffffffu, sum, o);
    if (lane == 0) s_red[warp] = sum;
    __syncthreads();
    if (tid == 0) {
        float ss = 0.f;
        for (int w = 0; w < 8; w++) ss += s_red[w];
        s_red[0] = 1.f / ss;
    }
    __syncthreads();
    const float inv = s_red[0];
    for (int n = tid; n < Nv; n += 256) {
        float a = s_sc[n] * inv;
        s_sc[n] = a;
        alphaOut[(size_t)b * Tv * Nv + n] = a;
    }
    __syncthreads();

    const float* fb = feat + (size_t)b * Nv * ENCv;
    for (int d = tid; d < ENCv; d += 256) {
        float acc = 0.f;
#pragma unroll 4
        for (int n = 0; n < Nv; n++) acc = fmaf(s_sc[n], fb[(size_t)n * ENCv + d], acc);
        const __nv_bfloat16 hh = __float2bfloat16(acc);
        ctxHi[b * ENCv + d] = hh;
        ctxLo[b * ENCv + d] = __float2bfloat16(acc - __bfloat162float(hh));
    }
}

// =================================================================
// Gates GEMM + fused LSTM epilogue.
// =================================================================
__global__ __launch_bounds__(256, 2)
void gates_lstm_kernel(const __nv_bfloat16* __restrict__ ctxHi, const __nv_bfloat16* __restrict__ ctxLo,
                       const __nv_bfloat16* __restrict__ wHi, const __nv_bfloat16* __restrict__ wLo,
                       const float* __restrict__ egt,
                       const float* __restrict__ hproj,
                       float* __restrict__ c,
                       __nv_bfloat16* __restrict__ HtHi, __nv_bfloat16* __restrict__ HtLo)
{
    extern __shared__ char sm[];
    const uint32_t sb = smem_u32(sm);
    const int tid = threadIdx.x;
    const int wid = tid >> 5, lane = tid & 31;
    const int warp_m = wid & 3;
    const int warp_n = wid >> 2;
    const int col0 = blockIdx.x * 64;

    float acc[2][4][4];
#pragma unroll
    for (int mt = 0; mt < 2; mt++)
#pragma unroll
        for (int nt = 0; nt < 4; nt++)
#pragma unroll
            for (int r = 0; r < 4; r++) acc[mt][nt][r] = 0.f;

    pipe_mainloop(sb, ctxHi, ctxLo, wHi, wLo, Dv, 0, col0, tid, warp_m, warp_n, lane, acc);

    float* gs = (float*)sm;
    const int quad = lane >> 2, tc = lane & 3;
#pragma unroll
    for (int mt = 0; mt < 2; mt++)
#pragma unroll
        for (int half = 0; half < 2; half++) {
            const int gm = warp_m * 32 + mt * 16 + quad + half * 8;
#pragma unroll
            for (int nt = 0; nt < 4; nt++) {
                const int gn = warp_n * 32 + nt * 8 + tc * 2;
                const float2 e = *(const float2*)&egt[(size_t)gm * G4D + col0 + gn];
                const float2 hp = *(const float2*)&hproj[(size_t)gm * HW + 512 + col0 + gn];
                gs[gm * 68 + gn]     = acc[mt][nt][half * 2]     + e.x + hp.x;
                gs[gm * 68 + gn + 1] = acc[mt][nt][half * 2 + 1] + e.y + hp.y;
            }
        }
    __syncthreads();

    const int d0 = col0 >> 2;
#pragma unroll
    for (int i = tid; i < 2048; i += 256) {
        const int b = i >> 4, u = i & 15;
        const float* gr = gs + b * 68 + u * 4;
        const float gi = gr[0], gf = gr[1], gg = gr[2], go = gr[3];
        const int d = d0 + u;
        const float si = 1.f / (1.f + __expf(-gi));
        const float sf = 1.f / (1.f + __expf(-gf));
        const float so = 1.f / (1.f + __expf(-go));
        const float tg = tanhf(gg);
        const float cn = sf * c[b * Dv + d] + si * tg;
        c[b * Dv + d] = cn;
        const float h = so * tanhf(cn);
        const __nv_bfloat16 hh = __float2bfloat16(h);
        HtHi[b * Dv + d] = hh;
        HtLo[b * Dv + d] = __float2bfloat16(h - __bfloat162float(hh));
    }
}

// =================================================================
// Small fp32 SGEMM (one-time h0/c0 init only)
// =================================================================
template<int BM, int BN, int BK, int TM, int TN>
__global__ void sgemm_kernel(int M, int N, int K,
                             const float* __restrict__ A, int lda,
                             const float* __restrict__ B, int ldb,
                             float* __restrict__ C, int ldc,
                             const float* __restrict__ bias)
{
    constexpr int TX = BN / TN;
    constexpr int TY = BM / TM;
    constexpr int NT = TX * TY;
    __shared__ float As[BK][BM + 1];
    __shared__ float Bs[BK][BN];

    const int tid = threadIdx.x;
    const int tx = tid % TX, ty = tid / TX;
    const int row0 = blockIdx.y * BM;
    const int col0 = blockIdx.x * BN;

    float acc[TM][TN];
#pragma unroll
    for (int i = 0; i < TM; i++)
#pragma unroll
        for (int j = 0; j < TN; j++) acc[i][j] = 0.f;

    for (int k0 = 0; k0 < K; k0 += BK) {
#pragma unroll
        for (int i = tid; i < BM * BK; i += NT) {
            int m = i / BK, k = i % BK;
            As[k][m] = A[(size_t)(row0 + m) * lda + k0 + k];
        }
#pragma unroll
        for (int i = tid; i < BK * BN; i += NT) {
            int k = i / BN, n = i % BN;
            Bs[k][n] = B[(size_t)(k0 + k) * ldb + col0 + n];
        }
        __syncthreads();
#pragma unroll
        for (int kk = 0; kk < BK; kk++) {
            float ra[TM], rb[TN];
#pragma unroll
            for (int i = 0; i < TM; i++) ra[i] = As[kk][ty * TM + i];
#pragma unroll
            for (int j = 0; j < TN; j++) rb[j] = Bs[kk][tx * TN + j];
#pragma unroll
            for (int i = 0; i < TM; i++)
#pragma unroll
                for (int j = 0; j < TN; j++)
                    acc[i][j] = fmaf(ra[i], rb[j], acc[i][j]);
        }
        __syncthreads();
    }

#pragma unroll
    for (int i = 0; i < TM; i++)
#pragma unroll
        for (int j = 0; j < TN; j++) {
            int gm = row0 + ty * TM + i, gn = col0 + tx * TN + j;
            C[(size_t)gm * ldc + gn] = acc[i][j] + bias[gn];
        }
}

// ---------------- prep kernels ----------------
__device__ __forceinline__ void split_hilo(float v, __nv_bfloat16& h, __nv_bfloat16& l) {
    h = __float2bfloat16(v);
    l = __float2bfloat16(v - __bfloat162float(h));
}

__global__ void whcatT_hilo_kernel(const float* __restrict__ Wdec, const float* __restrict__ Whh,
                                   __nv_bfloat16* __restrict__ hi, __nv_bfloat16* __restrict__ lo)
{
    int idx = blockIdx.x * blockDim.x + threadIdx.x;
    if (idx >= HW * Dv) return;
    int k = idx & 511, n = idx >> 9;
    float v;
    if (n < 512) {
        v = Wdec[(size_t)k * Av + n];
    } else {
        int m = n - 512;
        int col_old = (m & 3) * 512 + (m >> 2);
        v = Whh[(size_t)k * G4D + col_old];
    }
    split_hilo(v, hi[idx], lo[idx]);
}

__global__ void wihcTi_kernel(const float* __restrict__ Wih,
                              __nv_bfloat16* __restrict__ hi, __nv_bfloat16* __restrict__ lo)
{
    int idx = blockIdx.x * blockDim.x + threadIdx.x;
    if (idx >= G4D * Dv) return;
    int k = idx & 511, n = idx >> 9;
    int col_old = (n & 3) * 512 + (n >> 2);
    float v = Wih[(size_t)(Ev + k) * G4D + col_old];
    split_hilo(v, hi[idx], lo[idx]);
}

__global__ void wihTi_kernel(const float* __restrict__ Wih,
                             __nv_bfloat16* __restrict__ hi, __nv_bfloat16* __restrict__ lo)
{
    int idx = blockIdx.x * blockDim.x + threadIdx.x;
    if (idx >= G4D * KE) return;
    int k = idx % KE, n = idx / KE;
    int col_old = (n & 3) * 512 + (n >> 2);
    float v = (k < Ev) ? Wih[(size_t)k * G4D + col_old] : 0.f;
    split_hilo(v, hi[idx], lo[idx]);
}

__global__ void biases_kernel(const float* __restrict__ bdec,
                              const float* __restrict__ bih, const float* __restrict__ bhh,
                              float* __restrict__ bh, float* __restrict__ b2i)
{
    int j = blockIdx.x * blockDim.x + threadIdx.x;
    if (j < HW) bh[j] = (j < 512) ? bdec[j] : 0.f;
    if (j < G4D) {
        int col_old = (j & 3) * 512 + (j >> 2);
        b2i[j] = bih[col_old] + bhh[col_old];
    }
}

__global__ void embgather_hilo_kernel(const float* __restrict__ emb, const int* __restrict__ cap,
                                      __nv_bfloat16* __restrict__ hi, __nv_bfloat16* __restrict__ lo)
{
    int idx = blockIdx.x * blockDim.x + threadIdx.x;
    if (idx >= Tv * Bv * KE) return;
    int k = idx % KE, r = idx / KE;
    int t = r / Bv, b = r % Bv;
    float v = 0.f;
    if (k < Ev) v = emb[(size_t)cap[b * Lv + t] * Ev + k];
    split_hilo(v, hi[idx], lo[idx]);
}

__global__ void conv_hilo_kernel(const float* __restrict__ in, size_t n,
                                 __nv_bfloat16* __restrict__ hi, __nv_bfloat16* __restrict__ lo)
{
    size_t idx = (size_t)blockIdx.x * blockDim.x + threadIdx.x;
    if (idx >= n) return;
    split_hilo(in[idx], hi[idx], lo[idx]);
}

__global__ void conv4_hilo_kernel(const float4* __restrict__ in, size_t n4,
                                  __nv_bfloat162* __restrict__ hi, __nv_bfloat162* __restrict__ lo)
{
    size_t idx = (size_t)blockIdx.x * blockDim.x + threadIdx.x;
    if (idx >= n4) return;
    float4 v = in[idx];
    __nv_bfloat16 h0, l0, h1, l1, h2, l2, h3, l3;
    split_hilo(v.x, h0, l0); split_hilo(v.y, h1, l1);
    split_hilo(v.z, h2, l2); split_hilo(v.w, h3, l3);
    hi[idx * 2]     = __nv_bfloat162(h0, h1);
    hi[idx * 2 + 1] = __nv_bfloat162(h2, h3);
    lo[idx * 2]     = __nv_bfloat162(l0, l1);
    lo[idx * 2 + 1] = __nv_bfloat162(l2, l3);
}

__global__ void trans_hilo_kernel(const float* __restrict__ in, int R, int C,
                                  __nv_bfloat16* __restrict__ hi, __nv_bfloat16* __restrict__ lo,
                                  int Kpad, int Npad)
{
    __shared__ float t[32][33];
    const int cb = blockIdx.x * 32;
    const int rb = blockIdx.y * 32;
    const int x = threadIdx.x, y = threadIdx.y;
#pragma unroll
    for (int i = y; i < 32; i += 8) {
        int r = rb + i, ccol = cb + x;
        t[i][x] = (r < R && ccol < C) ? in[(size_t)r * C + ccol] : 0.f;
    }
    __syncthreads();
#pragma unroll
    for (int i = y; i < 32; i += 8) {
        int n = cb + i, k = rb + x;
        if (n < Npad && k < Kpad) {
            size_t o = (size_t)n * Kpad + k;
            split_hilo(t[x][i], hi[o], lo[o]);
        }
    }
}

__global__ void meanf_kernel(const float* __restrict__ feat, float* __restrict__ mf)
{
    int b = blockIdx.x, tid = threadIdx.x;
    for (int d = tid; d < ENCv; d += 256) {
        float s = 0.f;
        const float* p = feat + (size_t)b * Nv * ENCv + d;
#pragma unroll 4
        for (int n = 0; n < Nv; n++) s += p[(size_t)n * ENCv];
        mf[b * ENCv + d] = s * (1.0f / (float)Nv);
    }
}

// ---------------- host helpers ----------------
static void launch_big(int M, int N, int Nreal, int K,
                       const __nv_bfloat16* Ahi, const __nv_bfloat16* Alo,
                       const __nv_bfloat16* Bhi, const __nv_bfloat16* Blo,
                       float* C, __half* Ch, int ldc, const float* bias, int remap)
{
    dim3 grid(N / 64, M / 128);
    hmma_big_kernel<<<grid, 256, BIG_SMEM>>>(Nreal, K, Ahi, Alo, Bhi, Blo,
                                             C, Ch, ldc, bias, remap);
}

extern "C" void kernel_launch(void* const* d_in, const int* in_sizes, int n_in,
                              void* d_out, int out_size)
{
    const float* features  = (const float*)d_in[0];
    const int*   captions  = (const int*)  d_in[1];
    const float* embedding = (const float*)d_in[2];
    const float* W_enc     = (const float*)d_in[3];
    const float* b_enc     = (const float*)d_in[4];
    const float* W_dec     = (const float*)d_in[5];
    const float* b_dec     = (const float*)d_in[6];
    const float* w_att     = (const float*)d_in[7];
    // d_in[8] = b_att : softmax-invariant, unused
    const float* Wi_h      = (const float*)d_in[9];
    const float* bi_h      = (const float*)d_in[10];
    const float* Wi_c      = (const float*)d_in[11];
    const float* bi_c      = (const float*)d_in[12];
    const float* W_ih      = (const float*)d_in[13];
    const float* b_ih      = (const float*)d_in[14];
    const float* W_hh      = (const float*)d_in[15];
    const float* b_hh      = (const float*)d_in[16];
    const float* W_out     = (const float*)d_in[17];
    const float* b_out     = (const float*)d_in[18];
    float* out = (float*)d_out;

    cudaFuncSetAttribute(hmma_big_kernel,  cudaFuncAttributeMaxDynamicSharedMemorySize, BIG_SMEM);
    cudaFuncSetAttribute(hproj_kernel,     cudaFuncAttributeMaxDynamicSharedMemorySize, BIG_SMEM);
    cudaFuncSetAttribute(att_hh_kernel,    cudaFuncAttributeMaxDynamicSharedMemorySize, BIG_SMEM);
    cudaFuncSetAttribute(gates_lstm_kernel, cudaFuncAttributeMaxDynamicSharedMemorySize, BIG_SMEM);

    float *embgates, *bh, *bias2i, *meanf, *h0, *c, *hproj;
    __half* featprojh;
    __nv_bfloat16 *fhi, *flo, *wenchi, *wenclo, *wihhi, *wihlo, *wihchi, *wihclo,
                  *whcthi, *whctlo, *wouthi, *woutlo, *eahi, *ealo,
                  *Hhi, *Hlo, *h0hi, *h0lo, *ctxhi, *ctxlo;
    cudaGetSymbolAddress((void**)&featprojh, g_featproj_h);
    cudaGetSymbolAddress((void**)&embgates, g_embgates);
    cudaGetSymbolAddress((void**)&bh,       g_bh);
    cudaGetSymbolAddress((void**)&bias2i,   g_bias2i);
    cudaGetSymbolAddress((void**)&meanf,    g_meanf);
    cudaGetSymbolAddress((void**)&h0,       g_h0);
    cudaGetSymbolAddress((void**)&c,        g_c);
    cudaGetSymbolAddress((void**)&hproj,    g_hproj);
    cudaGetSymbolAddress((void**)&fhi,      g_feat_hi);
    cudaGetSymbolAddress((void**)&flo,      g_feat_lo);
    cudaGetSymbolAddress((void**)&wenchi,   g_WencT_hi);
    cudaGetSymbolAddress((void**)&wenclo,   g_WencT_lo);
    cudaGetSymbolAddress((void**)&wihhi,    g_WihTi_hi);
    cudaGetSymbolAddress((void**)&wihlo,    g_WihTi_lo);
    cudaGetSymbolAddress((void**)&wihchi,   g_WihcTi_hi);
    cudaGetSymbolAddress((void**)&wihclo,   g_WihcTi_lo);
    cudaGetSymbolAddress((void**)&whcthi,   g_whcatT_hi);
    cudaGetSymbolAddress((void**)&whctlo,   g_whcatT_lo);
    cudaGetSymbolAddress((void**)&wouthi,   g_WoutT_hi);
    cudaGetSymbolAddress((void**)&woutlo,   g_WoutT_lo);
    cudaGetSymbolAddress((void**)&eahi,     g_embA_hi);
    cudaGetSymbolAddress((void**)&ealo,     g_embA_lo);
    cudaGetSymbolAddress((void**)&Hhi,      g_H_hi);
    cudaGetSymbolAddress((void**)&Hlo,      g_H_lo);
    cudaGetSymbolAddress((void**)&h0hi,     g_h0_hi);
    cudaGetSymbolAddress((void**)&h0lo,     g_h0_lo);
    cudaGetSymbolAddress((void**)&ctxhi,    g_ctx_hi);
    cudaGetSymbolAddress((void**)&ctxlo,    g_ctx_lo);

    dim3 tthr(32, 8);

    // ---- prep, featproj big GEMM stays at launch #4 (ncu slot) ----
    {
        size_t n4 = (size_t)Bv * Nv * ENCv / 4;
        conv4_hilo_kernel<<<(unsigned)((n4 + 255) / 256), 256>>>(
            (const float4*)features, n4, (__nv_bfloat162*)fhi, (__nv_bfloat162*)flo);     // 1
    }
    trans_hilo_kernel<<<dim3(16, 16), tthr>>>(W_enc, ENCv, Av, wenchi, wenclo, ENCv, Av); // 2
    whcatT_hilo_kernel<<<(HW * Dv + 255) / 256, 256>>>(W_dec, W_hh, whcthi, whctlo);      // 3
    launch_big(Bv * Nv, Av, Av, ENCv, fhi, flo, wenchi, wenclo,
               nullptr, featprojh, Av, b_enc, 0);                                         // 4
    biases_kernel<<<(HW + 255) / 256, 256>>>(b_dec, b_ih, b_hh, bh, bias2i);              // 5
    embgather_hilo_kernel<<<(Tv * Bv * KE + 255) / 256, 256>>>(embedding, captions,
                                                               eahi, ealo);               // 6
    wihTi_kernel<<<(G4D * KE + 255) / 256, 256>>>(W_ih, wihhi, wihlo);                    // 7
    launch_big(Tv * Bv, G4D, G4D, KE, eahi, ealo, wihhi, wihlo,
               embgates, nullptr, G4D, bias2i, 0);                                        // 8
    wihcTi_kernel<<<(G4D * Dv + 255) / 256, 256>>>(W_ih, wihchi, wihclo);                 // 9
    trans_hilo_kernel<<<dim3((VP + 31) / 32, (Dv + 31) / 32), tthr>>>(
        W_out, Dv, Vv, wouthi, woutlo, Dv, VP);                                           // 10
    meanf_kernel<<<Bv, 256>>>(features, meanf);                                           // 11
    {
        dim3 g(Dv / 64, Bv / 32);
        sgemm_kernel<32, 64, 16, 2, 4><<<g, 256>>>(Bv, Dv, ENCv, meanf, ENCv,
                                                   Wi_h, Dv, h0, Dv, bi_h);               // 12
        sgemm_kernel<32, 64, 16, 2, 4><<<g, 256>>>(Bv, Dv, ENCv, meanf, ENCv,
                                                   Wi_c, Dv, c, Dv, bi_c);                // 13
    }
    conv_hilo_kernel<<<(Bv * Dv + 255) / 256, 256>>>(h0, (size_t)Bv * Dv, h0hi, h0lo);    // 14

    const size_t PRED = (size_t)Bv * Tv * Vv;

    for (int t = 0; t < Tv; t++) {
        const __nv_bfloat16* hpHi = (t == 0) ? h0hi : (Hhi + (size_t)(t - 1) * Bv * Dv);
        const __nv_bfloat16* hpLo = (t == 0) ? h0lo : (Hlo + (size_t)(t - 1) * Bv * Dv);
        // stage 1: dec = h @ W_dec + b_dec (cols 0..511 of hproj)
        hproj_kernel<<<8, 256, BIG_SMEM>>>(hpHi, hpLo, whcthi, whctlo, hproj, bh);
        // stage 2: attention (CTAs 0..127) || hproj W_hh part (CTAs 128..159)
        att_hh_kernel<<<160, 256, BIG_SMEM>>>(
            (const __half2*)featprojh, features, hproj, w_att,
            hpHi, hpLo, whcthi, whctlo, bh,
            ctxhi, ctxlo, out + PRED + (size_t)t * Nv);
        // stage 3: gates + fused LSTM -> c, Hhi/Hlo[t]
        gates_lstm_kernel<<<G4D / 64, 256, BIG_SMEM>>>(
            ctxhi, ctxlo, wihchi, wihclo,
            embgates + (size_t)t * Bv * G4D, hproj, c,
            Hhi + (size_t)t * Bv * Dv, Hlo + (size_t)t * Bv * Dv);
    }

    // preds: [T*B, V] = H @ W_out^T + b_out, remapped to [B, T, V]
    launch_big(Tv * Bv, VP, Vv, Dv, Hhi, Hlo, wouthi, woutlo,
               out, nullptr, Vv, b_out, 1);
}

// round 16
// speedup vs baseline: 1.4211x; 1.0234x over previous
#include <cuda_runtime.h>
#include <cuda_bf16.h>
#include <cuda_fp16.h>
#include <cstdint>
#include <cstddef>

// ---------------- problem constants ----------------
#define Bv   128
#define Nv   196
#define Lv   25
#define Tv   24
#define Vv   10000
#define Ev   300
#define Av   512
#define ENCv 512
#define Dv   512
#define G4D  2048   // 4*D
#define HW   2560   // cols of [W_dec | W_hh_interleaved]
#define KE   320    // E padded (multiple of 32)
#define VP   10112  // V padded (multiple of 64)

// ---------------- device scratch (static, no allocation) ----------------
__device__ __half g_featproj_h[(size_t)Bv * Nv * Av];   // f16 featproj
__device__ float g_embgates[(size_t)Tv * Bv * G4D];     // interleaved-gate layout
__device__ float g_bh[HW];
__device__ float g_bias2i[G4D];
__device__ float g_meanf[Bv * ENCv];
__device__ float g_h0[Bv * Dv];
__device__ float g_c[Bv * Dv];
__device__ float g_hproj[Bv * HW];

__device__ __nv_bfloat16 g_feat_hi[(size_t)Bv * Nv * ENCv];
__device__ __nv_bfloat16 g_feat_lo[(size_t)Bv * Nv * ENCv];
__device__ __nv_bfloat16 g_WencT_hi[Av * ENCv];
__device__ __nv_bfloat16 g_WencT_lo[Av * ENCv];
__device__ __nv_bfloat16 g_WihTi_hi[G4D * KE];
__device__ __nv_bfloat16 g_WihTi_lo[G4D * KE];
__device__ __nv_bfloat16 g_WihcTi_hi[G4D * Dv];
__device__ __nv_bfloat16 g_WihcTi_lo[G4D * Dv];
__device__ __nv_bfloat16 g_whcatT_hi[HW * Dv];
__device__ __nv_bfloat16 g_whcatT_lo[HW * Dv];
__device__ __nv_bfloat16 g_WoutT_hi[(size_t)VP * Dv];
__device__ __nv_bfloat16 g_WoutT_lo[(size_t)VP * Dv];
__device__ __nv_bfloat16 g_embA_hi[Tv * Bv * KE];
__device__ __nv_bfloat16 g_embA_lo[Tv * Bv * KE];
__device__ __nv_bfloat16 g_H_hi[(size_t)Tv * Bv * Dv];
__device__ __nv_bfloat16 g_H_lo[(size_t)Tv * Bv * Dv];
__device__ __nv_bfloat16 g_h0_hi[Bv * Dv];
__device__ __nv_bfloat16 g_h0_lo[Bv * Dv];
__device__ __nv_bfloat16 g_ctx_hi[Bv * Dv];
__device__ __nv_bfloat16 g_ctx_lo[Bv * Dv];

// ---------------- PTX helpers ----------------
__device__ __forceinline__ uint32_t smem_u32(const void* p) {
    uint32_t a;
    asm("{ .reg .u64 t; cvta.to.shared.u64 t, %1; cvt.u32.u64 %0, t; }" : "=r"(a) : "l"(p));
    return a;
}

#define LDSM4(r, addr) \
    asm volatile("ldmatrix.sync.aligned.m8n8.x4.shared.b16 {%0,%1,%2,%3}, [%4];" \
        : "=r"((r)[0]), "=r"((r)[1]), "=r"((r)[2]), "=r"((r)[3]) : "r"(addr))

#define MMA16816(d, a, b0, b1) \
    asm volatile("mma.sync.aligned.m16n8k16.row.col.f32.bf16.bf16.f32 " \
        "{%0,%1,%2,%3}, {%4,%5,%6,%7}, {%8,%9}, {%0,%1,%2,%3};" \
        : "+f"((d)[0]), "+f"((d)[1]), "+f"((d)[2]), "+f"((d)[3]) \
        : "r"((a)[0]), "r"((a)[1]), "r"((a)[2]), "r"((a)[3]), "r"(b0), "r"(b1))

#define CP16(dst, src) \
    asm volatile("cp.async.cg.shared.global [%0], [%1], 16;" :: "r"(dst), "l"(src) : "memory")
#define CP_COMMIT() asm volatile("cp.async.commit_group;" ::: "memory")
#define CP_WAIT1() asm volatile("cp.async.wait_group 1;" ::: "memory")
#define CP_WAIT0() asm volatile("cp.async.wait_group 0;" ::: "memory")

// =================================================================
// Shared pipelined HMMA mainloop: CTA 128x64, 4M x 2N warps, BK=32,
// 2-stage cp.async, smem row stride 80 B. lda == ldb == K assumed.
// =================================================================
#define SS       30720
#define POFF_AHI 0
#define POFF_ALO 10240
#define POFF_BHI 20480
#define POFF_BLO 25600
#define BIG_SMEM (2 * SS)   // 61440

__device__ __forceinline__ void big_load_stage(
    uint32_t base,
    const __nv_bfloat16* __restrict__ Ahi, const __nv_bfloat16* __restrict__ Alo,
    const __nv_bfloat16* __restrict__ Bhi, const __nv_bfloat16* __restrict__ Blo,
    int lda, int row0, int col0, int koff, int tid)
{
#pragma unroll
    for (int i = 0; i < 2; i++) {
        const int idx = tid + i * 256;
        const int r = idx >> 2, seg = idx & 3;
        const uint32_t d = base + (uint32_t)(r * 80 + seg * 16);
        const size_t g = (size_t)(row0 + r) * lda + koff + seg * 8;
        CP16(d + POFF_AHI, Ahi + g);
        CP16(d + POFF_ALO, Alo + g);
    }
    {
        const int r = tid >> 2, seg = tid & 3;
        const uint32_t d = base + (uint32_t)(r * 80 + seg * 16);
        const size_t g = (size_t)(col0 + r) * lda + koff + seg * 8;
        CP16(d + POFF_BHI, Bhi + g);
        CP16(d + POFF_BLO, Blo + g);
    }
}

__device__ __forceinline__ void pipe_mainloop(
    uint32_t sb,
    const __nv_bfloat16* __restrict__ Ahi, const __nv_bfloat16* __restrict__ Alo,
    const __nv_bfloat16* __restrict__ Bhi, const __nv_bfloat16* __restrict__ Blo,
    int K, int row0, int col0, int tid, int warp_m, int warp_n, int lane,
    float acc[2][4][4])
{
    const int a_lr = lane & 15, a_lk = (lane >> 4) * 8;
    const int b_grp = lane >> 3;
    const int b_lr = (lane & 7) + ((b_grp >> 1) * 8);
    const int b_lk = (b_grp & 1) * 8;

    const int nch = K >> 5;
    big_load_stage(sb, Ahi, Alo, Bhi, Blo, K, row0, col0, 0, tid);
    CP_COMMIT();
    for (int kc = 0; kc < nch; kc++) {
        if (kc + 1 < nch) {
            big_load_stage(sb + (uint32_t)(((kc + 1) & 1) * SS),
                           Ahi, Alo, Bhi, Blo, K, row0, col0, (kc + 1) * 32, tid);
            CP_COMMIT();
            CP_WAIT1();
        } else {
            CP_WAIT0();
        }
        __syncthreads();
        const uint32_t st = sb + (uint32_t)((kc & 1) * SS);
#pragma unroll
        for (int k16 = 0; k16 < 32; k16 += 16) {
            uint32_t aHi[2][4], aLo[2][4], bH[8], bL[8];
#pragma unroll
            for (int mt = 0; mt < 2; mt++) {
                const uint32_t ab = st + (uint32_t)((warp_m * 32 + mt * 16 + a_lr) * 80
                                                    + (k16 + a_lk) * 2);
                LDSM4(aHi[mt], ab + POFF_AHI);
                LDSM4(aLo[mt], ab + POFF_ALO);
            }
#pragma unroll
            for (int half = 0; half < 2; half++) {
                const uint32_t bb = st + (uint32_t)((warp_n * 32 + half * 16 + b_lr) * 80
                                                    + (k16 + b_lk) * 2);
                LDSM4(bH + half * 4, bb + POFF_BHI);
                LDSM4(bL + half * 4, bb + POFF_BLO);
            }
#pragma unroll
            for (int mt = 0; mt < 2; mt++)
#pragma unroll
                for (int nt = 0; nt < 4; nt++) {
                    MMA16816(acc[mt][nt], aHi[mt], bH[nt * 2], bH[nt * 2 + 1]);
                    MMA16816(acc[mt][nt], aLo[mt], bH[nt * 2], bH[nt * 2 + 1]);
                    MMA16816(acc[mt][nt], aHi[mt], bL[nt * 2], bL[nt * 2 + 1]);
                }
        }
        __syncthreads();
    }
}

// =================================================================
// BIG HMMA GEMM (featproj / embgates / logits). remap row: b*Tv + t + tbase.
// =================================================================
__global__ __launch_bounds__(256, 2)
void hmma_big_kernel(int Nreal, int K,
                     const __nv_bfloat16* __restrict__ Ahi, const __nv_bfloat16* __restrict__ Alo,
                     const __nv_bfloat16* __restrict__ Bhi, const __nv_bfloat16* __restrict__ Blo,
                     float* __restrict__ C, __half* __restrict__ Ch, int ldc,
                     const float* __restrict__ bias, int remap, int tbase)
{
    extern __shared__ char sm[];
    const uint32_t sb = smem_u32(sm);
    const int tid = threadIdx.x;
    const int wid = tid >> 5, lane = tid & 31;
    const int warp_m = wid & 3;
    const int warp_n = wid >> 2;
    const int row0 = blockIdx.y * 128;
    const int col0 = blockIdx.x * 64;

    float acc[2][4][4];
#pragma unroll
    for (int mt = 0; mt < 2; mt++)
#pragma unroll
        for (int nt = 0; nt < 4; nt++)
#pragma unroll
            for (int r = 0; r < 4; r++) acc[mt][nt][r] = 0.f;

    pipe_mainloop(sb, Ahi, Alo, Bhi, Blo, K, row0, col0, tid, warp_m, warp_n, lane, acc);

    const int quad = lane >> 2, tc = lane & 3;
#pragma unroll
    for (int mt = 0; mt < 2; mt++)
#pragma unroll
        for (int half = 0; half < 2; half++) {
            const int gm = row0 + warp_m * 32 + mt * 16 + quad + half * 8;
            const size_t rowC = remap ? ((size_t)(gm & (Bv - 1)) * Tv + (gm >> 7) + tbase)
                                      : (size_t)gm;
#pragma unroll
            for (int nt = 0; nt < 4; nt++) {
                const int gn = col0 + warp_n * 32 + nt * 8 + tc * 2;
                if (gn >= Nreal) continue;
                const float2 bv = *(const float2*)&bias[gn];
                const float v0 = acc[mt][nt][half * 2]     + bv.x;
                const float v1 = acc[mt][nt][half * 2 + 1] + bv.y;
                if (Ch) {
                    *(__half2*)&Ch[rowC * (size_t)ldc + gn] = __floats2half2_rn(v0, v1);
                } else {
                    float2 o; o.x = v0; o.y = v1;
                    *(float2*)&C[rowC * (size_t)ldc + gn] = o;
                }
            }
        }
}

// =================================================================
// hproj partial GEMM: cols [0, grid*64) of hproj (dec part, grid=8).
// =================================================================
__global__ __launch_bounds__(256, 2)
void hproj_kernel(const __nv_bfloat16* __restrict__ Ahi, const __nv_bfloat16* __restrict__ Alo,
                  const __nv_bfloat16* __restrict__ Bhi, const __nv_bfloat16* __restrict__ Blo,
                  float* __restrict__ C, const float* __restrict__ bias)
{
    extern __shared__ char sm[];
    const uint32_t sb = smem_u32(sm);
    const int tid = threadIdx.x;
    const int wid = tid >> 5, lane = tid & 31;
    const int warp_m = wid & 3;
    const int warp_n = wid >> 2;
    const int col0 = blockIdx.x * 64;

    float acc[2][4][4];
#pragma unroll
    for (int mt = 0; mt < 2; mt++)
#pragma unroll
        for (int nt = 0; nt < 4; nt++)
#pragma unroll
            for (int r = 0; r < 4; r++) acc[mt][nt][r] = 0.f;

    pipe_mainloop(sb, Ahi, Alo, Bhi, Blo, Dv, 0, col0, tid, warp_m, warp_n, lane, acc);

    const int quad = lane >> 2, tc = lane & 3;
#pragma unroll
    for (int mt = 0; mt < 2; mt++)
#pragma unroll
        for (int half = 0; half < 2; half++) {
            const int gm = warp_m * 32 + mt * 16 + quad + half * 8;
#pragma unroll
            for (int nt = 0; nt < 4; nt++) {
                const int gn = col0 + warp_n * 32 + nt * 8 + tc * 2;
                const float2 bv = *(const float2*)&bias[gn];
                float2 o;
                o.x = acc[mt][nt][half * 2]     + bv.x;
                o.y = acc[mt][nt][half * 2 + 1] + bv.y;
                *(float2*)&C[(size_t)gm * HW + gn] = o;
            }
        }
}

// =================================================================
// Fused stage 2 (318 CTAs):
//   0..127   attention
//   128..159 hproj W_hh-part GEMM
//   160..317 logits tile for step tprev (skipped when tprev < 0)
// Note: hpHi/hpLo (= h_{t-1}) double as the logits A operand.
// =================================================================
__global__ __launch_bounds__(256, 2)
void att_hh_kernel(const __half2* __restrict__ fp_h,
                   const float* __restrict__ feat,
                   float* hproj,
                   const float* __restrict__ watt,
                   const __nv_bfloat16* __restrict__ hpHi, const __nv_bfloat16* __restrict__ hpLo,
                   const __nv_bfloat16* __restrict__ wHi, const __nv_bfloat16* __restrict__ wLo,
                   const __nv_bfloat16* __restrict__ woutHi, const __nv_bfloat16* __restrict__ woutLo,
                   const float* __restrict__ bout,
                   float* __restrict__ outBase,
                   int tprev,
                   __nv_bfloat16* __restrict__ ctxHi, __nv_bfloat16* __restrict__ ctxLo,
                   float* __restrict__ alphaOut)
{
    extern __shared__ char sm[];
    const int tid = threadIdx.x;

    if (blockIdx.x >= 160) {
        // ---- logits tile for step tprev: preds[:, tprev, :] ----
        if (tprev < 0) return;
        const uint32_t sb = smem_u32(sm);
        const int wid = tid >> 5, lane = tid & 31;
        const int warp_m = wid & 3;
        const int warp_n = wid >> 2;
        const int col0 = (blockIdx.x - 160) * 64;

        float acc[2][4][4];
#pragma unroll
        for (int mt = 0; mt < 2; mt++)
#pragma unroll
            for (int nt = 0; nt < 4; nt++)
#pragma unroll
                for (int r = 0; r < 4; r++) acc[mt][nt][r] = 0.f;

        pipe_mainloop(sb, hpHi, hpLo, woutHi, woutLo, Dv, 0, col0,
                      tid, warp_m, warp_n, lane, acc);

        const int quad = lane >> 2, tc = lane & 3;
#pragma unroll
        for (int mt = 0; mt < 2; mt++)
#pragma unroll
            for (int half = 0; half < 2; half++) {
                const int gm = warp_m * 32 + mt * 16 + quad + half * 8;  // = b
                const size_t rowC = (size_t)gm * Tv + tprev;
#pragma unroll
                for (int nt = 0; nt < 4; nt++) {
                    const int gn = col0 + warp_n * 32 + nt * 8 + tc * 2;
                    if (gn >= Vv) continue;
                    const float2 bv = *(const float2*)&bout[gn];
                    float2 o;
                    o.x = acc[mt][nt][half * 2]     + bv.x;
                    o.y = acc[mt][nt][half * 2 + 1] + bv.y;
                    *(float2*)&outBase[rowC * Vv + gn] = o;
                }
            }
        return;
    }

    if (blockIdx.x >= 128) {
        // ---- hproj W_hh part: cols 512 + (bid-128)*64 ----
        const uint32_t sb = smem_u32(sm);
        const int wid = tid >> 5, lane = tid & 31;
        const int warp_m = wid & 3;
        const int warp_n = wid >> 2;
        const int col0 = 512 + (blockIdx.x - 128) * 64;

        float acc[2][4][4];
#pragma unroll
        for (int mt = 0; mt < 2; mt++)
#pragma unroll
            for (int nt = 0; nt < 4; nt++)
#pragma unroll
                for (int r = 0; r < 4; r++) acc[mt][nt][r] = 0.f;

        pipe_mainloop(sb, hpHi, hpLo, wHi, wLo, Dv, 0, col0, tid, warp_m, warp_n, lane, acc);

        const int quad = lane >> 2, tc = lane & 3;
#pragma unroll
        for (int mt = 0; mt < 2; mt++)
#pragma unroll
            for (int half = 0; half < 2; half++) {
                const int gm = warp_m * 32 + mt * 16 + quad + half * 8;
#pragma unroll
                for (int nt = 0; nt < 4; nt++) {
                    const int gn = col0 + warp_n * 32 + nt * 8 + tc * 2;
                    float2 o;
                    o.x = acc[mt][nt][half * 2];
                    o.y = acc[mt][nt][half * 2 + 1];
                    *(float2*)&hproj[(size_t)gm * HW + gn] = o;
                }
            }
        return;
    }

    // ---- attention for batch row b ----
    __shared__ __half2 s_dech[256];
    __shared__ __half2 s_wh[256];
    __shared__ float s_sc[Nv];
    __shared__ float s_red[8];
    const int b = blockIdx.x;

    {
        const float2 dv = ((const float2*)(hproj + (size_t)b * HW))[tid];
        s_dech[tid] = __floats2half2_rn(dv.x, dv.y);
        const float2 wv = ((const float2*)watt)[tid];
        s_wh[tid] = __floats2half2_rn(wv.x, wv.y);
    }
    __syncthreads();

    const int warp = tid >> 5, lane = tid & 31;
    __half2 rd[8], rw[8];
#pragma unroll
    for (int j = 0; j < 8; j++) {
        rd[j] = s_dech[lane * 8 + j];
        rw[j] = s_wh[lane * 8 + j];
    }

    for (int n = warp; n < Nv; n += 8) {
        const uint4* r4 = reinterpret_cast<const uint4*>(fp_h + (size_t)(b * Nv + n) * 256)
                          + lane * 2;
        const uint4 q0 = r4[0];
        const uint4 q1 = r4[1];
        uint32_t qa[8];
        qa[0] = q0.x; qa[1] = q0.y; qa[2] = q0.z; qa[3] = q0.w;
        qa[4] = q1.x; qa[5] = q1.y; qa[6] = q1.z; qa[7] = q1.w;
        __half2 acc2 = __floats2half2_rn(0.f, 0.f);
#pragma unroll
        for (int j = 0; j < 8; j++) {
            __half2 x = __hadd2(*(__half2*)&qa[j], rd[j]);
            uint32_t th;
            asm("tanh.approx.f16x2 %0, %1;" : "=r"(th) : "r"(*(uint32_t*)&x));
            acc2 = __hfma2(*(__half2*)&th, rw[j], acc2);
        }
        float s = __low2float(acc2) + __high2float(acc2);
#pragma unroll
        for (int o = 16; o; o >>= 1) s += __shfl_xor_sync(0xffffffffu, s, o);
        if (lane == 0) s_sc[n] = s;
    }
    __syncthreads();

    float m = -1e30f;
    for (int n = tid; n < Nv; n += 256) m = fmaxf(m, s_sc[n]);
#pragma unroll
    for (int o = 16; o; o >>= 1) m = fmaxf(m, __shfl_xor_sync(0xffffffffu, m, o));
    if (lane == 0) s_red[warp] = m;
    __syncthreads();
    if (tid == 0) {
        float mm = s_red[0];
        for (int w = 1; w < 8; w++) mm = fmaxf(mm, s_red[w]);
        s_red[0] = mm;
    }
    __syncthreads();
    m = s_red[0];
    __syncthreads();

    float sum = 0.f;
    for (int n = tid; n < Nv; n += 256) {
        float e = __expf(s_sc[n] - m);
        s_sc[n] = e;
        sum += e;
    }
#pragma unroll
    for (int o = 16; o; o >>= 1) sum += __shfl_xor_sync(0xffffffffu, sum, o);
    if (lane == 0) s_red[warp] = sum;
    __syncthreads();
    if (tid == 0) {
        float ss = 0.f;
        for (int w = 0; w < 8; w++) ss += s_red[w];
        s_red[0] = 1.f / ss;
    }
    __syncthreads();
    const float inv = s_red[0];
    for (int n = tid; n < Nv; n += 256) {
        float a = s_sc[n] * inv;
        s_sc[n] = a;
        alphaOut[(size_t)b * Tv * Nv + n] = a;
    }
    __syncthreads();

    const float* fb = feat + (size_t)b * Nv * ENCv;
    for (int d = tid; d < ENCv; d += 256) {
        float acc = 0.f;
#pragma unroll 4
        for (int n = 0; n < Nv; n++) acc = fmaf(s_sc[n], fb[(size_t)n * ENCv + d], acc);
        const __nv_bfloat16 hh = __float2bfloat16(acc);
        ctxHi[b * ENCv + d] = hh;
        ctxLo[b * ENCv + d] = __float2bfloat16(acc - __bfloat162float(hh));
    }
}

// =================================================================
// Gates GEMM + fused LSTM epilogue.
// =================================================================
__global__ __launch_bounds__(256, 2)
void gates_lstm_kernel(const __nv_bfloat16* __restrict__ ctxHi, const __nv_bfloat16* __restrict__ ctxLo,
                       const __nv_bfloat16* __restrict__ wHi, const __nv_bfloat16* __restrict__ wLo,
                       const float* __restrict__ egt,
                       const float* __restrict__ hproj,
                       float* __restrict__ c,
                       __nv_bfloat16* __restrict__ HtHi, __nv_bfloat16* __restrict__ HtLo)
{
    extern __shared__ char sm[];
    const uint32_t sb = smem_u32(sm);
    const int tid = threadIdx.x;
    const int wid = tid >> 5, lane = tid & 31;
    const int warp_m = wid & 3;
    const int warp_n = wid >> 2;
    const int col0 = blockIdx.x * 64;

    float acc[2][4][4];
#pragma unroll
    for (int mt = 0; mt < 2; mt++)
#pragma unroll
        for (int nt = 0; nt < 4; nt++)
#pragma unroll
            for (int r = 0; r < 4; r++) acc[mt][nt][r] = 0.f;

    pipe_mainloop(sb, ctxHi, ctxLo, wHi, wLo, Dv, 0, col0, tid, warp_m, warp_n, lane, acc);

    float* gs = (float*)sm;
    const int quad = lane >> 2, tc = lane & 3;
#pragma unroll
    for (int mt = 0; mt < 2; mt++)
#pragma unroll
        for (int half = 0; half < 2; half++) {
            const int gm = warp_m * 32 + mt * 16 + quad + half * 8;
#pragma unroll
            for (int nt = 0; nt < 4; nt++) {
                const int gn = warp_n * 32 + nt * 8 + tc * 2;
                const float2 e = *(const float2*)&egt[(size_t)gm * G4D + col0 + gn];
                const float2 hp = *(const float2*)&hproj[(size_t)gm * HW + 512 + col0 + gn];
                gs[gm * 68 + gn]     = acc[mt][nt][half * 2]     + e.x + hp.x;
                gs[gm * 68 + gn + 1] = acc[mt][nt][half * 2 + 1] + e.y + hp.y;
            }
        }
    __syncthreads();

    const int d0 = col0 >> 2;
#pragma unroll
    for (int i = tid; i < 2048; i += 256) {
        const int b = i >> 4, u = i & 15;
        const float* gr = gs + b * 68 + u * 4;
        const float gi = gr[0], gf = gr[1], gg = gr[2], go = gr[3];
        const int d = d0 + u;
        const float si = 1.f / (1.f + __expf(-gi));
        const float sf = 1.f / (1.f + __expf(-gf));
        const float so = 1.f / (1.f + __expf(-go));
        const float tg = tanhf(gg);
        const float cn = sf * c[b * Dv + d] + si * tg;
        c[b * Dv + d] = cn;
        const float h = so * tanhf(cn);
        const __nv_bfloat16 hh = __float2bfloat16(h);
        HtHi[b * Dv + d] = hh;
        HtLo[b * Dv + d] = __float2bfloat16(h - __bfloat162float(hh));
    }
}

// =================================================================
// Small fp32 SGEMM (one-time h0/c0 init only)
// =================================================================
template<int BM, int BN, int BK, int TM, int TN>
__global__ void sgemm_kernel(int M, int N, int K,
                             const float* __restrict__ A, int lda,
                             const float* __restrict__ B, int ldb,
                             float* __restrict__ C, int ldc,
                             const float* __restrict__ bias)
{
    constexpr int TX = BN / TN;
    constexpr int TY = BM / TM;
    constexpr int NT = TX * TY;
    __shared__ float As[BK][BM + 1];
    __shared__ float Bs[BK][BN];

    const int tid = threadIdx.x;
    const int tx = tid % TX, ty = tid / TX;
    const int row0 = blockIdx.y * BM;
    const int col0 = blockIdx.x * BN;

    float acc[TM][TN];
#pragma unroll
    for (int i = 0; i < TM; i++)
#pragma unroll
        for (int j = 0; j < TN; j++) acc[i][j] = 0.f;

    for (int k0 = 0; k0 < K; k0 += BK) {
#pragma unroll
        for (int i = tid; i < BM * BK; i += NT) {
            int m = i / BK, k = i % BK;
            As[k][m] = A[(size_t)(row0 + m) * lda + k0 + k];
        }
#pragma unroll
        for (int i = tid; i < BK * BN; i += NT) {
            int k = i / BN, n = i % BN;
            Bs[k][n] = B[(size_t)(k0 + k) * ldb + col0 + n];
        }
        __syncthreads();
#pragma unroll
        for (int kk = 0; kk < BK; kk++) {
            float ra[TM], rb[TN];
#pragma unroll
            for (int i = 0; i < TM; i++) ra[i] = As[kk][ty * TM + i];
#pragma unroll
            for (int j = 0; j < TN; j++) rb[j] = Bs[kk][tx * TN + j];
#pragma unroll
            for (int i = 0; i < TM; i++)
#pragma unroll
                for (int j = 0; j < TN; j++)
                    acc[i][j] = fmaf(ra[i], rb[j], acc[i][j]);
        }
        __syncthreads();
    }

#pragma unroll
    for (int i = 0; i < TM; i++)
#pragma unroll
        for (int j = 0; j < TN; j++) {
            int gm = row0 + ty * TM + i, gn = col0 + tx * TN + j;
            C[(size_t)gm * ldc + gn] = acc[i][j] + bias[gn];
        }
}

// ---------------- prep kernels ----------------
__device__ __forceinline__ void split_hilo(float v, __nv_bfloat16& h, __nv_bfloat16& l) {
    h = __float2bfloat16(v);
    l = __float2bfloat16(v - __bfloat162float(h));
}

__global__ void whcatT_hilo_kernel(const float* __restrict__ Wdec, const float* __restrict__ Whh,
                                   __nv_bfloat16* __restrict__ hi, __nv_bfloat16* __restrict__ lo)
{
    int idx = blockIdx.x * blockDim.x + threadIdx.x;
    if (idx >= HW * Dv) return;
    int k = idx & 511, n = idx >> 9;
    float v;
    if (n < 512) {
        v = Wdec[(size_t)k * Av + n];
    } else {
        int m = n - 512;
        int col_old = (m & 3) * 512 + (m >> 2);
        v = Whh[(size_t)k * G4D + col_old];
    }
    split_hilo(v, hi[idx], lo[idx]);
}

__global__ void wihcTi_kernel(const float* __restrict__ Wih,
                              __nv_bfloat16* __restrict__ hi, __nv_bfloat16* __restrict__ lo)
{
    int idx = blockIdx.x * blockDim.x + threadIdx.x;
    if (idx >= G4D * Dv) return;
    int k = idx & 511, n = idx >> 9;
    int col_old = (n & 3) * 512 + (n >> 2);
    float v = Wih[(size_t)(Ev + k) * G4D + col_old];
    split_hilo(v, hi[idx], lo[idx]);
}

__global__ void wihTi_kernel(const float* __restrict__ Wih,
                             __nv_bfloat16* __restrict__ hi, __nv_bfloat16* __restrict__ lo)
{
    int idx = blockIdx.x * blockDim.x + threadIdx.x;
    if (idx >= G4D * KE) return;
    int k = idx % KE, n = idx / KE;
    int col_old = (n & 3) * 512 + (n >> 2);
    float v = (k < Ev) ? Wih[(size_t)k * G4D + col_old] : 0.f;
    split_hilo(v, hi[idx], lo[idx]);
}

__global__ void biases_kernel(const float* __restrict__ bdec,
                              const float* __restrict__ bih, const float* __restrict__ bhh,
                              float* __restrict__ bh, float* __restrict__ b2i)
{
    int j = blockIdx.x * blockDim.x + threadIdx.x;
    if (j < HW) bh[j] = (j < 512) ? bdec[j] : 0.f;
    if (j < G4D) {
        int col_old = (j & 3) * 512 + (j >> 2);
        b2i[j] = bih[col_old] + bhh[col_old];
    }
}

__global__ void embgather_hilo_kernel(const float* __restrict__ emb, const int* __restrict__ cap,
                                      __nv_bfloat16* __restrict__ hi, __nv_bfloat16* __restrict__ lo)
{
    int idx = blockIdx.x * blockDim.x + threadIdx.x;
    if (idx >= Tv * Bv * KE) return;
    int k = idx % KE, r = idx / KE;
    int t = r / Bv, b = r % Bv;
    float v = 0.f;
    if (k < Ev) v = emb[(size_t)cap[b * Lv + t] * Ev + k];
    split_hilo(v, hi[idx], lo[idx]);
}

__global__ void conv_hilo_kernel(const float* __restrict__ in, size_t n,
                                 __nv_bfloat16* __restrict__ hi, __nv_bfloat16* __restrict__ lo)
{
    size_t idx = (size_t)blockIdx.x * blockDim.x + threadIdx.x;
    if (idx >= n) return;
    split_hilo(in[idx], hi[idx], lo[idx]);
}

__global__ void conv4_hilo_kernel(const float4* __restrict__ in, size_t n4,
                                  __nv_bfloat162* __restrict__ hi, __nv_bfloat162* __restrict__ lo)
{
    size_t idx = (size_t)blockIdx.x * blockDim.x + threadIdx.x;
    if (idx >= n4) return;
    float4 v = in[idx];
    __nv_bfloat16 h0, l0, h1, l1, h2, l2, h3, l3;
    split_hilo(v.x, h0, l0); split_hilo(v.y, h1, l1);
    split_hilo(v.z, h2, l2); split_hilo(v.w, h3, l3);
    hi[idx * 2]     = __nv_bfloat162(h0, h1);
    hi[idx * 2 + 1] = __nv_bfloat162(h2, h3);
    lo[idx * 2]     = __nv_bfloat162(l0, l1);
    lo[idx * 2 + 1] = __nv_bfloat162(l2, l3);
}

__global__ void trans_hilo_kernel(const float* __restrict__ in, int R, int C,
                                  __nv_bfloat16* __restrict__ hi, __nv_bfloat16* __restrict__ lo,
                                  int Kpad, int Npad)
{
    __shared__ float t[32][33];
    const int cb = blockIdx.x * 32;
    const int rb = blockIdx.y * 32;
    const int x = threadIdx.x, y = threadIdx.y;
#pragma unroll
    for (int i = y; i < 32; i += 8) {
        int r = rb + i, ccol = cb + x;
        t[i][x] = (r < R && ccol < C) ? in[(size_t)r * C + ccol] : 0.f;
    }
    __syncthreads();
#pragma unroll
    for (int i = y; i < 32; i += 8) {
        int n = cb + i, k = rb + x;
        if (n < Npad && k < Kpad) {
            size_t o = (size_t)n * Kpad + k;
            split_hilo(t[x][i], hi[o], lo[o]);
        }
    }
}

__global__ void meanf_kernel(const float* __restrict__ feat, float* __restrict__ mf)
{
    int b = blockIdx.x, tid = threadIdx.x;
    for (int d = tid; d < ENCv; d += 256) {
        float s = 0.f;
        const float* p = feat + (size_t)b * Nv * ENCv + d;
#pragma unroll 4
        for (int n = 0; n < Nv; n++) s += p[(size_t)n * ENCv];
        mf[b * ENCv + d] = s * (1.0f / (float)Nv);
    }
}

// ---------------- host helpers ----------------
static void launch_big(int M, int N, int Nreal, int K,
                       const __nv_bfloat16* Ahi, const __nv_bfloat16* Alo,
                       const __nv_bfloat16* Bhi, const __nv_bfloat16* Blo,
                       float* C, __half* Ch, int ldc, const float* bias,
                       int remap, int tbase)
{
    dim3 grid(N / 64, M / 128);
    hmma_big_kernel<<<grid, 256, BIG_SMEM>>>(Nreal, K, Ahi, Alo, Bhi, Blo,
                                             C, Ch, ldc, bias, remap, tbase);
}

extern "C" void kernel_launch(void* const* d_in, const int* in_sizes, int n_in,
                              void* d_out, int out_size)
{
    const float* features  = (const float*)d_in[0];
    const int*   captions  = (const int*)  d_in[1];
    const float* embedding = (const float*)d_in[2];
    const float* W_enc     = (const float*)d_in[3];
    const float* b_enc     = (const float*)d_in[4];
    const float* W_dec     = (const float*)d_in[5];
    const float* b_dec     = (const float*)d_in[6];
    const float* w_att     = (const float*)d_in[7];
    // d_in[8] = b_att : softmax-invariant, unused
    const float* Wi_h      = (const float*)d_in[9];
    const float* bi_h      = (const float*)d_in[10];
    const float* Wi_c      = (const float*)d_in[11];
    const float* bi_c      = (const float*)d_in[12];
    const float* W_ih      = (const float*)d_in[13];
    const float* b_ih      = (const float*)d_in[14];
    const float* W_hh      = (const float*)d_in[15];
    const float* b_hh      = (const float*)d_in[16];
    const float* W_out     = (const float*)d_in[17];
    const float* b_out     = (const float*)d_in[18];
    float* out = (float*)d_out;

    cudaFuncSetAttribute(hmma_big_kernel,  cudaFuncAttributeMaxDynamicSharedMemorySize, BIG_SMEM);
    cudaFuncSetAttribute(hproj_kernel,     cudaFuncAttributeMaxDynamicSharedMemorySize, BIG_SMEM);
    cudaFuncSetAttribute(att_hh_kernel,    cudaFuncAttributeMaxDynamicSharedMemorySize, BIG_SMEM);
    cudaFuncSetAttribute(gates_lstm_kernel, cudaFuncAttributeMaxDynamicSharedMemorySize, BIG_SMEM);

    float *embgates, *bh, *bias2i, *meanf, *h0, *c, *hproj;
    __half* featprojh;
    __nv_bfloat16 *fhi, *flo, *wenchi, *wenclo, *wihhi, *wihlo, *wihchi, *wihclo,
                  *whcthi, *whctlo, *wouthi, *woutlo, *eahi, *ealo,
                  *Hhi, *Hlo, *h0hi, *h0lo, *ctxhi, *ctxlo;
    cudaGetSymbolAddress((void**)&featprojh, g_featproj_h);
    cudaGetSymbolAddress((void**)&embgates, g_embgates);
    cudaGetSymbolAddress((void**)&bh,       g_bh);
    cudaGetSymbolAddress((void**)&bias2i,   g_bias2i);
    cudaGetSymbolAddress((void**)&meanf,    g_meanf);
    cudaGetSymbolAddress((void**)&h0,       g_h0);
    cudaGetSymbolAddress((void**)&c,        g_c);
    cudaGetSymbolAddress((void**)&hproj,    g_hproj);
    cudaGetSymbolAddress((void**)&fhi,      g_feat_hi);
    cudaGetSymbolAddress((void**)&flo,      g_feat_lo);
    cudaGetSymbolAddress((void**)&wenchi,   g_WencT_hi);
    cudaGetSymbolAddress((void**)&wenclo,   g_WencT_lo);
    cudaGetSymbolAddress((void**)&wihhi,    g_WihTi_hi);
    cudaGetSymbolAddress((void**)&wihlo,    g_WihTi_lo);
    cudaGetSymbolAddress((void**)&wihchi,   g_WihcTi_hi);
    cudaGetSymbolAddress((void**)&wihclo,   g_WihcTi_lo);
    cudaGetSymbolAddress((void**)&whcthi,   g_whcatT_hi);
    cudaGetSymbolAddress((void**)&whctlo,   g_whcatT_lo);
    cudaGetSymbolAddress((void**)&wouthi,   g_WoutT_hi);
    cudaGetSymbolAddress((void**)&woutlo,   g_WoutT_lo);
    cudaGetSymbolAddress((void**)&eahi,     g_embA_hi);
    cudaGetSymbolAddress((void**)&ealo,     g_embA_lo);
    cudaGetSymbolAddress((void**)&Hhi,      g_H_hi);
    cudaGetSymbolAddress((void**)&Hlo,      g_H_lo);
    cudaGetSymbolAddress((void**)&h0hi,     g_h0_hi);
    cudaGetSymbolAddress((void**)&h0lo,     g_h0_lo);
    cudaGetSymbolAddress((void**)&ctxhi,    g_ctx_hi);
    cudaGetSymbolAddress((void**)&ctxlo,    g_ctx_lo);

    dim3 tthr(32, 8);

    // ---- prep, featproj big GEMM stays at launch #4 (ncu slot) ----
    {
        size_t n4 = (size_t)Bv * Nv * ENCv / 4;
        conv4_hilo_kernel<<<(unsigned)((n4 + 255) / 256), 256>>>(
            (const float4*)features, n4, (__nv_bfloat162*)fhi, (__nv_bfloat162*)flo);     // 1
    }
    trans_hilo_kernel<<<dim3(16, 16), tthr>>>(W_enc, ENCv, Av, wenchi, wenclo, ENCv, Av); // 2
    whcatT_hilo_kernel<<<(HW * Dv + 255) / 256, 256>>>(W_dec, W_hh, whcthi, whctlo);      // 3
    launch_big(Bv * Nv, Av, Av, ENCv, fhi, flo, wenchi, wenclo,
               nullptr, featprojh, Av, b_enc, 0, 0);                                      // 4
    biases_kernel<<<(HW + 255) / 256, 256>>>(b_dec, b_ih, b_hh, bh, bias2i);              // 5
    embgather_hilo_kernel<<<(Tv * Bv * KE + 255) / 256, 256>>>(embedding, captions,
                                                               eahi, ealo);               // 6
    wihTi_kernel<<<(G4D * KE + 255) / 256, 256>>>(W_ih, wihhi, wihlo);                    // 7
    launch_big(Tv * Bv, G4D, G4D, KE, eahi, ealo, wihhi, wihlo,
               embgates, nullptr, G4D, bias2i, 0, 0);                                     // 8
    wihcTi_kernel<<<(G4D * Dv + 255) / 256, 256>>>(W_ih, wihchi, wihclo);                 // 9
    trans_hilo_kernel<<<dim3((VP + 31) / 32, (Dv + 31) / 32), tthr>>>(
        W_out, Dv, Vv, wouthi, woutlo, Dv, VP);                                           // 10
    meanf_kernel<<<Bv, 256>>>(features, meanf);                                           // 11
    {
        dim3 g(Dv / 64, Bv / 32);
        sgemm_kernel<32, 64, 16, 2, 4><<<g, 256>>>(Bv, Dv, ENCv, meanf, ENCv,
                                                   Wi_h, Dv, h0, Dv, bi_h);               // 12
        sgemm_kernel<32, 64, 16, 2, 4><<<g, 256>>>(Bv, Dv, ENCv, meanf, ENCv,
                                                   Wi_c, Dv, c, Dv, bi_c);                // 13
    }
    conv_hilo_kernel<<<(Bv * Dv + 255) / 256, 256>>>(h0, (size_t)Bv * Dv, h0hi, h0lo);    // 14

    const size_t PRED = (size_t)Bv * Tv * Vv;

    for (int t = 0; t < Tv; t++) {
        const __nv_bfloat16* hpHi = (t == 0) ? h0hi : (Hhi + (size_t)(t - 1) * Bv * Dv);
        const __nv_bfloat16* hpLo = (t == 0) ? h0lo : (Hlo + (size_t)(t - 1) * Bv * Dv);
        // stage 1: dec = h @ W_dec + b_dec
        hproj_kernel<<<8, 256, BIG_SMEM>>>(hpHi, hpLo, whcthi, whctlo, hproj, bh);
        // stage 2: attention || W_hh GEMM || logits of step t-1
        att_hh_kernel<<<318, 256, BIG_SMEM>>>(
            (const __half2*)featprojh, features, hproj, w_att,
            hpHi, hpLo, whcthi, whctlo,
            wouthi, woutlo, b_out, out, t - 1,
            ctxhi, ctxlo, out + PRED + (size_t)t * Nv);
        // stage 3: gates + fused LSTM -> c, Hhi/Hlo[t]
        gates_lstm_kernel<<<G4D / 64, 256, BIG_SMEM>>>(
            ctxhi, ctxlo, wihchi, wihclo,
            embgates + (size_t)t * Bv * G4D, hproj, c,
            Hhi + (size_t)t * Bv * Dv, Hlo + (size_t)t * Bv * Dv);
    }

    // logits for the last step (t = 23)
    launch_big(Bv, VP, Vv, Dv,
               Hhi + (size_t)(Tv - 1) * Bv * Dv, Hlo + (size_t)(Tv - 1) * Bv * Dv,
               wouthi, woutlo, out, nullptr, Vv, b_out, 1, Tv - 1);
}